// round 2
// baseline (speedup 1.0000x reference)
#include <cuda_runtime.h>
#include <cstdint>
#include <cstddef>

#define NF   16000
#define KNBR 64
#define RADIUS_F ((float)(0.5*6.0*1.5*0.025))

// ---------------- scratch (device globals; no allocation APIs) ----------------
__device__ float  g_A[(size_t)NF * 64 * 96];   // 393MB scatter target, reused per layer
__device__ float4 g_gF_ff[NF * KNBR];
__device__ int    g_gI_ff[NF * KNBR];
__device__ float4 g_gF_wf[NF * KNBR];
__device__ int    g_gI_wf[NF * KNBR];
__device__ float  g_out1[NF * 96];
__device__ float  g_out2[NF * 64];
__device__ float  g_out3[NF * 64];
__device__ float  g_dense[NF * 64];
__device__ int    g_mask_u8;                   // 1 if masks stored as 1-byte, 0 if int32

// ---------------- mask dtype detector ----------------
// If the mask buffer holds int32 0/1, every 32-bit word is <= 1.
// If it holds 1-byte bools, words contain packed patterns like 0x00000101 > 1.
__global__ void detect_mask_kernel(const unsigned int* __restrict__ m)
{
    __shared__ int s;
    if (threadIdx.x == 0) s = 0;
    __syncthreads();
    int bad = 0;
    for (int i = threadIdx.x; i < 65536; i += blockDim.x)
        if (m[i] > 1u) { bad = 1; break; }
    if (bad) atomicOr(&s, 1);
    __syncthreads();
    if (threadIdx.x == 0) g_mask_u8 = s;
}

// ---------------- helpers ----------------
static __device__ __forceinline__ float sgnf(float v) {
    return (v > 0.f) ? 1.f : ((v < 0.f) ? -1.f : 0.f);
}

__device__ __forceinline__ void gridmap(float u, int& i0, float& f) {
    float cc = (u * 0.5f + 0.5f) * 3.f;
    cc = fminf(fmaxf(cc, 0.f), 3.f);
    float fi = floorf(cc);
    fi = fminf(fi, 2.f);
    f = cc - fi;
    i0 = (int)fi;
}

// ---------------- geometry precompute: per (particle, neighbor) ----------------
// Produces: gF = (fx, fy, fz, win*mask), gI = base cell index.
__global__ void geom_kernel(const float* __restrict__ pin, const float* __restrict__ pout,
                            const int* __restrict__ nbr, const void* __restrict__ mask,
                            float4* __restrict__ gF, int* __restrict__ gI)
{
    int idx = blockIdx.x * blockDim.x + threadIdx.x;
    if (idx >= NF * KNBR) return;
    int mv = g_mask_u8 ? (int)((const unsigned char*)mask)[idx]
                       : ((const int*)mask)[idx];
    if (mv == 0) { gF[idx] = make_float4(0.f, 0.f, 0.f, 0.f); gI[idx] = 0; return; }
    int n = idx >> 6;
    int j = nbr[idx];
    float x = (pin[j*3+0] - pout[n*3+0]) / RADIUS_F;
    float y = (pin[j*3+1] - pout[n*3+1]) / RADIUS_F;
    float z = (pin[j*3+2] - pout[n*3+2]) / RADIUS_F;
    float sq = x*x + y*y + z*z;
    float t1 = 1.f - sq;
    float win = fminf(fmaxf(t1*t1*t1, 0.f), 1.f);

    const float eps = 1e-12f;
    float norm = sqrtf(fmaxf(sq, eps));
    float rho  = sqrtf(fmaxf(x*x + y*y, eps));
    bool  top  = (1.25f*z*z > x*x + y*y);
    float s_top = sqrtf(3.f*norm / (norm + fabsf(z)));
    float xs = top ? x*s_top : (x*norm)/rho;
    float ys = top ? y*s_top : (y*norm)/rho;
    float zs = top ? sgnf(z)*norm : 1.5f*z;
    if (sq < eps) { xs = 0.f; ys = 0.f; zs = 0.f; }
    float rxy = sqrtf(fmaxf(xs*xs + ys*ys, eps));
    bool use_x = fabsf(ys) <= fabsf(xs);
    float ddx = (use_x  && fabsf(xs) > eps) ? xs : 1.f;
    float ddy = (!use_x && fabsf(ys) > eps) ? ys : 1.f;
    const float c4 = 1.27323954473516276487f;  // 4/pi
    float xc = use_x ? sgnf(xs)*rxy : sgnf(ys)*rxy*c4*atanf(xs/ddy);
    float yc = use_x ? sgnf(xs)*rxy*c4*atanf(ys/ddx) : sgnf(ys)*rxy;
    if (xs*xs + ys*ys < eps) { xc = 0.f; yc = 0.f; }

    int ix, iy, iz; float fx, fy, fz;
    gridmap(xc, ix, fx); gridmap(yc, iy, fy); gridmap(zs, iz, fz);
    gF[idx] = make_float4(fx, fy, fz, win);
    gI[idx] = (ix*4 + iy)*4 + iz;
}

// ---------------- layer-1 cconv (cin=3, cout=32), fully fused per particle ----------------
__global__ void conv1_kernel(const float* __restrict__ feat, const int* __restrict__ nbr,
                             const float4* __restrict__ gF, const int* __restrict__ gI,
                             const float* __restrict__ W, const float* __restrict__ b,
                             float* __restrict__ out1, int col0)
{
    __shared__ float A[192];     // [cell][3]
    __shared__ float red[64];
    int n = blockIdx.x, t = threadIdx.x;           // 64 threads
    A[t] = 0.f; A[t + 64] = 0.f; A[t + 128] = 0.f;
    __syncthreads();

    int idx = n * KNBR + t;
    float4 g = gF[idx];
    if (g.w != 0.f) {
        int j = nbr[idx];
        float f0 = feat[j*3+0]*g.w, f1 = feat[j*3+1]*g.w, f2 = feat[j*3+2]*g.w;
        int base = gI[idx];
        float wx[2] = {1.f - g.x, g.x};
        float wy[2] = {1.f - g.y, g.y};
        float wz[2] = {1.f - g.z, g.z};
        #pragma unroll
        for (int cx = 0; cx < 2; cx++)
        #pragma unroll
        for (int cy = 0; cy < 2; cy++)
        #pragma unroll
        for (int cz = 0; cz < 2; cz++) {
            float wc = wx[cx]*wy[cy]*wz[cz];
            int cell = base + cx*16 + cy*4 + cz;
            atomicAdd(&A[cell*3+0], wc*f0);
            atomicAdd(&A[cell*3+1], wc*f1);
            atomicAdd(&A[cell*3+2], wc*f2);
        }
    }
    __syncthreads();

    int o = t & 31, h = t >> 5;
    float acc = 0.f;
    for (int i = h*96; i < h*96 + 96; i++)
        acc += A[i] * W[i*32 + o];
    red[t] = acc;
    __syncthreads();
    if (t < 32) {
        float v = red[t] + red[t + 32] + b[o];
        out1[n*96 + col0 + t] = fmaxf(v, 0.f);
    }
}

// ---------------- scatter: build dense A[n, 64*CIN] in shared, write to global ----------------
// Channel-owner layout: thread owns channel c -> no atomics, no conflicts.
template<int CIN, int R>
__global__ void scatter_kernel(const float* __restrict__ feat, const int* __restrict__ nbr,
                               const float4* __restrict__ gF, const int* __restrict__ gI,
                               float* __restrict__ A)
{
    constexpr int BD = CIN * R;
    __shared__ float sA[R * 64 * CIN];
    __shared__ float4 sG[KNBR];
    __shared__ int    sB[KNBR];
    __shared__ int    sJ[KNBR];
    int n = blockIdx.x, t = threadIdx.x;
    if (t < KNBR) { sG[t] = gF[n*KNBR + t]; sB[t] = gI[n*KNBR + t]; sJ[t] = nbr[n*KNBR + t]; }
    for (int i = t; i < R * 64 * CIN; i += BD) sA[i] = 0.f;
    __syncthreads();

    int c = t % CIN;
    int r = t / CIN;
    float* Ar = sA + r * 64 * CIN;
    const int KPR = KNBR / R;
    for (int k = r*KPR; k < (r+1)*KPR; k++) {
        float4 g = sG[k];
        if (g.w == 0.f) continue;                  // uniform per block
        float v = feat[(size_t)sJ[k]*CIN + c] * g.w;
        float wx0 = 1.f - g.x, wx1 = g.x;
        float wy0 = 1.f - g.y, wy1 = g.y;
        float wz0 = 1.f - g.z, wz1 = g.z;
        int p = sB[k]*CIN + c;
        Ar[p           ] += wx0*wy0*wz0*v;
        Ar[p +     CIN ] += wx0*wy0*wz1*v;
        Ar[p +  4*CIN  ] += wx0*wy1*wz0*v;
        Ar[p +  5*CIN  ] += wx0*wy1*wz1*v;
        Ar[p + 16*CIN  ] += wx1*wy0*wz0*v;
        Ar[p + 17*CIN  ] += wx1*wy0*wz1*v;
        Ar[p + 20*CIN  ] += wx1*wy1*wz0*v;
        Ar[p + 21*CIN  ] += wx1*wy1*wz1*v;
    }
    __syncthreads();

    float* out = A + (size_t)n * 64 * CIN;
    for (int i = t; i < 64 * CIN; i += BD) {
        float s = sA[i];
        #pragma unroll
        for (int rr = 1; rr < R; rr++) s += sA[rr*64*CIN + i];
        out[i] = s;
    }
}

// ---------------- GEMM: out[M,64] = A[M,K] @ W[K,64] + bias (+add) (+res) (relu) ----------------
template<int HAS_ADD, int HAS_RES, int RELU>
__global__ __launch_bounds__(256) void gemm_kernel(
    const float* __restrict__ A, const float* __restrict__ W,
    const float* __restrict__ bias, const float* __restrict__ addv,
    const float* __restrict__ resv, float* __restrict__ out, int K)
{
    __shared__ float As[16][68];
    __shared__ float Ws[16][68];
    int m0 = blockIdx.x * 64;
    int tid = threadIdx.x;
    int tx = tid & 15, ty = tid >> 4;
    int arow = tid >> 2, akk = (tid & 3) * 4;
    int wk = tid >> 4, wc = (tid & 15) * 4;
    float acc[4][4] = {};

    for (int k0 = 0; k0 < K; k0 += 16) {
        float4 a4 = *(const float4*)(A + (size_t)(m0 + arow)*K + k0 + akk);
        float4 w4 = *(const float4*)(W + (size_t)(k0 + wk)*64 + wc);
        As[akk+0][arow] = a4.x; As[akk+1][arow] = a4.y;
        As[akk+2][arow] = a4.z; As[akk+3][arow] = a4.w;
        *(float4*)&Ws[wk][wc] = w4;
        __syncthreads();
        #pragma unroll
        for (int kk = 0; kk < 16; kk++) {
            float4 av = *(const float4*)&As[kk][ty*4];
            float4 bv = *(const float4*)&Ws[kk][tx*4];
            float a[4] = {av.x, av.y, av.z, av.w};
            float bb[4] = {bv.x, bv.y, bv.z, bv.w};
            #pragma unroll
            for (int i = 0; i < 4; i++)
                #pragma unroll
                for (int j = 0; j < 4; j++)
                    acc[i][j] += a[i]*bb[j];
        }
        __syncthreads();
    }

    #pragma unroll
    for (int i = 0; i < 4; i++) {
        int m = m0 + ty*4 + i;
        #pragma unroll
        for (int j = 0; j < 4; j++) {
            int nn = tx*4 + j;
            float v = acc[i][j] + bias[nn];
            if (HAS_ADD) v += addv[m*64 + nn];
            if (HAS_RES) v += resv[m*64 + nn];
            if (RELU) v = fmaxf(v, 0.f);
            out[m*64 + nn] = v;
        }
    }
}

// ---------------- dense shortcut: Y[n, col0+o] = X[n,:CIN] @ W + b ----------------
__global__ void dense_kernel(const float* __restrict__ X, const float* __restrict__ W,
                             const float* __restrict__ b, float* __restrict__ Y,
                             int CIN, int COUT, int ldY, int col0)
{
    int idx = blockIdx.x * blockDim.x + threadIdx.x;
    if (idx >= NF * COUT) return;
    int n = idx / COUT, o = idx - n*COUT;
    float acc = b[o];
    const float* x = X + (size_t)n * CIN;
    for (int c = 0; c < CIN; c++) acc += x[c] * W[c*COUT + o];
    Y[(size_t)n*ldY + col0 + o] = acc;
}

// ---------------- final layer: out[n,3] = A4[n,:4096]@W_c4 + b_c4 + dense4[n,:] ----------------
__global__ void final_kernel(const float* __restrict__ A, const float* __restrict__ W,
                             const float* __restrict__ b, const float* __restrict__ dense,
                             float* __restrict__ out)
{
    int n = blockIdx.x, t = threadIdx.x;  // 128 threads
    const float* Ar = A + (size_t)n * 4096;
    float a0 = 0.f, a1 = 0.f, a2 = 0.f;
    for (int i = t; i < 4096; i += 128) {
        float av = Ar[i];
        a0 += av * W[i*3 + 0];
        a1 += av * W[i*3 + 1];
        a2 += av * W[i*3 + 2];
    }
    __shared__ float red[3][128];
    red[0][t] = a0; red[1][t] = a1; red[2][t] = a2;
    __syncthreads();
    for (int s = 64; s > 0; s >>= 1) {
        if (t < s) {
            red[0][t] += red[0][t+s];
            red[1][t] += red[1][t+s];
            red[2][t] += red[2][t+s];
        }
        __syncthreads();
    }
    if (t < 3) out[n*3 + t] = red[t][0] + b[t] + dense[n*3 + t];
}

// ---------------- launch ----------------
extern "C" void kernel_launch(void* const* d_in, const int* in_sizes, int n_in,
                              void* d_out, int out_size)
{
    const float* fluid_pos = (const float*)d_in[0];
    const float* wall_pos  = (const float*)d_in[1];
    const float* fluid_vel = (const float*)d_in[2];
    const float* wall_nv   = (const float*)d_in[3];
    const int*   nbr_wf    = (const int*)d_in[4];
    const void*  mask_wf   = d_in[5];
    const int*   nbr_ff    = (const int*)d_in[6];
    const void*  mask_ff   = d_in[7];
    const float* W_wall1 = (const float*)d_in[8];
    const float* b_wall1 = (const float*)d_in[9];
    const float* W_fluid1 = (const float*)d_in[10];
    const float* b_fluid1 = (const float*)d_in[11];
    const float* W_d1 = (const float*)d_in[12];
    const float* b_d1 = (const float*)d_in[13];
    const float* W_c2 = (const float*)d_in[14];
    const float* b_c2 = (const float*)d_in[15];
    const float* W_d2 = (const float*)d_in[16];
    const float* b_d2 = (const float*)d_in[17];
    const float* W_c3 = (const float*)d_in[18];
    const float* b_c3 = (const float*)d_in[19];
    const float* W_d3 = (const float*)d_in[20];
    const float* b_d3 = (const float*)d_in[21];
    const float* W_c4 = (const float*)d_in[22];
    const float* b_c4 = (const float*)d_in[23];
    const float* W_d4 = (const float*)d_in[24];
    const float* b_d4 = (const float*)d_in[25];

    void *pA, *pgFff, *pgIff, *pgFwf, *pgIwf, *pout1, *pout2, *pout3, *pdense;
    cudaGetSymbolAddress(&pA, g_A);
    cudaGetSymbolAddress(&pgFff, g_gF_ff);
    cudaGetSymbolAddress(&pgIff, g_gI_ff);
    cudaGetSymbolAddress(&pgFwf, g_gF_wf);
    cudaGetSymbolAddress(&pgIwf, g_gI_wf);
    cudaGetSymbolAddress(&pout1, g_out1);
    cudaGetSymbolAddress(&pout2, g_out2);
    cudaGetSymbolAddress(&pout3, g_out3);
    cudaGetSymbolAddress(&pdense, g_dense);
    float*  A     = (float*)pA;
    float4* gFff  = (float4*)pgFff;
    int*    gIff  = (int*)pgIff;
    float4* gFwf  = (float4*)pgFwf;
    int*    gIwf  = (int*)pgIwf;
    float*  out1  = (float*)pout1;
    float*  out2  = (float*)pout2;
    float*  out3  = (float*)pout3;
    float*  dense = (float*)pdense;

    const int tot = NF * KNBR;
    detect_mask_kernel<<<1, 1024>>>((const unsigned int*)mask_wf);
    geom_kernel<<<(tot + 255)/256, 256>>>(wall_pos,  fluid_pos, nbr_wf, mask_wf, gFwf, gIwf);
    geom_kernel<<<(tot + 255)/256, 256>>>(fluid_pos, fluid_pos, nbr_ff, mask_ff, gFff, gIff);

    // layer 1
    conv1_kernel<<<NF, 64>>>(wall_nv,   nbr_wf, gFwf, gIwf, W_wall1,  b_wall1,  out1, 0);
    conv1_kernel<<<NF, 64>>>(fluid_vel, nbr_ff, gFff, gIff, W_fluid1, b_fluid1, out1, 32);
    dense_kernel<<<(NF*32 + 255)/256, 256>>>(fluid_vel, W_d1, b_d1, out1, 3, 32, 96, 64);

    // layer 2
    dense_kernel<<<(NF*64 + 255)/256, 256>>>(out1, W_d2, b_d2, dense, 96, 64, 64, 0);
    scatter_kernel<96, 1><<<NF, 96>>>(out1, nbr_ff, gFff, gIff, A);
    gemm_kernel<1, 0, 1><<<NF/64, 256>>>(A, W_c2, b_c2, dense, nullptr, out2, 6144);

    // layer 3
    dense_kernel<<<(NF*64 + 255)/256, 256>>>(out2, W_d3, b_d3, dense, 64, 64, 64, 0);
    scatter_kernel<64, 2><<<NF, 128>>>(out2, nbr_ff, gFff, gIff, A);
    gemm_kernel<1, 1, 1><<<NF/64, 256>>>(A, W_c3, b_c3, dense, out2, out3, 4096);

    // layer 4
    dense_kernel<<<(NF*3 + 255)/256, 256>>>(out3, W_d4, b_d4, dense, 64, 3, 3, 0);
    scatter_kernel<64, 2><<<NF, 128>>>(out3, nbr_ff, gFff, gIff, A);
    final_kernel<<<NF, 128>>>(A, W_c4, b_c4, dense, (float*)d_out);
}

// round 3
// speedup vs baseline: 1.1402x; 1.1402x over previous
#include <cuda_runtime.h>
#include <cstdint>
#include <cstddef>

#define NF   16000
#define KNBR 64
#define RADIUS_F ((float)(0.5*6.0*1.5*0.025))

// ---------------- scratch (device globals; no allocation APIs) ----------------
__device__ float  g_A[(size_t)NF * 64 * 96];   // 393MB scatter target, reused per layer
__device__ float4 g_gF_ff[NF * KNBR];
__device__ int    g_gI_ff[NF * KNBR];
__device__ float4 g_gF_wf[NF * KNBR];
__device__ int    g_gI_wf[NF * KNBR];
__device__ float  g_out1[NF * 96];
__device__ float  g_out2[NF * 64];
__device__ float  g_out3[NF * 64];
__device__ float  g_dense[NF * 64];
__device__ int    g_mask_u8;                   // 1 if masks stored as 1-byte, 0 if int32

// ---------------- packed f32x2 helpers ----------------
__device__ __forceinline__ unsigned long long pack2(float a) {
    unsigned long long r;
    asm("mov.b64 %0, {%1, %1};" : "=l"(r) : "f"(a));
    return r;
}
__device__ __forceinline__ void fma2(unsigned long long& d, unsigned long long a, unsigned long long b) {
    asm("fma.rn.f32x2 %0, %1, %2, %0;" : "+l"(d) : "l"(a), "l"(b));
}
__device__ __forceinline__ void unpack2(unsigned long long v, float& lo, float& hi) {
    asm("mov.b64 {%0, %1}, %2;" : "=f"(lo), "=f"(hi) : "l"(v));
}

// ---------------- mask dtype detector ----------------
__global__ void detect_mask_kernel(const unsigned int* __restrict__ m)
{
    __shared__ int s;
    if (threadIdx.x == 0) s = 0;
    __syncthreads();
    int bad = 0;
    for (int i = threadIdx.x; i < 65536; i += blockDim.x)
        if (m[i] > 1u) { bad = 1; break; }
    if (bad) atomicOr(&s, 1);
    __syncthreads();
    if (threadIdx.x == 0) g_mask_u8 = s;
}

// ---------------- helpers ----------------
static __device__ __forceinline__ float sgnf(float v) {
    return (v > 0.f) ? 1.f : ((v < 0.f) ? -1.f : 0.f);
}

__device__ __forceinline__ void gridmap(float u, int& i0, float& f) {
    float cc = (u * 0.5f + 0.5f) * 3.f;
    cc = fminf(fmaxf(cc, 0.f), 3.f);
    float fi = floorf(cc);
    fi = fminf(fi, 2.f);
    f = cc - fi;
    i0 = (int)fi;
}

// ---------------- geometry precompute ----------------
__global__ void geom_kernel(const float* __restrict__ pin, const float* __restrict__ pout,
                            const int* __restrict__ nbr, const void* __restrict__ mask,
                            float4* __restrict__ gF, int* __restrict__ gI)
{
    int idx = blockIdx.x * blockDim.x + threadIdx.x;
    if (idx >= NF * KNBR) return;
    int mv = g_mask_u8 ? (int)((const unsigned char*)mask)[idx]
                       : ((const int*)mask)[idx];
    if (mv == 0) { gF[idx] = make_float4(0.f, 0.f, 0.f, 0.f); gI[idx] = 0; return; }
    int n = idx >> 6;
    int j = nbr[idx];
    float x = (pin[j*3+0] - pout[n*3+0]) / RADIUS_F;
    float y = (pin[j*3+1] - pout[n*3+1]) / RADIUS_F;
    float z = (pin[j*3+2] - pout[n*3+2]) / RADIUS_F;
    float sq = x*x + y*y + z*z;
    float t1 = 1.f - sq;
    float win = fminf(fmaxf(t1*t1*t1, 0.f), 1.f);

    const float eps = 1e-12f;
    float norm = sqrtf(fmaxf(sq, eps));
    float rho  = sqrtf(fmaxf(x*x + y*y, eps));
    bool  top  = (1.25f*z*z > x*x + y*y);
    float s_top = sqrtf(3.f*norm / (norm + fabsf(z)));
    float xs = top ? x*s_top : (x*norm)/rho;
    float ys = top ? y*s_top : (y*norm)/rho;
    float zs = top ? sgnf(z)*norm : 1.5f*z;
    if (sq < eps) { xs = 0.f; ys = 0.f; zs = 0.f; }
    float rxy = sqrtf(fmaxf(xs*xs + ys*ys, eps));
    bool use_x = fabsf(ys) <= fabsf(xs);
    float ddx = (use_x  && fabsf(xs) > eps) ? xs : 1.f;
    float ddy = (!use_x && fabsf(ys) > eps) ? ys : 1.f;
    const float c4 = 1.27323954473516276487f;  // 4/pi
    float xc = use_x ? sgnf(xs)*rxy : sgnf(ys)*rxy*c4*atanf(xs/ddy);
    float yc = use_x ? sgnf(xs)*rxy*c4*atanf(ys/ddx) : sgnf(ys)*rxy;
    if (xs*xs + ys*ys < eps) { xc = 0.f; yc = 0.f; }

    int ix, iy, iz; float fx, fy, fz;
    gridmap(xc, ix, fx); gridmap(yc, iy, fy); gridmap(zs, iz, fz);
    gF[idx] = make_float4(fx, fy, fz, win);
    gI[idx] = (ix*4 + iy)*4 + iz;
}

// ---------------- layer-1 cconv (cin=3, cout=32): 4 particles/block for W reuse ----------------
__global__ __launch_bounds__(256) void conv1_kernel(
    const float* __restrict__ feat, const int* __restrict__ nbr,
    const float4* __restrict__ gF, const int* __restrict__ gI,
    const float* __restrict__ W, const float* __restrict__ b,
    float* __restrict__ out1, int col0)
{
    __shared__ float A[4][192];     // per-particle [cell][3]
    __shared__ float red[256];
    int t = threadIdx.x;
    int p = t >> 6, tl = t & 63;
    int n = blockIdx.x * 4 + p;
    float* Ap = A[p];
    Ap[tl] = 0.f; Ap[tl + 64] = 0.f; Ap[tl + 128] = 0.f;
    __syncthreads();

    int idx = n * KNBR + tl;
    float4 g = gF[idx];
    if (g.w != 0.f) {
        int j = nbr[idx];
        float f0 = feat[j*3+0]*g.w, f1 = feat[j*3+1]*g.w, f2 = feat[j*3+2]*g.w;
        int base = gI[idx];
        float wx[2] = {1.f - g.x, g.x};
        float wy[2] = {1.f - g.y, g.y};
        float wz[2] = {1.f - g.z, g.z};
        #pragma unroll
        for (int cx = 0; cx < 2; cx++)
        #pragma unroll
        for (int cy = 0; cy < 2; cy++)
        #pragma unroll
        for (int cz = 0; cz < 2; cz++) {
            float wc = wx[cx]*wy[cy]*wz[cz];
            int cell = base + cx*16 + cy*4 + cz;
            atomicAdd(&Ap[cell*3+0], wc*f0);
            atomicAdd(&Ap[cell*3+1], wc*f1);
            atomicAdd(&Ap[cell*3+2], wc*f2);
        }
    }
    __syncthreads();

    int o = tl & 31, h = tl >> 5;
    float acc = 0.f;
    for (int i = h*96; i < h*96 + 96; i++)
        acc += Ap[i] * W[i*32 + o];
    red[t] = acc;
    __syncthreads();
    if (tl < 32) {
        float v = red[p*64 + tl] + red[p*64 + tl + 32] + b[o];
        out1[n*96 + col0 + tl] = fmaxf(v, 0.f);
    }
}

// ---------------- scatter: build dense A[n, 64*CIN] in shared, write to global ----------------
template<int CIN, int R>
__global__ void scatter_kernel(const float* __restrict__ feat, const int* __restrict__ nbr,
                               const float4* __restrict__ gF, const int* __restrict__ gI,
                               float* __restrict__ A)
{
    constexpr int BD = CIN * R;
    __shared__ float sA[R * 64 * CIN];
    __shared__ float4 sG[KNBR];
    __shared__ int    sB[KNBR];
    __shared__ int    sJ[KNBR];
    int n = blockIdx.x, t = threadIdx.x;
    if (t < KNBR) { sG[t] = gF[n*KNBR + t]; sB[t] = gI[n*KNBR + t]; sJ[t] = nbr[n*KNBR + t]; }
    for (int i = t; i < R * 64 * CIN; i += BD) sA[i] = 0.f;
    __syncthreads();

    int c = t % CIN;
    int r = t / CIN;
    float* Ar = sA + r * 64 * CIN;
    const int KPR = KNBR / R;
    for (int k = r*KPR; k < (r+1)*KPR; k++) {
        float4 g = sG[k];
        if (g.w == 0.f) continue;                  // uniform per block
        float v = feat[(size_t)sJ[k]*CIN + c] * g.w;
        float wx0 = 1.f - g.x, wx1 = g.x;
        float wy0 = 1.f - g.y, wy1 = g.y;
        float wz0 = 1.f - g.z, wz1 = g.z;
        int p = sB[k]*CIN + c;
        Ar[p           ] += wx0*wy0*wz0*v;
        Ar[p +     CIN ] += wx0*wy0*wz1*v;
        Ar[p +  4*CIN  ] += wx0*wy1*wz0*v;
        Ar[p +  5*CIN  ] += wx0*wy1*wz1*v;
        Ar[p + 16*CIN  ] += wx1*wy0*wz0*v;
        Ar[p + 17*CIN  ] += wx1*wy0*wz1*v;
        Ar[p + 20*CIN  ] += wx1*wy1*wz0*v;
        Ar[p + 21*CIN  ] += wx1*wy1*wz1*v;
    }
    __syncthreads();

    float* out = A + (size_t)n * 64 * CIN;
    for (int i = t; i < 64 * CIN; i += BD) {
        float s = sA[i];
        #pragma unroll
        for (int rr = 1; rr < R; rr++) s += sA[rr*64*CIN + i];
        out[i] = s;
    }
}

// ---------------- GEMM: out[M,64] = A[M,K] @ W[K,64], FFMA2, 128x64 tile ----------------
// 128 threads, 8x8 microtile, double-buffered smem, permuted A layout for
// conflict-free LDS.128 (thread t's 8 rows live at 16B chunks t and 16+t).
#define AS_LD 132
#define WS_LD 72
template<int HAS_ADD, int HAS_RES, int RELU>
__global__ __launch_bounds__(128) void gemm_kernel(
    const float* __restrict__ A, const float* __restrict__ W,
    const float* __restrict__ bias, const float* __restrict__ addv,
    const float* __restrict__ resv, float* __restrict__ out, int K)
{
    __shared__ float As[2][16][AS_LD];
    __shared__ float Ws[2][16][WS_LD];
    int tid = threadIdx.x;
    int m0 = blockIdx.x * 128;
    int tm = tid & 15;            // thread M index (rows 8*tm .. 8*tm+7)
    int nb = (tid >> 4) * 8;      // thread N offset

    // A loader: 4 float4 per thread; idx = it*128+tid -> row=idx>>2, k4=idx&3
    int arow = tid >> 2;          // base row for it=0 pattern: row = (it*128+tid)>>2 = it*32 + (tid>>2)
    int ak4  = tid & 3;
    // permuted store word for row m: w = ((m&4)<<4) + ((m>>3)<<2) + (m&3)
    // W loader: 2 float4 per thread; idx = it*128+tid -> wr=idx>>4, wc4=idx&15
    int wr = tid >> 4;            // row = it*8 + (tid>>4)
    int wc4 = tid & 15;

    unsigned long long acc[8][4];
    #pragma unroll
    for (int i = 0; i < 8; i++)
        #pragma unroll
        for (int j = 0; j < 4; j++) acc[i][j] = 0ull;

    float4 pa[4], pw[2];
    // preload chunk 0
    #pragma unroll
    for (int it = 0; it < 4; it++) {
        int row = it*32 + arow;
        pa[it] = *(const float4*)(A + (size_t)(m0 + row)*K + ak4*4);
    }
    #pragma unroll
    for (int it = 0; it < 2; it++) {
        int row = it*8 + wr;
        pw[it] = *(const float4*)(W + (size_t)row*64 + wc4*4);
    }
    // store chunk 0 into buf 0
    #pragma unroll
    for (int it = 0; it < 4; it++) {
        int row = it*32 + arow;
        int w = ((row & 4) << 4) + ((row >> 3) << 2) + (row & 3);
        As[0][ak4*4+0][w] = pa[it].x;
        As[0][ak4*4+1][w] = pa[it].y;
        As[0][ak4*4+2][w] = pa[it].z;
        As[0][ak4*4+3][w] = pa[it].w;
    }
    #pragma unroll
    for (int it = 0; it < 2; it++)
        *(float4*)&Ws[0][it*8 + wr][wc4*4] = pw[it];
    __syncthreads();

    int NIT = K >> 4;
    for (int itk = 0; itk < NIT; itk++) {
        int cur = itk & 1;
        bool more = (itk + 1 < NIT);
        if (more) {
            int k0 = (itk + 1) << 4;
            #pragma unroll
            for (int it = 0; it < 4; it++) {
                int row = it*32 + arow;
                pa[it] = *(const float4*)(A + (size_t)(m0 + row)*K + k0 + ak4*4);
            }
            #pragma unroll
            for (int it = 0; it < 2; it++) {
                int row = it*8 + wr;
                pw[it] = *(const float4*)(W + (size_t)(k0 + row)*64 + wc4*4);
            }
        }
        // compute
        const float* asb = &As[cur][0][0];
        const float* wsb = &Ws[cur][0][0];
        #pragma unroll
        for (int kk = 0; kk < 16; kk++) {
            float4 a0 = *(const float4*)(asb + kk*AS_LD + 4*tm);
            float4 a1 = *(const float4*)(asb + kk*AS_LD + 64 + 4*tm);
            ulonglong2 b01 = *(const ulonglong2*)(wsb + kk*WS_LD + nb);
            ulonglong2 b23 = *(const ulonglong2*)(wsb + kk*WS_LD + nb + 4);
            float av[8] = {a0.x, a0.y, a0.z, a0.w, a1.x, a1.y, a1.z, a1.w};
            #pragma unroll
            for (int i = 0; i < 8; i++) {
                unsigned long long ad = pack2(av[i]);
                fma2(acc[i][0], ad, b01.x);
                fma2(acc[i][1], ad, b01.y);
                fma2(acc[i][2], ad, b23.x);
                fma2(acc[i][3], ad, b23.y);
            }
        }
        if (more) {
            int nxt = cur ^ 1;
            #pragma unroll
            for (int it = 0; it < 4; it++) {
                int row = it*32 + arow;
                int w = ((row & 4) << 4) + ((row >> 3) << 2) + (row & 3);
                As[nxt][ak4*4+0][w] = pa[it].x;
                As[nxt][ak4*4+1][w] = pa[it].y;
                As[nxt][ak4*4+2][w] = pa[it].z;
                As[nxt][ak4*4+3][w] = pa[it].w;
            }
            #pragma unroll
            for (int it = 0; it < 2; it++)
                *(float4*)&Ws[nxt][it*8 + wr][wc4*4] = pw[it];
        }
        __syncthreads();
    }

    // epilogue: rows m0 + 8*tm + i (a0 = rows 0..3, a1 = rows 4..7 of the group)
    #pragma unroll
    for (int i = 0; i < 8; i++) {
        int m = m0 + tm*8 + i;
        #pragma unroll
        for (int j = 0; j < 4; j++) {
            int n0 = nb + 2*j;
            float lo, hi;
            unpack2(acc[i][j], lo, hi);
            float2 bb = *(const float2*)&bias[n0];
            lo += bb.x; hi += bb.y;
            if (HAS_ADD) {
                float2 av = *(const float2*)&addv[(size_t)m*64 + n0];
                lo += av.x; hi += av.y;
            }
            if (HAS_RES) {
                float2 rv = *(const float2*)&resv[(size_t)m*64 + n0];
                lo += rv.x; hi += rv.y;
            }
            if (RELU) { lo = fmaxf(lo, 0.f); hi = fmaxf(hi, 0.f); }
            float2 o2 = make_float2(lo, hi);
            *(float2*)&out[(size_t)m*64 + n0] = o2;
        }
    }
}

// ---------------- dense shortcut: Y[n, col0+o] = X[n,:CIN] @ W + b ----------------
__global__ void dense_kernel(const float* __restrict__ X, const float* __restrict__ W,
                             const float* __restrict__ b, float* __restrict__ Y,
                             int CIN, int COUT, int ldY, int col0)
{
    int idx = blockIdx.x * blockDim.x + threadIdx.x;
    if (idx >= NF * COUT) return;
    int n = idx / COUT, o = idx - n*COUT;
    float acc = b[o];
    const float* x = X + (size_t)n * CIN;
    for (int c = 0; c < CIN; c++) acc += x[c] * W[c*COUT + o];
    Y[(size_t)n*ldY + col0 + o] = acc;
}

// ---------------- final layer: out[n,3] = A4[n,:4096]@W_c4 + b_c4 + dense4[n,:] ----------------
__global__ void final_kernel(const float* __restrict__ A, const float* __restrict__ W,
                             const float* __restrict__ b, const float* __restrict__ dense,
                             float* __restrict__ out)
{
    int n = blockIdx.x, t = threadIdx.x;  // 128 threads
    const float* Ar = A + (size_t)n * 4096;
    float a0 = 0.f, a1 = 0.f, a2 = 0.f;
    for (int i = t; i < 4096; i += 128) {
        float av = Ar[i];
        a0 += av * W[i*3 + 0];
        a1 += av * W[i*3 + 1];
        a2 += av * W[i*3 + 2];
    }
    __shared__ float red[3][128];
    red[0][t] = a0; red[1][t] = a1; red[2][t] = a2;
    __syncthreads();
    for (int s = 64; s > 0; s >>= 1) {
        if (t < s) {
            red[0][t] += red[0][t+s];
            red[1][t] += red[1][t+s];
            red[2][t] += red[2][t+s];
        }
        __syncthreads();
    }
    if (t < 3) out[n*3 + t] = red[t][0] + b[t] + dense[n*3 + t];
}

// ---------------- launch ----------------
extern "C" void kernel_launch(void* const* d_in, const int* in_sizes, int n_in,
                              void* d_out, int out_size)
{
    const float* fluid_pos = (const float*)d_in[0];
    const float* wall_pos  = (const float*)d_in[1];
    const float* fluid_vel = (const float*)d_in[2];
    const float* wall_nv   = (const float*)d_in[3];
    const int*   nbr_wf    = (const int*)d_in[4];
    const void*  mask_wf   = d_in[5];
    const int*   nbr_ff    = (const int*)d_in[6];
    const void*  mask_ff   = d_in[7];
    const float* W_wall1 = (const float*)d_in[8];
    const float* b_wall1 = (const float*)d_in[9];
    const float* W_fluid1 = (const float*)d_in[10];
    const float* b_fluid1 = (const float*)d_in[11];
    const float* W_d1 = (const float*)d_in[12];
    const float* b_d1 = (const float*)d_in[13];
    const float* W_c2 = (const float*)d_in[14];
    const float* b_c2 = (const float*)d_in[15];
    const float* W_d2 = (const float*)d_in[16];
    const float* b_d2 = (const float*)d_in[17];
    const float* W_c3 = (const float*)d_in[18];
    const float* b_c3 = (const float*)d_in[19];
    const float* W_d3 = (const float*)d_in[20];
    const float* b_d3 = (const float*)d_in[21];
    const float* W_c4 = (const float*)d_in[22];
    const float* b_c4 = (const float*)d_in[23];
    const float* W_d4 = (const float*)d_in[24];
    const float* b_d4 = (const float*)d_in[25];

    void *pA, *pgFff, *pgIff, *pgFwf, *pgIwf, *pout1, *pout2, *pout3, *pdense;
    cudaGetSymbolAddress(&pA, g_A);
    cudaGetSymbolAddress(&pgFff, g_gF_ff);
    cudaGetSymbolAddress(&pgIff, g_gI_ff);
    cudaGetSymbolAddress(&pgFwf, g_gF_wf);
    cudaGetSymbolAddress(&pgIwf, g_gI_wf);
    cudaGetSymbolAddress(&pout1, g_out1);
    cudaGetSymbolAddress(&pout2, g_out2);
    cudaGetSymbolAddress(&pout3, g_out3);
    cudaGetSymbolAddress(&pdense, g_dense);
    float*  A     = (float*)pA;
    float4* gFff  = (float4*)pgFff;
    int*    gIff  = (int*)pgIff;
    float4* gFwf  = (float4*)pgFwf;
    int*    gIwf  = (int*)pgIwf;
    float*  out1  = (float*)pout1;
    float*  out2  = (float*)pout2;
    float*  out3  = (float*)pout3;
    float*  dense = (float*)pdense;

    const int tot = NF * KNBR;
    detect_mask_kernel<<<1, 1024>>>((const unsigned int*)mask_wf);
    geom_kernel<<<(tot + 255)/256, 256>>>(wall_pos,  fluid_pos, nbr_wf, mask_wf, gFwf, gIwf);
    geom_kernel<<<(tot + 255)/256, 256>>>(fluid_pos, fluid_pos, nbr_ff, mask_ff, gFff, gIff);

    // layer 1
    conv1_kernel<<<NF/4, 256>>>(wall_nv,   nbr_wf, gFwf, gIwf, W_wall1,  b_wall1,  out1, 0);
    conv1_kernel<<<NF/4, 256>>>(fluid_vel, nbr_ff, gFff, gIff, W_fluid1, b_fluid1, out1, 32);
    dense_kernel<<<(NF*32 + 255)/256, 256>>>(fluid_vel, W_d1, b_d1, out1, 3, 32, 96, 64);

    // layer 2
    dense_kernel<<<(NF*64 + 255)/256, 256>>>(out1, W_d2, b_d2, dense, 96, 64, 64, 0);
    scatter_kernel<96, 1><<<NF, 96>>>(out1, nbr_ff, gFff, gIff, A);
    gemm_kernel<1, 0, 1><<<NF/128, 128>>>(A, W_c2, b_c2, dense, nullptr, out2, 6144);

    // layer 3
    dense_kernel<<<(NF*64 + 255)/256, 256>>>(out2, W_d3, b_d3, dense, 64, 64, 64, 0);
    scatter_kernel<64, 2><<<NF, 128>>>(out2, nbr_ff, gFff, gIff, A);
    gemm_kernel<1, 1, 1><<<NF/128, 128>>>(A, W_c3, b_c3, dense, out2, out3, 4096);

    // layer 4
    dense_kernel<<<(NF*3 + 255)/256, 256>>>(out3, W_d4, b_d4, dense, 64, 3, 3, 0);
    scatter_kernel<64, 2><<<NF, 128>>>(out3, nbr_ff, gFff, gIff, A);
    final_kernel<<<NF, 128>>>(A, W_c4, b_c4, dense, (float*)d_out);
}

// round 5
// speedup vs baseline: 1.4982x; 1.3140x over previous
#include <cuda_runtime.h>
#include <cstdint>
#include <cstddef>

#define NF   16000
#define KNBR 64
#define RADIUS_F ((float)(0.5*6.0*1.5*0.025))

// ---------------- scratch (device globals; no allocation APIs) ----------------
__device__ float  g_A[(size_t)NF * 64 * 96];   // scatter target (tf32-rounded), reused per layer
__device__ float4 g_gF_ff[NF * KNBR];
__device__ int    g_gI_ff[NF * KNBR];
__device__ float4 g_gF_wf[NF * KNBR];
__device__ int    g_gI_wf[NF * KNBR];
__device__ float  g_out1[NF * 96];
__device__ float  g_out2[NF * 64];
__device__ float  g_out3[NF * 64];
__device__ float  g_dense[NF * 64];
__device__ float  g_Wt2[6144 * 64];            // tf32-rounded W_c2 (same [K,64] layout)
__device__ float  g_Wt3[4096 * 64];            // tf32-rounded W_c3
__device__ int    g_mask_u8;

// ---------------- helpers ----------------
__device__ __forceinline__ uint32_t smem_u32(const void* p) {
    uint32_t a;
    asm("{ .reg .u64 t; cvta.to.shared.u64 t, %1; cvt.u32.u64 %0, t; }" : "=r"(a) : "l"(p));
    return a;
}
__device__ __forceinline__ void cp16(uint32_t dst, const void* src) {
    asm volatile("cp.async.cg.shared.global [%0], [%1], 16;" :: "r"(dst), "l"(src));
}
#define CP_COMMIT() asm volatile("cp.async.commit_group;" ::: "memory")
__device__ __forceinline__ float tf32_rna(float s) {
    uint32_t u;
    asm("cvt.rna.tf32.f32 %0, %1;" : "=r"(u) : "f"(s));
    return __uint_as_float(u);
}

// ---------------- mask dtype detector ----------------
__global__ void detect_mask_kernel(const unsigned int* __restrict__ m)
{
    __shared__ int s;
    if (threadIdx.x == 0) s = 0;
    __syncthreads();
    int bad = 0;
    for (int i = threadIdx.x; i < 65536; i += blockDim.x)
        if (m[i] > 1u) { bad = 1; break; }
    if (bad) atomicOr(&s, 1);
    __syncthreads();
    if (threadIdx.x == 0) g_mask_u8 = s;
}

// ---------------- geometry ----------------
static __device__ __forceinline__ float sgnf(float v) {
    return (v > 0.f) ? 1.f : ((v < 0.f) ? -1.f : 0.f);
}
__device__ __forceinline__ void gridmap(float u, int& i0, float& f) {
    float cc = (u * 0.5f + 0.5f) * 3.f;
    cc = fminf(fmaxf(cc, 0.f), 3.f);
    float fi = floorf(cc);
    fi = fminf(fi, 2.f);
    f = cc - fi;
    i0 = (int)fi;
}

__global__ void geom_kernel(const float* __restrict__ pin, const float* __restrict__ pout,
                            const int* __restrict__ nbr, const void* __restrict__ mask,
                            float4* __restrict__ gF, int* __restrict__ gI)
{
    int idx = blockIdx.x * blockDim.x + threadIdx.x;
    if (idx >= NF * KNBR) return;
    int mv = g_mask_u8 ? (int)((const unsigned char*)mask)[idx]
                       : ((const int*)mask)[idx];
    if (mv == 0) { gF[idx] = make_float4(0.f, 0.f, 0.f, 0.f); gI[idx] = 0; return; }
    int n = idx >> 6;
    int j = nbr[idx];
    float x = (pin[j*3+0] - pout[n*3+0]) / RADIUS_F;
    float y = (pin[j*3+1] - pout[n*3+1]) / RADIUS_F;
    float z = (pin[j*3+2] - pout[n*3+2]) / RADIUS_F;
    float sq = x*x + y*y + z*z;
    float t1 = 1.f - sq;
    float win = fminf(fmaxf(t1*t1*t1, 0.f), 1.f);

    const float eps = 1e-12f;
    float norm = sqrtf(fmaxf(sq, eps));
    float rho  = sqrtf(fmaxf(x*x + y*y, eps));
    bool  top  = (1.25f*z*z > x*x + y*y);
    float s_top = sqrtf(3.f*norm / (norm + fabsf(z)));
    float xs = top ? x*s_top : (x*norm)/rho;
    float ys = top ? y*s_top : (y*norm)/rho;
    float zs = top ? sgnf(z)*norm : 1.5f*z;
    if (sq < eps) { xs = 0.f; ys = 0.f; zs = 0.f; }
    float rxy = sqrtf(fmaxf(xs*xs + ys*ys, eps));
    bool use_x = fabsf(ys) <= fabsf(xs);
    float ddx = (use_x  && fabsf(xs) > eps) ? xs : 1.f;
    float ddy = (!use_x && fabsf(ys) > eps) ? ys : 1.f;
    const float c4 = 1.27323954473516276487f;  // 4/pi
    float xc = use_x ? sgnf(xs)*rxy : sgnf(ys)*rxy*c4*atanf(xs/ddy);
    float yc = use_x ? sgnf(xs)*rxy*c4*atanf(ys/ddx) : sgnf(ys)*rxy;
    if (xs*xs + ys*ys < eps) { xc = 0.f; yc = 0.f; }

    int ix, iy, iz; float fx, fy, fz;
    gridmap(xc, ix, fx); gridmap(yc, iy, fy); gridmap(zs, iz, fz);
    gF[idx] = make_float4(fx, fy, fz, win);
    gI[idx] = (ix*4 + iy)*4 + iz;
}

// ---------------- layer-1 cconv (cin=3, cout=32) ----------------
__global__ __launch_bounds__(256) void conv1_kernel(
    const float* __restrict__ feat, const int* __restrict__ nbr,
    const float4* __restrict__ gF, const int* __restrict__ gI,
    const float* __restrict__ W, const float* __restrict__ b,
    float* __restrict__ out1, int col0)
{
    __shared__ float A[4][192];
    __shared__ float red[256];
    int t = threadIdx.x;
    int p = t >> 6, tl = t & 63;
    int n = blockIdx.x * 4 + p;
    float* Ap = A[p];
    Ap[tl] = 0.f; Ap[tl + 64] = 0.f; Ap[tl + 128] = 0.f;
    __syncthreads();

    int idx = n * KNBR + tl;
    float4 g = gF[idx];
    if (g.w != 0.f) {
        int j = nbr[idx];
        float f0 = feat[j*3+0]*g.w, f1 = feat[j*3+1]*g.w, f2 = feat[j*3+2]*g.w;
        int base = gI[idx];
        float wx[2] = {1.f - g.x, g.x};
        float wy[2] = {1.f - g.y, g.y};
        float wz[2] = {1.f - g.z, g.z};
        #pragma unroll
        for (int cx = 0; cx < 2; cx++)
        #pragma unroll
        for (int cy = 0; cy < 2; cy++)
        #pragma unroll
        for (int cz = 0; cz < 2; cz++) {
            float wc = wx[cx]*wy[cy]*wz[cz];
            int cell = base + cx*16 + cy*4 + cz;
            atomicAdd(&Ap[cell*3+0], wc*f0);
            atomicAdd(&Ap[cell*3+1], wc*f1);
            atomicAdd(&Ap[cell*3+2], wc*f2);
        }
    }
    __syncthreads();

    int o = tl & 31, h = tl >> 5;
    float acc = 0.f;
    for (int i = h*96; i < h*96 + 96; i++)
        acc += Ap[i] * W[i*32 + o];
    red[t] = acc;
    __syncthreads();
    if (tl < 32) {
        float v = red[p*64 + tl] + red[p*64 + tl + 32] + b[o];
        out1[n*96 + col0 + tl] = fmaxf(v, 0.f);
    }
}

// ---------------- scatter: dense A[n, 64*CIN], tf32-rounded output ----------------
template<int CIN, int R, int TF32>
__global__ void scatter_kernel(const float* __restrict__ feat, const int* __restrict__ nbr,
                               const float4* __restrict__ gF, const int* __restrict__ gI,
                               float* __restrict__ A)
{
    constexpr int BD = CIN * R;
    __shared__ float sA[R * 64 * CIN];
    __shared__ float4 sG[KNBR];
    __shared__ int    sB[KNBR];
    __shared__ int    sJ[KNBR];
    int n = blockIdx.x, t = threadIdx.x;
    if (t < KNBR) { sG[t] = gF[n*KNBR + t]; sB[t] = gI[n*KNBR + t]; sJ[t] = nbr[n*KNBR + t]; }
    for (int i = t; i < R * 64 * CIN; i += BD) sA[i] = 0.f;
    __syncthreads();

    int c = t % CIN;
    int r = t / CIN;
    float* Ar = sA + r * 64 * CIN;
    const int KPR = KNBR / R;
    for (int k = r*KPR; k < (r+1)*KPR; k++) {
        float4 g = sG[k];
        if (g.w == 0.f) continue;
        float v = feat[(size_t)sJ[k]*CIN + c] * g.w;
        float wx0 = 1.f - g.x, wx1 = g.x;
        float wy0 = 1.f - g.y, wy1 = g.y;
        float wz0 = 1.f - g.z, wz1 = g.z;
        int p = sB[k]*CIN + c;
        Ar[p           ] += wx0*wy0*wz0*v;
        Ar[p +     CIN ] += wx0*wy0*wz1*v;
        Ar[p +  4*CIN  ] += wx0*wy1*wz0*v;
        Ar[p +  5*CIN  ] += wx0*wy1*wz1*v;
        Ar[p + 16*CIN  ] += wx1*wy0*wz0*v;
        Ar[p + 17*CIN  ] += wx1*wy0*wz1*v;
        Ar[p + 20*CIN  ] += wx1*wy1*wz0*v;
        Ar[p + 21*CIN  ] += wx1*wy1*wz1*v;
    }
    __syncthreads();

    float* out = A + (size_t)n * 64 * CIN;
    for (int i = t; i < 64 * CIN; i += BD) {
        float s = sA[i];
        #pragma unroll
        for (int rr = 1; rr < R; rr++) s += sA[rr*64*CIN + i];
        out[i] = TF32 ? tf32_rna(s) : s;
    }
}

// ---------------- tf32 round a weight tensor (same layout) ----------------
__global__ void cvt_tf32_kernel(const float* __restrict__ W, float* __restrict__ Wt, int nelem)
{
    int idx = blockIdx.x * blockDim.x + threadIdx.x;
    if (idx < nelem) Wt[idx] = tf32_rna(W[idx]);
}

// ---------------- tensor GEMM: out[M,64] = A[M,K] @ W[K,64], mma.sync tf32 ----------------
// 128 threads, tile 128x64, BK=32, 4-stage cp.async ring.
#define STAGES 4
#define A_LDS 36
#define B_LDS 72
#define A_STAGE (128*A_LDS)       // floats
#define B_STAGE (32*B_LDS)
#define GEMM_SMEM (STAGES*(A_STAGE + B_STAGE)*4)

template<int HAS_ADD, int HAS_RES, int RELU>
__global__ __launch_bounds__(128) void gemm_mma(
    const float* __restrict__ Ag, const float* __restrict__ Wt,
    const float* __restrict__ bias, const float* __restrict__ addv,
    const float* __restrict__ resv, float* __restrict__ out, int K)
{
    extern __shared__ float sm[];
    float* sA = sm;
    float* sB = sm + STAGES * A_STAGE;
    int tid = threadIdx.x, w = tid >> 5, lane = tid & 31;
    int g = lane >> 2, tg = lane & 3;
    int m0 = blockIdx.x * 128;
    int NIT = K >> 5;
    uint32_t sAu = smem_u32(sA), sBu = smem_u32(sB);

    auto load_stage = [&](int s, int c) {
        uint32_t ab = sAu + (uint32_t)s * A_STAGE * 4;
        const float* as = Ag + (size_t)m0 * K + c * 32;
        #pragma unroll
        for (int r = 0; r < 8; r++) {
            int idx = r * 128 + tid;
            int row = idx >> 3, seg = idx & 7;
            cp16(ab + (row * A_LDS + seg * 4) * 4, as + (size_t)row * K + seg * 4);
        }
        uint32_t bb = sBu + (uint32_t)s * B_STAGE * 4;
        const float* bs = Wt + (size_t)c * 32 * 64;
        #pragma unroll
        for (int r = 0; r < 4; r++) {
            int idx = r * 128 + tid;
            int row = idx >> 4, seg = idx & 15;
            cp16(bb + (row * B_LDS + seg * 4) * 4, bs + row * 64 + seg * 4);
        }
    };

    float acc[2][8][4];
    #pragma unroll
    for (int mt = 0; mt < 2; mt++)
        #pragma unroll
        for (int nt = 0; nt < 8; nt++)
            #pragma unroll
            for (int q = 0; q < 4; q++) acc[mt][nt][q] = 0.f;

    #pragma unroll
    for (int s = 0; s < STAGES; s++) { load_stage(s, s); CP_COMMIT(); }

    for (int i = 0; i < NIT; i++) {
        asm volatile("cp.async.wait_group %0;" :: "n"(STAGES - 1));
        __syncthreads();
        const float* cA = sA + (i % STAGES) * A_STAGE;
        const float* cB = sB + (i % STAGES) * B_STAGE;
        #pragma unroll
        for (int k8 = 0; k8 < 4; k8++) {
            int kb = k8 * 8;
            uint32_t a[2][4], b[8][2];
            #pragma unroll
            for (int mt = 0; mt < 2; mt++) {
                int r = w * 32 + mt * 16 + g;
                a[mt][0] = __float_as_uint(cA[(r    ) * A_LDS + kb + tg    ]);
                a[mt][1] = __float_as_uint(cA[(r + 8) * A_LDS + kb + tg    ]);
                a[mt][2] = __float_as_uint(cA[(r    ) * A_LDS + kb + tg + 4]);
                a[mt][3] = __float_as_uint(cA[(r + 8) * A_LDS + kb + tg + 4]);
            }
            #pragma unroll
            for (int nt = 0; nt < 8; nt++) {
                b[nt][0] = __float_as_uint(cB[(kb + tg    ) * B_LDS + nt * 8 + g]);
                b[nt][1] = __float_as_uint(cB[(kb + tg + 4) * B_LDS + nt * 8 + g]);
            }
            #pragma unroll
            for (int mt = 0; mt < 2; mt++)
                #pragma unroll
                for (int nt = 0; nt < 8; nt++)
                    asm volatile(
                        "mma.sync.aligned.m16n8k8.row.col.f32.tf32.tf32.f32 "
                        "{%0,%1,%2,%3},{%4,%5,%6,%7},{%8,%9},{%0,%1,%2,%3};"
                        : "+f"(acc[mt][nt][0]), "+f"(acc[mt][nt][1]),
                          "+f"(acc[mt][nt][2]), "+f"(acc[mt][nt][3])
                        : "r"(a[mt][0]), "r"(a[mt][1]), "r"(a[mt][2]), "r"(a[mt][3]),
                          "r"(b[nt][0]), "r"(b[nt][1]));
        }
        __syncthreads();
        if (i + STAGES < NIT) load_stage(i % STAGES, i + STAGES);
        CP_COMMIT();
    }

    // epilogue
    #pragma unroll
    for (int mt = 0; mt < 2; mt++) {
        #pragma unroll
        for (int nt = 0; nt < 8; nt++) {
            #pragma unroll
            for (int h = 0; h < 2; h++) {
                int m = m0 + w * 32 + mt * 16 + g + h * 8;
                int n0 = nt * 8 + 2 * tg;
                float lo = acc[mt][nt][h*2+0], hi = acc[mt][nt][h*2+1];
                float2 bb = *(const float2*)&bias[n0];
                lo += bb.x; hi += bb.y;
                if (HAS_ADD) {
                    float2 v = *(const float2*)&addv[(size_t)m*64 + n0];
                    lo += v.x; hi += v.y;
                }
                if (HAS_RES) {
                    float2 v = *(const float2*)&resv[(size_t)m*64 + n0];
                    lo += v.x; hi += v.y;
                }
                if (RELU) { lo = fmaxf(lo, 0.f); hi = fmaxf(hi, 0.f); }
                *(float2*)&out[(size_t)m*64 + n0] = make_float2(lo, hi);
            }
        }
    }
}

// ---------------- dense shortcut ----------------
__global__ void dense_kernel(const float* __restrict__ X, const float* __restrict__ W,
                             const float* __restrict__ b, float* __restrict__ Y,
                             int CIN, int COUT, int ldY, int col0)
{
    int idx = blockIdx.x * blockDim.x + threadIdx.x;
    if (idx >= NF * COUT) return;
    int n = idx / COUT, o = idx - n*COUT;
    float acc = b[o];
    const float* x = X + (size_t)n * CIN;
    for (int c = 0; c < CIN; c++) acc += x[c] * W[c*COUT + o];
    Y[(size_t)n*ldY + col0 + o] = acc;
}

// ---------------- final layer ----------------
__global__ void final_kernel(const float* __restrict__ A, const float* __restrict__ W,
                             const float* __restrict__ b, const float* __restrict__ dense,
                             float* __restrict__ out)
{
    int n = blockIdx.x, t = threadIdx.x;  // 128 threads
    const float* Ar = A + (size_t)n * 4096;
    float a0 = 0.f, a1 = 0.f, a2 = 0.f;
    for (int i = t; i < 4096; i += 128) {
        float av = Ar[i];
        a0 += av * W[i*3 + 0];
        a1 += av * W[i*3 + 1];
        a2 += av * W[i*3 + 2];
    }
    __shared__ float red[3][128];
    red[0][t] = a0; red[1][t] = a1; red[2][t] = a2;
    __syncthreads();
    for (int s = 64; s > 0; s >>= 1) {
        if (t < s) {
            red[0][t] += red[0][t+s];
            red[1][t] += red[1][t+s];
            red[2][t] += red[2][t+s];
        }
        __syncthreads();
    }
    if (t < 3) out[n*3 + t] = red[t][0] + b[t] + dense[n*3 + t];
}

// ---------------- launch ----------------
extern "C" void kernel_launch(void* const* d_in, const int* in_sizes, int n_in,
                              void* d_out, int out_size)
{
    const float* fluid_pos = (const float*)d_in[0];
    const float* wall_pos  = (const float*)d_in[1];
    const float* fluid_vel = (const float*)d_in[2];
    const float* wall_nv   = (const float*)d_in[3];
    const int*   nbr_wf    = (const int*)d_in[4];
    const void*  mask_wf   = d_in[5];
    const int*   nbr_ff    = (const int*)d_in[6];
    const void*  mask_ff   = d_in[7];
    const float* W_wall1 = (const float*)d_in[8];
    const float* b_wall1 = (const float*)d_in[9];
    const float* W_fluid1 = (const float*)d_in[10];
    const float* b_fluid1 = (const float*)d_in[11];
    const float* W_d1 = (const float*)d_in[12];
    const float* b_d1 = (const float*)d_in[13];
    const float* W_c2 = (const float*)d_in[14];
    const float* b_c2 = (const float*)d_in[15];
    const float* W_d2 = (const float*)d_in[16];
    const float* b_d2 = (const float*)d_in[17];
    const float* W_c3 = (const float*)d_in[18];
    const float* b_c3 = (const float*)d_in[19];
    const float* W_d3 = (const float*)d_in[20];
    const float* b_d3 = (const float*)d_in[21];
    const float* W_c4 = (const float*)d_in[22];
    const float* b_c4 = (const float*)d_in[23];
    const float* W_d4 = (const float*)d_in[24];
    const float* b_d4 = (const float*)d_in[25];

    void *pA, *pgFff, *pgIff, *pgFwf, *pgIwf, *pout1, *pout2, *pout3, *pdense, *pWt2, *pWt3;
    cudaGetSymbolAddress(&pA, g_A);
    cudaGetSymbolAddress(&pgFff, g_gF_ff);
    cudaGetSymbolAddress(&pgIff, g_gI_ff);
    cudaGetSymbolAddress(&pgFwf, g_gF_wf);
    cudaGetSymbolAddress(&pgIwf, g_gI_wf);
    cudaGetSymbolAddress(&pout1, g_out1);
    cudaGetSymbolAddress(&pout2, g_out2);
    cudaGetSymbolAddress(&pout3, g_out3);
    cudaGetSymbolAddress(&pdense, g_dense);
    cudaGetSymbolAddress(&pWt2, g_Wt2);
    cudaGetSymbolAddress(&pWt3, g_Wt3);
    float*  A     = (float*)pA;
    float4* gFff  = (float4*)pgFff;
    int*    gIff  = (int*)pgIff;
    float4* gFwf  = (float4*)pgFwf;
    int*    gIwf  = (int*)pgIwf;
    float*  out1  = (float*)pout1;
    float*  out2  = (float*)pout2;
    float*  out3  = (float*)pout3;
    float*  dense = (float*)pdense;
    float*  Wt2   = (float*)pWt2;
    float*  Wt3   = (float*)pWt3;

    cudaFuncSetAttribute(gemm_mma<1,0,1>, cudaFuncAttributeMaxDynamicSharedMemorySize, GEMM_SMEM);
    cudaFuncSetAttribute(gemm_mma<1,1,1>, cudaFuncAttributeMaxDynamicSharedMemorySize, GEMM_SMEM);

    const int tot = NF * KNBR;
    detect_mask_kernel<<<1, 1024>>>((const unsigned int*)mask_wf);
    geom_kernel<<<(tot + 255)/256, 256>>>(wall_pos,  fluid_pos, nbr_wf, mask_wf, gFwf, gIwf);
    geom_kernel<<<(tot + 255)/256, 256>>>(fluid_pos, fluid_pos, nbr_ff, mask_ff, gFff, gIff);
    cvt_tf32_kernel<<<(6144*64 + 255)/256, 256>>>(W_c2, Wt2, 6144*64);
    cvt_tf32_kernel<<<(4096*64 + 255)/256, 256>>>(W_c3, Wt3, 4096*64);

    // layer 1
    conv1_kernel<<<NF/4, 256>>>(wall_nv,   nbr_wf, gFwf, gIwf, W_wall1,  b_wall1,  out1, 0);
    conv1_kernel<<<NF/4, 256>>>(fluid_vel, nbr_ff, gFff, gIff, W_fluid1, b_fluid1, out1, 32);
    dense_kernel<<<(NF*32 + 255)/256, 256>>>(fluid_vel, W_d1, b_d1, out1, 3, 32, 96, 64);

    // layer 2
    dense_kernel<<<(NF*64 + 255)/256, 256>>>(out1, W_d2, b_d2, dense, 96, 64, 64, 0);
    scatter_kernel<96, 1, 1><<<NF, 96>>>(out1, nbr_ff, gFff, gIff, A);
    gemm_mma<1, 0, 1><<<NF/128, 128, GEMM_SMEM>>>(A, Wt2, b_c2, dense, nullptr, out2, 6144);

    // layer 3
    dense_kernel<<<(NF*64 + 255)/256, 256>>>(out2, W_d3, b_d3, dense, 64, 64, 64, 0);
    scatter_kernel<64, 2, 1><<<NF, 128>>>(out2, nbr_ff, gFff, gIff, A);
    gemm_mma<1, 1, 1><<<NF/128, 128, GEMM_SMEM>>>(A, Wt3, b_c3, dense, out2, out3, 4096);

    // layer 4 (fp32 A for the fp32 final reduction)
    dense_kernel<<<(NF*3 + 255)/256, 256>>>(out3, W_d4, b_d4, dense, 64, 3, 3, 0);
    scatter_kernel<64, 2, 0><<<NF, 128>>>(out3, nbr_ff, gFff, gIff, A);
    final_kernel<<<NF, 128>>>(A, W_c4, b_c4, dense, (float*)d_out);
}

// round 6
// speedup vs baseline: 1.7217x; 1.1492x over previous
#include <cuda_runtime.h>
#include <cuda_bf16.h>
#include <cstdint>
#include <cstddef>

#define NF   16000
#define KNBR 64
#define RADIUS_F ((float)(0.5*6.0*1.5*0.025))

// ---------------- scratch (device globals; no allocation APIs) ----------------
__device__ float  g_A[(size_t)NF * 64 * 96];   // scatter target (bf16 or fp32), reused per layer
__device__ float4 g_gF_ff[NF * KNBR];
__device__ int    g_gI_ff[NF * KNBR];
__device__ float4 g_gF_wf[NF * KNBR];
__device__ int    g_gI_wf[NF * KNBR];
__device__ float  g_out1[NF * 96];
__device__ float  g_out2[NF * 64];
__device__ float  g_out3[NF * 64];
__device__ float  g_dense[NF * 64];
__device__ uint32_t g_Wb2[3072 * 64];          // W_c2 packed bf16x2, [kp][n]
__device__ uint32_t g_Wb3[2048 * 64];          // W_c3 packed bf16x2
__device__ int    g_mask_u8;

// ---------------- helpers ----------------
__device__ __forceinline__ uint32_t smem_u32(const void* p) {
    uint32_t a;
    asm("{ .reg .u64 t; cvta.to.shared.u64 t, %1; cvt.u32.u64 %0, t; }" : "=r"(a) : "l"(p));
    return a;
}
__device__ __forceinline__ void cp16(uint32_t dst, const void* src) {
    asm volatile("cp.async.cg.shared.global [%0], [%1], 16;" :: "r"(dst), "l"(src));
}
#define CP_COMMIT() asm volatile("cp.async.commit_group;" ::: "memory")
__device__ __forceinline__ uint32_t bf16x2(float hi, float lo) {
    uint32_t r;
    asm("cvt.rn.bf16x2.f32 %0, %1, %2;" : "=r"(r) : "f"(hi), "f"(lo));
    return r;
}

// ---------------- mask dtype detector ----------------
__global__ void detect_mask_kernel(const unsigned int* __restrict__ m)
{
    __shared__ int s;
    if (threadIdx.x == 0) s = 0;
    __syncthreads();
    int bad = 0;
    for (int i = threadIdx.x; i < 65536; i += blockDim.x)
        if (m[i] > 1u) { bad = 1; break; }
    if (bad) atomicOr(&s, 1);
    __syncthreads();
    if (threadIdx.x == 0) g_mask_u8 = s;
}

// ---------------- geometry ----------------
static __device__ __forceinline__ float sgnf(float v) {
    return (v > 0.f) ? 1.f : ((v < 0.f) ? -1.f : 0.f);
}
__device__ __forceinline__ void gridmap(float u, int& i0, float& f) {
    float cc = (u * 0.5f + 0.5f) * 3.f;
    cc = fminf(fmaxf(cc, 0.f), 3.f);
    float fi = floorf(cc);
    fi = fminf(fi, 2.f);
    f = cc - fi;
    i0 = (int)fi;
}

__global__ void geom_kernel(const float* __restrict__ pin, const float* __restrict__ pout,
                            const int* __restrict__ nbr, const void* __restrict__ mask,
                            float4* __restrict__ gF, int* __restrict__ gI)
{
    int idx = blockIdx.x * blockDim.x + threadIdx.x;
    if (idx >= NF * KNBR) return;
    int mv = g_mask_u8 ? (int)((const unsigned char*)mask)[idx]
                       : ((const int*)mask)[idx];
    if (mv == 0) { gF[idx] = make_float4(0.f, 0.f, 0.f, 0.f); gI[idx] = 0; return; }
    int n = idx >> 6;
    int j = nbr[idx];
    float x = (pin[j*3+0] - pout[n*3+0]) / RADIUS_F;
    float y = (pin[j*3+1] - pout[n*3+1]) / RADIUS_F;
    float z = (pin[j*3+2] - pout[n*3+2]) / RADIUS_F;
    float sq = x*x + y*y + z*z;
    float t1 = 1.f - sq;
    float win = fminf(fmaxf(t1*t1*t1, 0.f), 1.f);

    const float eps = 1e-12f;
    float norm = sqrtf(fmaxf(sq, eps));
    float rho  = sqrtf(fmaxf(x*x + y*y, eps));
    bool  top  = (1.25f*z*z > x*x + y*y);
    float s_top = sqrtf(3.f*norm / (norm + fabsf(z)));
    float xs = top ? x*s_top : (x*norm)/rho;
    float ys = top ? y*s_top : (y*norm)/rho;
    float zs = top ? sgnf(z)*norm : 1.5f*z;
    if (sq < eps) { xs = 0.f; ys = 0.f; zs = 0.f; }
    float rxy = sqrtf(fmaxf(xs*xs + ys*ys, eps));
    bool use_x = fabsf(ys) <= fabsf(xs);
    float ddx = (use_x  && fabsf(xs) > eps) ? xs : 1.f;
    float ddy = (!use_x && fabsf(ys) > eps) ? ys : 1.f;
    const float c4 = 1.27323954473516276487f;  // 4/pi
    float xc = use_x ? sgnf(xs)*rxy : sgnf(ys)*rxy*c4*atanf(xs/ddy);
    float yc = use_x ? sgnf(xs)*rxy*c4*atanf(ys/ddx) : sgnf(ys)*rxy;
    if (xs*xs + ys*ys < eps) { xc = 0.f; yc = 0.f; }

    int ix, iy, iz; float fx, fy, fz;
    gridmap(xc, ix, fx); gridmap(yc, iy, fy); gridmap(zs, iz, fz);
    gF[idx] = make_float4(fx, fy, fz, win);
    gI[idx] = (ix*4 + iy)*4 + iz;
}

// ---------------- layer-1 cconv (cin=3, cout=32) ----------------
__global__ __launch_bounds__(256) void conv1_kernel(
    const float* __restrict__ feat, const int* __restrict__ nbr,
    const float4* __restrict__ gF, const int* __restrict__ gI,
    const float* __restrict__ W, const float* __restrict__ b,
    float* __restrict__ out1, int col0)
{
    __shared__ float A[4][192];
    __shared__ float red[256];
    int t = threadIdx.x;
    int p = t >> 6, tl = t & 63;
    int n = blockIdx.x * 4 + p;
    float* Ap = A[p];
    Ap[tl] = 0.f; Ap[tl + 64] = 0.f; Ap[tl + 128] = 0.f;
    __syncthreads();

    int idx = n * KNBR + tl;
    float4 g = gF[idx];
    if (g.w != 0.f) {
        int j = nbr[idx];
        float f0 = feat[j*3+0]*g.w, f1 = feat[j*3+1]*g.w, f2 = feat[j*3+2]*g.w;
        int base = gI[idx];
        float wx[2] = {1.f - g.x, g.x};
        float wy[2] = {1.f - g.y, g.y};
        float wz[2] = {1.f - g.z, g.z};
        #pragma unroll
        for (int cx = 0; cx < 2; cx++)
        #pragma unroll
        for (int cy = 0; cy < 2; cy++)
        #pragma unroll
        for (int cz = 0; cz < 2; cz++) {
            float wc = wx[cx]*wy[cy]*wz[cz];
            int cell = base + cx*16 + cy*4 + cz;
            atomicAdd(&Ap[cell*3+0], wc*f0);
            atomicAdd(&Ap[cell*3+1], wc*f1);
            atomicAdd(&Ap[cell*3+2], wc*f2);
        }
    }
    __syncthreads();

    int o = tl & 31, h = tl >> 5;
    float acc = 0.f;
    for (int i = h*96; i < h*96 + 96; i++)
        acc += Ap[i] * W[i*32 + o];
    red[t] = acc;
    __syncthreads();
    if (tl < 32) {
        float v = red[p*64 + tl] + red[p*64 + tl + 32] + b[o];
        out1[n*96 + col0 + tl] = fmaxf(v, 0.f);
    }
}

// ---------------- scatter: dense A[n, 64*CIN]; OUT 0=fp32, 1=packed bf16 ----------------
template<int CIN, int R, int OUTBF16>
__global__ void scatter_kernel(const float* __restrict__ feat, const int* __restrict__ nbr,
                               const float4* __restrict__ gF, const int* __restrict__ gI,
                               void* __restrict__ Aout)
{
    constexpr int BD = CIN * R;
    __shared__ float sA[R * 64 * CIN];
    __shared__ float4 sG[KNBR];
    __shared__ int    sB[KNBR];
    __shared__ int    sJ[KNBR];
    int n = blockIdx.x, t = threadIdx.x;
    if (t < KNBR) { sG[t] = gF[n*KNBR + t]; sB[t] = gI[n*KNBR + t]; sJ[t] = nbr[n*KNBR + t]; }
    for (int i = t; i < R * 64 * CIN; i += BD) sA[i] = 0.f;
    __syncthreads();

    int c = t % CIN;
    int r = t / CIN;
    float* Ar = sA + r * 64 * CIN;
    const int KPR = KNBR / R;
    for (int k = r*KPR; k < (r+1)*KPR; k++) {
        float4 g = sG[k];
        if (g.w == 0.f) continue;
        float v = feat[(size_t)sJ[k]*CIN + c] * g.w;
        float wx0 = 1.f - g.x, wx1 = g.x;
        float wy0 = 1.f - g.y, wy1 = g.y;
        float wz0 = 1.f - g.z, wz1 = g.z;
        int p = sB[k]*CIN + c;
        Ar[p           ] += wx0*wy0*wz0*v;
        Ar[p +     CIN ] += wx0*wy0*wz1*v;
        Ar[p +  4*CIN  ] += wx0*wy1*wz0*v;
        Ar[p +  5*CIN  ] += wx0*wy1*wz1*v;
        Ar[p + 16*CIN  ] += wx1*wy0*wz0*v;
        Ar[p + 17*CIN  ] += wx1*wy0*wz1*v;
        Ar[p + 20*CIN  ] += wx1*wy1*wz0*v;
        Ar[p + 21*CIN  ] += wx1*wy1*wz1*v;
    }
    __syncthreads();

    if (OUTBF16) {
        uint32_t* out = (uint32_t*)Aout + (size_t)n * 32 * CIN;
        for (int i = t; i < 32 * CIN; i += BD) {
            float lo = sA[2*i], hi = sA[2*i+1];
            #pragma unroll
            for (int rr = 1; rr < R; rr++) {
                lo += sA[rr*64*CIN + 2*i];
                hi += sA[rr*64*CIN + 2*i+1];
            }
            out[i] = bf16x2(hi, lo);
        }
    } else {
        float* out = (float*)Aout + (size_t)n * 64 * CIN;
        for (int i = t; i < 64 * CIN; i += BD) {
            float s = sA[i];
            #pragma unroll
            for (int rr = 1; rr < R; rr++) s += sA[rr*64*CIN + i];
            out[i] = s;
        }
    }
}

// ---------------- W pack: Wb[kp*64+n] = bf16x2(W[(2kp+1)*64+n], W[2kp*64+n]) ----------------
__global__ void pack_w_kernel(const float* __restrict__ W, uint32_t* __restrict__ Wb, int KP)
{
    int idx = blockIdx.x * blockDim.x + threadIdx.x;
    if (idx >= KP * 64) return;
    int kp = idx >> 6, n = idx & 63;
    Wb[idx] = bf16x2(W[(size_t)(2*kp+1)*64 + n], W[(size_t)(2*kp)*64 + n]);
}

// ---------------- bf16 tensor GEMM: out[M,64] = A[M,K] @ W[K,64], mma m16n8k16 ----------------
// 128 threads, tile 128x64, BK=32 (2 k16 chunks), 4-stage cp.async ring.
#define STAGES 4
#define A_WLDS 20                 // uint32 words per A row (16 data + 4 pad)
#define B_WLDS 72                 // uint32 words per B kp-row (64 data + 8 pad)
#define A_WSTAGE (128*A_WLDS)
#define B_WSTAGE (16*B_WLDS)
#define GEMM_SMEM (STAGES*(A_WSTAGE + B_WSTAGE)*4)

template<int HAS_ADD, int HAS_RES, int RELU>
__global__ __launch_bounds__(128) void gemm_mma(
    const __nv_bfloat16* __restrict__ Ag, const uint32_t* __restrict__ Wb,
    const float* __restrict__ bias, const float* __restrict__ addv,
    const float* __restrict__ resv, float* __restrict__ out, int K)
{
    extern __shared__ uint32_t sm[];
    uint32_t* sA = sm;
    uint32_t* sB = sm + STAGES * A_WSTAGE;
    int tid = threadIdx.x, w = tid >> 5, lane = tid & 31;
    int g = lane >> 2, tg = lane & 3;
    int m0 = blockIdx.x * 128;
    int NIT = K >> 5;
    uint32_t sAu = smem_u32(sA), sBu = smem_u32(sB);

    auto load_stage = [&](int s, int c) {
        uint32_t ab = sAu + (uint32_t)s * A_WSTAGE * 4;
        const __nv_bfloat16* as = Ag + (size_t)m0 * K + c * 32;
        #pragma unroll
        for (int r = 0; r < 4; r++) {
            int idx = r * 128 + tid;
            int row = idx >> 2, seg = idx & 3;
            cp16(ab + (row * A_WLDS + seg * 4) * 4, as + (size_t)row * K + seg * 8);
        }
        uint32_t bb = sBu + (uint32_t)s * B_WSTAGE * 4;
        const uint32_t* bs = Wb + (size_t)c * 16 * 64;
        #pragma unroll
        for (int r = 0; r < 2; r++) {
            int idx = r * 128 + tid;
            int kp = idx >> 4, seg = idx & 15;
            cp16(bb + (kp * B_WLDS + seg * 4) * 4, bs + kp * 64 + seg * 4);
        }
    };

    float acc[2][8][4];
    #pragma unroll
    for (int mt = 0; mt < 2; mt++)
        #pragma unroll
        for (int nt = 0; nt < 8; nt++)
            #pragma unroll
            for (int q = 0; q < 4; q++) acc[mt][nt][q] = 0.f;

    #pragma unroll
    for (int s = 0; s < STAGES; s++) { load_stage(s, s); CP_COMMIT(); }

    for (int i = 0; i < NIT; i++) {
        asm volatile("cp.async.wait_group %0;" :: "n"(STAGES - 1));
        __syncthreads();
        const uint32_t* cA = sA + (i % STAGES) * A_WSTAGE;
        const uint32_t* cB = sB + (i % STAGES) * B_WSTAGE;
        #pragma unroll
        for (int q = 0; q < 2; q++) {          // two k16 chunks per BK=32
            uint32_t a[2][4], b[8][2];
            #pragma unroll
            for (int mt = 0; mt < 2; mt++) {
                int r = w * 32 + mt * 16 + g;
                a[mt][0] = cA[(r    ) * A_WLDS + 8*q + tg    ];
                a[mt][1] = cA[(r + 8) * A_WLDS + 8*q + tg    ];
                a[mt][2] = cA[(r    ) * A_WLDS + 8*q + tg + 4];
                a[mt][3] = cA[(r + 8) * A_WLDS + 8*q + tg + 4];
            }
            #pragma unroll
            for (int nt = 0; nt < 8; nt++) {
                b[nt][0] = cB[(8*q + tg    ) * B_WLDS + nt * 8 + g];
                b[nt][1] = cB[(8*q + tg + 4) * B_WLDS + nt * 8 + g];
            }
            #pragma unroll
            for (int mt = 0; mt < 2; mt++)
                #pragma unroll
                for (int nt = 0; nt < 8; nt++)
                    asm volatile(
                        "mma.sync.aligned.m16n8k16.row.col.f32.bf16.bf16.f32 "
                        "{%0,%1,%2,%3},{%4,%5,%6,%7},{%8,%9},{%0,%1,%2,%3};"
                        : "+f"(acc[mt][nt][0]), "+f"(acc[mt][nt][1]),
                          "+f"(acc[mt][nt][2]), "+f"(acc[mt][nt][3])
                        : "r"(a[mt][0]), "r"(a[mt][1]), "r"(a[mt][2]), "r"(a[mt][3]),
                          "r"(b[nt][0]), "r"(b[nt][1]));
        }
        __syncthreads();
        if (i + STAGES < NIT) load_stage(i % STAGES, i + STAGES);
        CP_COMMIT();
    }

    // epilogue: acc[mt][nt] rows (g, g+8), cols (2tg, 2tg+1)
    #pragma unroll
    for (int mt = 0; mt < 2; mt++) {
        #pragma unroll
        for (int nt = 0; nt < 8; nt++) {
            #pragma unroll
            for (int h = 0; h < 2; h++) {
                int m = m0 + w * 32 + mt * 16 + g + h * 8;
                int n0 = nt * 8 + 2 * tg;
                float lo = acc[mt][nt][h*2+0], hi = acc[mt][nt][h*2+1];
                float2 bb = *(const float2*)&bias[n0];
                lo += bb.x; hi += bb.y;
                if (HAS_ADD) {
                    float2 v = *(const float2*)&addv[(size_t)m*64 + n0];
                    lo += v.x; hi += v.y;
                }
                if (HAS_RES) {
                    float2 v = *(const float2*)&resv[(size_t)m*64 + n0];
                    lo += v.x; hi += v.y;
                }
                if (RELU) { lo = fmaxf(lo, 0.f); hi = fmaxf(hi, 0.f); }
                *(float2*)&out[(size_t)m*64 + n0] = make_float2(lo, hi);
            }
        }
    }
}

// ---------------- dense shortcut ----------------
__global__ void dense_kernel(const float* __restrict__ X, const float* __restrict__ W,
                             const float* __restrict__ b, float* __restrict__ Y,
                             int CIN, int COUT, int ldY, int col0)
{
    int idx = blockIdx.x * blockDim.x + threadIdx.x;
    if (idx >= NF * COUT) return;
    int n = idx / COUT, o = idx - n*COUT;
    float acc = b[o];
    const float* x = X + (size_t)n * CIN;
    for (int c = 0; c < CIN; c++) acc += x[c] * W[c*COUT + o];
    Y[(size_t)n*ldY + col0 + o] = acc;
}

// ---------------- final layer (fp32) ----------------
__global__ void final_kernel(const float* __restrict__ A, const float* __restrict__ W,
                             const float* __restrict__ b, const float* __restrict__ dense,
                             float* __restrict__ out)
{
    int n = blockIdx.x, t = threadIdx.x;  // 128 threads
    const float* Ar = A + (size_t)n * 4096;
    float a0 = 0.f, a1 = 0.f, a2 = 0.f;
    for (int i = t; i < 4096; i += 128) {
        float av = Ar[i];
        a0 += av * W[i*3 + 0];
        a1 += av * W[i*3 + 1];
        a2 += av * W[i*3 + 2];
    }
    __shared__ float red[3][128];
    red[0][t] = a0; red[1][t] = a1; red[2][t] = a2;
    __syncthreads();
    for (int s = 64; s > 0; s >>= 1) {
        if (t < s) {
            red[0][t] += red[0][t+s];
            red[1][t] += red[1][t+s];
            red[2][t] += red[2][t+s];
        }
        __syncthreads();
    }
    if (t < 3) out[n*3 + t] = red[t][0] + b[t] + dense[n*3 + t];
}

// ---------------- launch ----------------
extern "C" void kernel_launch(void* const* d_in, const int* in_sizes, int n_in,
                              void* d_out, int out_size)
{
    const float* fluid_pos = (const float*)d_in[0];
    const float* wall_pos  = (const float*)d_in[1];
    const float* fluid_vel = (const float*)d_in[2];
    const float* wall_nv   = (const float*)d_in[3];
    const int*   nbr_wf    = (const int*)d_in[4];
    const void*  mask_wf   = d_in[5];
    const int*   nbr_ff    = (const int*)d_in[6];
    const void*  mask_ff   = d_in[7];
    const float* W_wall1 = (const float*)d_in[8];
    const float* b_wall1 = (const float*)d_in[9];
    const float* W_fluid1 = (const float*)d_in[10];
    const float* b_fluid1 = (const float*)d_in[11];
    const float* W_d1 = (const float*)d_in[12];
    const float* b_d1 = (const float*)d_in[13];
    const float* W_c2 = (const float*)d_in[14];
    const float* b_c2 = (const float*)d_in[15];
    const float* W_d2 = (const float*)d_in[16];
    const float* b_d2 = (const float*)d_in[17];
    const float* W_c3 = (const float*)d_in[18];
    const float* b_c3 = (const float*)d_in[19];
    const float* W_d3 = (const float*)d_in[20];
    const float* b_d3 = (const float*)d_in[21];
    const float* W_c4 = (const float*)d_in[22];
    const float* b_c4 = (const float*)d_in[23];
    const float* W_d4 = (const float*)d_in[24];
    const float* b_d4 = (const float*)d_in[25];

    void *pA, *pgFff, *pgIff, *pgFwf, *pgIwf, *pout1, *pout2, *pout3, *pdense, *pWb2, *pWb3;
    cudaGetSymbolAddress(&pA, g_A);
    cudaGetSymbolAddress(&pgFff, g_gF_ff);
    cudaGetSymbolAddress(&pgIff, g_gI_ff);
    cudaGetSymbolAddress(&pgFwf, g_gF_wf);
    cudaGetSymbolAddress(&pgIwf, g_gI_wf);
    cudaGetSymbolAddress(&pout1, g_out1);
    cudaGetSymbolAddress(&pout2, g_out2);
    cudaGetSymbolAddress(&pout3, g_out3);
    cudaGetSymbolAddress(&pdense, g_dense);
    cudaGetSymbolAddress(&pWb2, g_Wb2);
    cudaGetSymbolAddress(&pWb3, g_Wb3);
    void*   A     = pA;
    float4* gFff  = (float4*)pgFff;
    int*    gIff  = (int*)pgIff;
    float4* gFwf  = (float4*)pgFwf;
    int*    gIwf  = (int*)pgIwf;
    float*  out1  = (float*)pout1;
    float*  out2  = (float*)pout2;
    float*  out3  = (float*)pout3;
    float*  dense = (float*)pdense;
    uint32_t* Wb2 = (uint32_t*)pWb2;
    uint32_t* Wb3 = (uint32_t*)pWb3;

    cudaFuncSetAttribute(gemm_mma<1,0,1>, cudaFuncAttributeMaxDynamicSharedMemorySize, GEMM_SMEM);
    cudaFuncSetAttribute(gemm_mma<1,1,1>, cudaFuncAttributeMaxDynamicSharedMemorySize, GEMM_SMEM);

    const int tot = NF * KNBR;
    detect_mask_kernel<<<1, 1024>>>((const unsigned int*)mask_wf);
    geom_kernel<<<(tot + 255)/256, 256>>>(wall_pos,  fluid_pos, nbr_wf, mask_wf, gFwf, gIwf);
    geom_kernel<<<(tot + 255)/256, 256>>>(fluid_pos, fluid_pos, nbr_ff, mask_ff, gFff, gIff);
    pack_w_kernel<<<(3072*64 + 255)/256, 256>>>(W_c2, Wb2, 3072);
    pack_w_kernel<<<(2048*64 + 255)/256, 256>>>(W_c3, Wb3, 2048);

    // layer 1
    conv1_kernel<<<NF/4, 256>>>(wall_nv,   nbr_wf, gFwf, gIwf, W_wall1,  b_wall1,  out1, 0);
    conv1_kernel<<<NF/4, 256>>>(fluid_vel, nbr_ff, gFff, gIff, W_fluid1, b_fluid1, out1, 32);
    dense_kernel<<<(NF*32 + 255)/256, 256>>>(fluid_vel, W_d1, b_d1, out1, 3, 32, 96, 64);

    // layer 2
    dense_kernel<<<(NF*64 + 255)/256, 256>>>(out1, W_d2, b_d2, dense, 96, 64, 64, 0);
    scatter_kernel<96, 1, 1><<<NF, 96>>>(out1, nbr_ff, gFff, gIff, A);
    gemm_mma<1, 0, 1><<<NF/128, 128, GEMM_SMEM>>>((const __nv_bfloat16*)A, Wb2, b_c2, dense, nullptr, out2, 6144);

    // layer 3
    dense_kernel<<<(NF*64 + 255)/256, 256>>>(out2, W_d3, b_d3, dense, 64, 64, 64, 0);
    scatter_kernel<64, 2, 1><<<NF, 128>>>(out2, nbr_ff, gFff, gIff, A);
    gemm_mma<1, 1, 1><<<NF/128, 128, GEMM_SMEM>>>((const __nv_bfloat16*)A, Wb3, b_c3, dense, out2, out3, 4096);

    // layer 4 (fp32 A for the fp32 final reduction)
    dense_kernel<<<(NF*3 + 255)/256, 256>>>(out3, W_d4, b_d4, dense, 64, 3, 3, 0);
    scatter_kernel<64, 2, 0><<<NF, 128>>>(out3, nbr_ff, gFff, gIff, A);
    final_kernel<<<NF, 128>>>((const float*)A, W_c4, b_c4, dense, (float*)d_out);
}

// round 7
// speedup vs baseline: 2.0113x; 1.1682x over previous
#include <cuda_runtime.h>
#include <cuda_bf16.h>
#include <cstdint>
#include <cstddef>

#define NF   16000
#define KNBR 64
#define RADIUS_F ((float)(0.5*6.0*1.5*0.025))

// ---------------- scratch (device globals; no allocation APIs) ----------------
__device__ float  g_A[(size_t)NF * 64 * 96];   // scatter target (bf16 or fp32), reused per layer
__device__ float4 g_gF_ff[NF * KNBR];
__device__ int    g_gI_ff[NF * KNBR];
__device__ float4 g_gF_wf[NF * KNBR];
__device__ int    g_gI_wf[NF * KNBR];
__device__ float  g_out1[NF * 96];
__device__ float  g_out2[NF * 64];
__device__ float  g_out3[NF * 64];
__device__ float  g_dense[NF * 64];
__device__ uint32_t g_Wb2[3072 * 64];          // W_c2 packed bf16x2, [kp][n]
__device__ uint32_t g_Wb3[2048 * 64];          // W_c3 packed bf16x2
__device__ int    g_mask_u8;

// ---------------- helpers ----------------
__device__ __forceinline__ uint32_t smem_u32(const void* p) {
    uint32_t a;
    asm("{ .reg .u64 t; cvta.to.shared.u64 t, %1; cvt.u32.u64 %0, t; }" : "=r"(a) : "l"(p));
    return a;
}
__device__ __forceinline__ void cp16(uint32_t dst, const void* src) {
    asm volatile("cp.async.cg.shared.global [%0], [%1], 16;" :: "r"(dst), "l"(src));
}
#define CP_COMMIT() asm volatile("cp.async.commit_group;" ::: "memory")
__device__ __forceinline__ uint32_t bf16x2(float hi, float lo) {
    uint32_t r;
    asm("cvt.rn.bf16x2.f32 %0, %1, %2;" : "=r"(r) : "f"(hi), "f"(lo));
    return r;
}

// ---------------- mask dtype detector ----------------
__global__ void detect_mask_kernel(const unsigned int* __restrict__ m)
{
    __shared__ int s;
    if (threadIdx.x == 0) s = 0;
    __syncthreads();
    int bad = 0;
    for (int i = threadIdx.x; i < 65536; i += blockDim.x)
        if (m[i] > 1u) { bad = 1; break; }
    if (bad) atomicOr(&s, 1);
    __syncthreads();
    if (threadIdx.x == 0) g_mask_u8 = s;
}

// ---------------- geometry ----------------
static __device__ __forceinline__ float sgnf(float v) {
    return (v > 0.f) ? 1.f : ((v < 0.f) ? -1.f : 0.f);
}
__device__ __forceinline__ void gridmap(float u, int& i0, float& f) {
    float cc = (u * 0.5f + 0.5f) * 3.f;
    cc = fminf(fmaxf(cc, 0.f), 3.f);
    float fi = floorf(cc);
    fi = fminf(fi, 2.f);
    f = cc - fi;
    i0 = (int)fi;
}

__global__ void geom_kernel(const float* __restrict__ pin, const float* __restrict__ pout,
                            const int* __restrict__ nbr, const void* __restrict__ mask,
                            float4* __restrict__ gF, int* __restrict__ gI)
{
    int idx = blockIdx.x * blockDim.x + threadIdx.x;
    if (idx >= NF * KNBR) return;
    int mv = g_mask_u8 ? (int)((const unsigned char*)mask)[idx]
                       : ((const int*)mask)[idx];
    if (mv == 0) { gF[idx] = make_float4(0.f, 0.f, 0.f, 0.f); gI[idx] = 0; return; }
    int n = idx >> 6;
    int j = nbr[idx];
    float x = (pin[j*3+0] - pout[n*3+0]) / RADIUS_F;
    float y = (pin[j*3+1] - pout[n*3+1]) / RADIUS_F;
    float z = (pin[j*3+2] - pout[n*3+2]) / RADIUS_F;
    float sq = x*x + y*y + z*z;
    float t1 = 1.f - sq;
    float win = fminf(fmaxf(t1*t1*t1, 0.f), 1.f);

    const float eps = 1e-12f;
    float norm = sqrtf(fmaxf(sq, eps));
    float rho  = sqrtf(fmaxf(x*x + y*y, eps));
    bool  top  = (1.25f*z*z > x*x + y*y);
    float s_top = sqrtf(3.f*norm / (norm + fabsf(z)));
    float xs = top ? x*s_top : (x*norm)/rho;
    float ys = top ? y*s_top : (y*norm)/rho;
    float zs = top ? sgnf(z)*norm : 1.5f*z;
    if (sq < eps) { xs = 0.f; ys = 0.f; zs = 0.f; }
    float rxy = sqrtf(fmaxf(xs*xs + ys*ys, eps));
    bool use_x = fabsf(ys) <= fabsf(xs);
    float ddx = (use_x  && fabsf(xs) > eps) ? xs : 1.f;
    float ddy = (!use_x && fabsf(ys) > eps) ? ys : 1.f;
    const float c4 = 1.27323954473516276487f;  // 4/pi
    float xc = use_x ? sgnf(xs)*rxy : sgnf(ys)*rxy*c4*atanf(xs/ddy);
    float yc = use_x ? sgnf(xs)*rxy*c4*atanf(ys/ddx) : sgnf(ys)*rxy;
    if (xs*xs + ys*ys < eps) { xc = 0.f; yc = 0.f; }

    int ix, iy, iz; float fx, fy, fz;
    gridmap(xc, ix, fx); gridmap(yc, iy, fy); gridmap(zs, iz, fz);
    gF[idx] = make_float4(fx, fy, fz, win);
    gI[idx] = (ix*4 + iy)*4 + iz;
}

// ---------------- layer-1 cconv (cin=3, cout=32) ----------------
__global__ __launch_bounds__(256) void conv1_kernel(
    const float* __restrict__ feat, const int* __restrict__ nbr,
    const float4* __restrict__ gF, const int* __restrict__ gI,
    const float* __restrict__ W, const float* __restrict__ b,
    float* __restrict__ out1, int col0)
{
    __shared__ float A[4][192];
    __shared__ float red[256];
    int t = threadIdx.x;
    int p = t >> 6, tl = t & 63;
    int n = blockIdx.x * 4 + p;
    float* Ap = A[p];
    Ap[tl] = 0.f; Ap[tl + 64] = 0.f; Ap[tl + 128] = 0.f;
    __syncthreads();

    int idx = n * KNBR + tl;
    float4 g = gF[idx];
    if (g.w != 0.f) {
        int j = nbr[idx];
        float f0 = feat[j*3+0]*g.w, f1 = feat[j*3+1]*g.w, f2 = feat[j*3+2]*g.w;
        int base = gI[idx];
        float wx[2] = {1.f - g.x, g.x};
        float wy[2] = {1.f - g.y, g.y};
        float wz[2] = {1.f - g.z, g.z};
        #pragma unroll
        for (int cx = 0; cx < 2; cx++)
        #pragma unroll
        for (int cy = 0; cy < 2; cy++)
        #pragma unroll
        for (int cz = 0; cz < 2; cz++) {
            float wc = wx[cx]*wy[cy]*wz[cz];
            int cell = base + cx*16 + cy*4 + cz;
            atomicAdd(&Ap[cell*3+0], wc*f0);
            atomicAdd(&Ap[cell*3+1], wc*f1);
            atomicAdd(&Ap[cell*3+2], wc*f2);
        }
    }
    __syncthreads();

    int o = tl & 31, h = tl >> 5;
    float acc = 0.f;
    for (int i = h*96; i < h*96 + 96; i++)
        acc += Ap[i] * W[i*32 + o];
    red[t] = acc;
    __syncthreads();
    if (tl < 32) {
        float v = red[p*64 + tl] + red[p*64 + tl + 32] + b[o];
        out1[n*96 + col0 + tl] = fmaxf(v, 0.f);
    }
}

// ---------------- cellgemm: A[n] = S[n] @ F[n] on tensor cores ----------------
// S[64 cells x 64 nbr] bf16 built in smem (unique (cell,k) -> no RMW);
// F[64 nbr x CIN] gathered rows; out = packed-bf16 A row, layout [cell][c].
#define S_WLDS 36                  // words per S row (32 data + 4 pad); bank-exact
template<int CIN>
__global__ __launch_bounds__(128) void cellgemm_kernel(
    const float* __restrict__ feat, const int* __restrict__ nbr,
    const float4* __restrict__ gF, const int* __restrict__ gI,
    uint32_t* __restrict__ Aout)
{
    constexpr int F_WLDS = CIN + 8;          // words per kp row
    constexpr int NT = CIN / 8;
    __shared__ uint32_t sS[64 * S_WLDS];
    __shared__ uint32_t sF[32 * F_WLDS];
    __shared__ float4 sG[KNBR];
    __shared__ int    sJ[KNBR];
    __shared__ int    sB[KNBR];
    int n = blockIdx.x, t = threadIdx.x;
    int w = t >> 5, lane = t & 31;
    int g = lane >> 2, tg = lane & 3;

    if (t < KNBR) { sG[t] = gF[n*KNBR + t]; sB[t] = gI[n*KNBR + t]; sJ[t] = nbr[n*KNBR + t]; }
    for (int i = t; i < 64 * S_WLDS; i += 128) sS[i] = 0;
    __syncthreads();

    // build S: thread t<64 owns neighbor k=t; writes 8 unique (cell,k) bf16 entries
    if (t < KNBR) {
        float4 gv = sG[t];
        if (gv.w != 0.f) {
            __nv_bfloat16* Sh = (__nv_bfloat16*)sS;
            int base = sB[t];
            float wx0 = (1.f - gv.x) * gv.w, wx1 = gv.x * gv.w;
            float wy0 = 1.f - gv.y, wy1 = gv.y;
            float wz0 = 1.f - gv.z, wz1 = gv.z;
            Sh[(base     ) * (2*S_WLDS) + t] = __float2bfloat16(wx0*wy0*wz0);
            Sh[(base +  1) * (2*S_WLDS) + t] = __float2bfloat16(wx0*wy0*wz1);
            Sh[(base +  4) * (2*S_WLDS) + t] = __float2bfloat16(wx0*wy1*wz0);
            Sh[(base +  5) * (2*S_WLDS) + t] = __float2bfloat16(wx0*wy1*wz1);
            Sh[(base + 16) * (2*S_WLDS) + t] = __float2bfloat16(wx1*wy0*wz0);
            Sh[(base + 17) * (2*S_WLDS) + t] = __float2bfloat16(wx1*wy0*wz1);
            Sh[(base + 20) * (2*S_WLDS) + t] = __float2bfloat16(wx1*wy1*wz0);
            Sh[(base + 21) * (2*S_WLDS) + t] = __float2bfloat16(wx1*wy1*wz1);
        }
    }

    // gather F: word [kp][c] = bf16x2(feat[j_{2kp+1}][c], feat[j_{2kp}][c])
    for (int i = t; i < 32 * CIN; i += 128) {
        int kp = i / CIN, c = i - kp * CIN;
        float f0 = feat[(size_t)sJ[2*kp    ] * CIN + c];
        float f1 = feat[(size_t)sJ[2*kp + 1] * CIN + c];
        sF[kp * F_WLDS + c] = bf16x2(f1, f0);
    }
    __syncthreads();

    // mma: warp w computes cells w*16 .. w*16+15, all CIN columns
    float acc[NT][4];
    #pragma unroll
    for (int nt = 0; nt < NT; nt++)
        #pragma unroll
        for (int q = 0; q < 4; q++) acc[nt][q] = 0.f;

    #pragma unroll
    for (int q = 0; q < 4; q++) {            // k16 steps over K=64
        int r = w * 16 + g;
        uint32_t a0 = sS[(r    ) * S_WLDS + 8*q + tg    ];
        uint32_t a1 = sS[(r + 8) * S_WLDS + 8*q + tg    ];
        uint32_t a2 = sS[(r    ) * S_WLDS + 8*q + tg + 4];
        uint32_t a3 = sS[(r + 8) * S_WLDS + 8*q + tg + 4];
        #pragma unroll
        for (int nt = 0; nt < NT; nt++) {
            uint32_t b0 = sF[(8*q + tg    ) * F_WLDS + nt * 8 + g];
            uint32_t b1 = sF[(8*q + tg + 4) * F_WLDS + nt * 8 + g];
            asm volatile(
                "mma.sync.aligned.m16n8k16.row.col.f32.bf16.bf16.f32 "
                "{%0,%1,%2,%3},{%4,%5,%6,%7},{%8,%9},{%0,%1,%2,%3};"
                : "+f"(acc[nt][0]), "+f"(acc[nt][1]), "+f"(acc[nt][2]), "+f"(acc[nt][3])
                : "r"(a0), "r"(a1), "r"(a2), "r"(a3), "r"(b0), "r"(b1));
        }
    }

    // write packed bf16 A row: word = cell*(CIN/2) + nt*4 + tg
    uint32_t* out = Aout + (size_t)n * (32 * CIN);
    #pragma unroll
    for (int nt = 0; nt < NT; nt++) {
        #pragma unroll
        for (int h = 0; h < 2; h++) {
            int cell = w * 16 + g + h * 8;
            out[cell * (CIN/2) + nt * 4 + tg] = bf16x2(acc[nt][h*2+1], acc[nt][h*2+0]);
        }
    }
}

// ---------------- scatter (fp32, layer 4 only) ----------------
template<int CIN, int R>
__global__ void scatter_kernel(const float* __restrict__ feat, const int* __restrict__ nbr,
                               const float4* __restrict__ gF, const int* __restrict__ gI,
                               float* __restrict__ Aout)
{
    constexpr int BD = CIN * R;
    __shared__ float sA[R * 64 * CIN];
    __shared__ float4 sG[KNBR];
    __shared__ int    sB[KNBR];
    __shared__ int    sJ[KNBR];
    int n = blockIdx.x, t = threadIdx.x;
    if (t < KNBR) { sG[t] = gF[n*KNBR + t]; sB[t] = gI[n*KNBR + t]; sJ[t] = nbr[n*KNBR + t]; }
    for (int i = t; i < R * 64 * CIN; i += BD) sA[i] = 0.f;
    __syncthreads();

    int c = t % CIN;
    int r = t / CIN;
    float* Ar = sA + r * 64 * CIN;
    const int KPR = KNBR / R;
    for (int k = r*KPR; k < (r+1)*KPR; k++) {
        float4 g = sG[k];
        if (g.w == 0.f) continue;
        float v = feat[(size_t)sJ[k]*CIN + c] * g.w;
        float wx0 = 1.f - g.x, wx1 = g.x;
        float wy0 = 1.f - g.y, wy1 = g.y;
        float wz0 = 1.f - g.z, wz1 = g.z;
        int p = sB[k]*CIN + c;
        Ar[p           ] += wx0*wy0*wz0*v;
        Ar[p +     CIN ] += wx0*wy0*wz1*v;
        Ar[p +  4*CIN  ] += wx0*wy1*wz0*v;
        Ar[p +  5*CIN  ] += wx0*wy1*wz1*v;
        Ar[p + 16*CIN  ] += wx1*wy0*wz0*v;
        Ar[p + 17*CIN  ] += wx1*wy0*wz1*v;
        Ar[p + 20*CIN  ] += wx1*wy1*wz0*v;
        Ar[p + 21*CIN  ] += wx1*wy1*wz1*v;
    }
    __syncthreads();

    float* out = Aout + (size_t)n * 64 * CIN;
    for (int i = t; i < 64 * CIN; i += BD) {
        float s = sA[i];
        #pragma unroll
        for (int rr = 1; rr < R; rr++) s += sA[rr*64*CIN + i];
        out[i] = s;
    }
}

// ---------------- W pack: Wb[kp*64+n] = bf16x2(W[(2kp+1)*64+n], W[2kp*64+n]) ----------------
__global__ void pack_w_kernel(const float* __restrict__ W, uint32_t* __restrict__ Wb, int KP)
{
    int idx = blockIdx.x * blockDim.x + threadIdx.x;
    if (idx >= KP * 64) return;
    int kp = idx >> 6, n = idx & 63;
    Wb[idx] = bf16x2(W[(size_t)(2*kp+1)*64 + n], W[(size_t)(2*kp)*64 + n]);
}

// ---------------- bf16 tensor GEMM: out[M,64] = A[M,K] @ W[K,64], mma m16n8k16 ----------------
#define STAGES 4
#define A_WLDS 20
#define B_WLDS 72
#define A_WSTAGE (128*A_WLDS)
#define B_WSTAGE (16*B_WLDS)
#define GEMM_SMEM (STAGES*(A_WSTAGE + B_WSTAGE)*4)

template<int HAS_ADD, int HAS_RES, int RELU>
__global__ __launch_bounds__(128) void gemm_mma(
    const __nv_bfloat16* __restrict__ Ag, const uint32_t* __restrict__ Wb,
    const float* __restrict__ bias, const float* __restrict__ addv,
    const float* __restrict__ resv, float* __restrict__ out, int K)
{
    extern __shared__ uint32_t sm[];
    uint32_t* sA = sm;
    uint32_t* sB = sm + STAGES * A_WSTAGE;
    int tid = threadIdx.x, w = tid >> 5, lane = tid & 31;
    int g = lane >> 2, tg = lane & 3;
    int m0 = blockIdx.x * 128;
    int NIT = K >> 5;
    uint32_t sAu = smem_u32(sA), sBu = smem_u32(sB);

    auto load_stage = [&](int s, int c) {
        uint32_t ab = sAu + (uint32_t)s * A_WSTAGE * 4;
        const __nv_bfloat16* as = Ag + (size_t)m0 * K + c * 32;
        #pragma unroll
        for (int r = 0; r < 4; r++) {
            int idx = r * 128 + tid;
            int row = idx >> 2, seg = idx & 3;
            cp16(ab + (row * A_WLDS + seg * 4) * 4, as + (size_t)row * K + seg * 8);
        }
        uint32_t bb = sBu + (uint32_t)s * B_WSTAGE * 4;
        const uint32_t* bs = Wb + (size_t)c * 16 * 64;
        #pragma unroll
        for (int r = 0; r < 2; r++) {
            int idx = r * 128 + tid;
            int kp = idx >> 4, seg = idx & 15;
            cp16(bb + (kp * B_WLDS + seg * 4) * 4, bs + kp * 64 + seg * 4);
        }
    };

    float acc[2][8][4];
    #pragma unroll
    for (int mt = 0; mt < 2; mt++)
        #pragma unroll
        for (int nt = 0; nt < 8; nt++)
            #pragma unroll
            for (int q = 0; q < 4; q++) acc[mt][nt][q] = 0.f;

    #pragma unroll
    for (int s = 0; s < STAGES; s++) { load_stage(s, s); CP_COMMIT(); }

    for (int i = 0; i < NIT; i++) {
        asm volatile("cp.async.wait_group %0;" :: "n"(STAGES - 1));
        __syncthreads();
        const uint32_t* cA = sA + (i % STAGES) * A_WSTAGE;
        const uint32_t* cB = sB + (i % STAGES) * B_WSTAGE;
        #pragma unroll
        for (int q = 0; q < 2; q++) {
            uint32_t a[2][4], b[8][2];
            #pragma unroll
            for (int mt = 0; mt < 2; mt++) {
                int r = w * 32 + mt * 16 + g;
                a[mt][0] = cA[(r    ) * A_WLDS + 8*q + tg    ];
                a[mt][1] = cA[(r + 8) * A_WLDS + 8*q + tg    ];
                a[mt][2] = cA[(r    ) * A_WLDS + 8*q + tg + 4];
                a[mt][3] = cA[(r + 8) * A_WLDS + 8*q + tg + 4];
            }
            #pragma unroll
            for (int nt = 0; nt < 8; nt++) {
                b[nt][0] = cB[(8*q + tg    ) * B_WLDS + nt * 8 + g];
                b[nt][1] = cB[(8*q + tg + 4) * B_WLDS + nt * 8 + g];
            }
            #pragma unroll
            for (int mt = 0; mt < 2; mt++)
                #pragma unroll
                for (int nt = 0; nt < 8; nt++)
                    asm volatile(
                        "mma.sync.aligned.m16n8k16.row.col.f32.bf16.bf16.f32 "
                        "{%0,%1,%2,%3},{%4,%5,%6,%7},{%8,%9},{%0,%1,%2,%3};"
                        : "+f"(acc[mt][nt][0]), "+f"(acc[mt][nt][1]),
                          "+f"(acc[mt][nt][2]), "+f"(acc[mt][nt][3])
                        : "r"(a[mt][0]), "r"(a[mt][1]), "r"(a[mt][2]), "r"(a[mt][3]),
                          "r"(b[nt][0]), "r"(b[nt][1]));
        }
        __syncthreads();
        if (i + STAGES < NIT) load_stage(i % STAGES, i + STAGES);
        CP_COMMIT();
    }

    #pragma unroll
    for (int mt = 0; mt < 2; mt++) {
        #pragma unroll
        for (int nt = 0; nt < 8; nt++) {
            #pragma unroll
            for (int h = 0; h < 2; h++) {
                int m = m0 + w * 32 + mt * 16 + g + h * 8;
                int n0 = nt * 8 + 2 * tg;
                float lo = acc[mt][nt][h*2+0], hi = acc[mt][nt][h*2+1];
                float2 bb = *(const float2*)&bias[n0];
                lo += bb.x; hi += bb.y;
                if (HAS_ADD) {
                    float2 v = *(const float2*)&addv[(size_t)m*64 + n0];
                    lo += v.x; hi += v.y;
                }
                if (HAS_RES) {
                    float2 v = *(const float2*)&resv[(size_t)m*64 + n0];
                    lo += v.x; hi += v.y;
                }
                if (RELU) { lo = fmaxf(lo, 0.f); hi = fmaxf(hi, 0.f); }
                *(float2*)&out[(size_t)m*64 + n0] = make_float2(lo, hi);
            }
        }
    }
}

// ---------------- dense shortcut ----------------
__global__ void dense_kernel(const float* __restrict__ X, const float* __restrict__ W,
                             const float* __restrict__ b, float* __restrict__ Y,
                             int CIN, int COUT, int ldY, int col0)
{
    int idx = blockIdx.x * blockDim.x + threadIdx.x;
    if (idx >= NF * COUT) return;
    int n = idx / COUT, o = idx - n*COUT;
    float acc = b[o];
    const float* x = X + (size_t)n * CIN;
    for (int c = 0; c < CIN; c++) acc += x[c] * W[c*COUT + o];
    Y[(size_t)n*ldY + col0 + o] = acc;
}

// ---------------- final layer (fp32) ----------------
__global__ void final_kernel(const float* __restrict__ A, const float* __restrict__ W,
                             const float* __restrict__ b, const float* __restrict__ dense,
                             float* __restrict__ out)
{
    int n = blockIdx.x, t = threadIdx.x;  // 128 threads
    const float* Ar = A + (size_t)n * 4096;
    float a0 = 0.f, a1 = 0.f, a2 = 0.f;
    for (int i = t; i < 4096; i += 128) {
        float av = Ar[i];
        a0 += av * W[i*3 + 0];
        a1 += av * W[i*3 + 1];
        a2 += av * W[i*3 + 2];
    }
    __shared__ float red[3][128];
    red[0][t] = a0; red[1][t] = a1; red[2][t] = a2;
    __syncthreads();
    for (int s = 64; s > 0; s >>= 1) {
        if (t < s) {
            red[0][t] += red[0][t+s];
            red[1][t] += red[1][t+s];
            red[2][t] += red[2][t+s];
        }
        __syncthreads();
    }
    if (t < 3) out[n*3 + t] = red[t][0] + b[t] + dense[n*3 + t];
}

// ---------------- launch ----------------
extern "C" void kernel_launch(void* const* d_in, const int* in_sizes, int n_in,
                              void* d_out, int out_size)
{
    const float* fluid_pos = (const float*)d_in[0];
    const float* wall_pos  = (const float*)d_in[1];
    const float* fluid_vel = (const float*)d_in[2];
    const float* wall_nv   = (const float*)d_in[3];
    const int*   nbr_wf    = (const int*)d_in[4];
    const void*  mask_wf   = d_in[5];
    const int*   nbr_ff    = (const int*)d_in[6];
    const void*  mask_ff   = d_in[7];
    const float* W_wall1 = (const float*)d_in[8];
    const float* b_wall1 = (const float*)d_in[9];
    const float* W_fluid1 = (const float*)d_in[10];
    const float* b_fluid1 = (const float*)d_in[11];
    const float* W_d1 = (const float*)d_in[12];
    const float* b_d1 = (const float*)d_in[13];
    const float* W_c2 = (const float*)d_in[14];
    const float* b_c2 = (const float*)d_in[15];
    const float* W_d2 = (const float*)d_in[16];
    const float* b_d2 = (const float*)d_in[17];
    const float* W_c3 = (const float*)d_in[18];
    const float* b_c3 = (const float*)d_in[19];
    const float* W_d3 = (const float*)d_in[20];
    const float* b_d3 = (const float*)d_in[21];
    const float* W_c4 = (const float*)d_in[22];
    const float* b_c4 = (const float*)d_in[23];
    const float* W_d4 = (const float*)d_in[24];
    const float* b_d4 = (const float*)d_in[25];

    void *pA, *pgFff, *pgIff, *pgFwf, *pgIwf, *pout1, *pout2, *pout3, *pdense, *pWb2, *pWb3;
    cudaGetSymbolAddress(&pA, g_A);
    cudaGetSymbolAddress(&pgFff, g_gF_ff);
    cudaGetSymbolAddress(&pgIff, g_gI_ff);
    cudaGetSymbolAddress(&pgFwf, g_gF_wf);
    cudaGetSymbolAddress(&pgIwf, g_gI_wf);
    cudaGetSymbolAddress(&pout1, g_out1);
    cudaGetSymbolAddress(&pout2, g_out2);
    cudaGetSymbolAddress(&pout3, g_out3);
    cudaGetSymbolAddress(&pdense, g_dense);
    cudaGetSymbolAddress(&pWb2, g_Wb2);
    cudaGetSymbolAddress(&pWb3, g_Wb3);
    void*   A     = pA;
    float4* gFff  = (float4*)pgFff;
    int*    gIff  = (int*)pgIff;
    float4* gFwf  = (float4*)pgFwf;
    int*    gIwf  = (int*)pgIwf;
    float*  out1  = (float*)pout1;
    float*  out2  = (float*)pout2;
    float*  out3  = (float*)pout3;
    float*  dense = (float*)pdense;
    uint32_t* Wb2 = (uint32_t*)pWb2;
    uint32_t* Wb3 = (uint32_t*)pWb3;

    cudaFuncSetAttribute(gemm_mma<1,0,1>, cudaFuncAttributeMaxDynamicSharedMemorySize, GEMM_SMEM);
    cudaFuncSetAttribute(gemm_mma<1,1,1>, cudaFuncAttributeMaxDynamicSharedMemorySize, GEMM_SMEM);

    const int tot = NF * KNBR;
    detect_mask_kernel<<<1, 1024>>>((const unsigned int*)mask_wf);
    geom_kernel<<<(tot + 255)/256, 256>>>(wall_pos,  fluid_pos, nbr_wf, mask_wf, gFwf, gIwf);
    geom_kernel<<<(tot + 255)/256, 256>>>(fluid_pos, fluid_pos, nbr_ff, mask_ff, gFff, gIff);
    pack_w_kernel<<<(3072*64 + 255)/256, 256>>>(W_c2, Wb2, 3072);
    pack_w_kernel<<<(2048*64 + 255)/256, 256>>>(W_c3, Wb3, 2048);

    // layer 1
    conv1_kernel<<<NF/4, 256>>>(wall_nv,   nbr_wf, gFwf, gIwf, W_wall1,  b_wall1,  out1, 0);
    conv1_kernel<<<NF/4, 256>>>(fluid_vel, nbr_ff, gFff, gIff, W_fluid1, b_fluid1, out1, 32);
    dense_kernel<<<(NF*32 + 255)/256, 256>>>(fluid_vel, W_d1, b_d1, out1, 3, 32, 96, 64);

    // layer 2
    dense_kernel<<<(NF*64 + 255)/256, 256>>>(out1, W_d2, b_d2, dense, 96, 64, 64, 0);
    cellgemm_kernel<96><<<NF, 128>>>(out1, nbr_ff, gFff, gIff, (uint32_t*)A);
    gemm_mma<1, 0, 1><<<NF/128, 128, GEMM_SMEM>>>((const __nv_bfloat16*)A, Wb2, b_c2, dense, nullptr, out2, 6144);

    // layer 3
    dense_kernel<<<(NF*64 + 255)/256, 256>>>(out2, W_d3, b_d3, dense, 64, 64, 64, 0);
    cellgemm_kernel<64><<<NF, 128>>>(out2, nbr_ff, gFff, gIff, (uint32_t*)A);
    gemm_mma<1, 1, 1><<<NF/128, 128, GEMM_SMEM>>>((const __nv_bfloat16*)A, Wb3, b_c3, dense, out2, out3, 4096);

    // layer 4 (fp32 A for the fp32 final reduction)
    dense_kernel<<<(NF*3 + 255)/256, 256>>>(out3, W_d4, b_d4, dense, 64, 3, 3, 0);
    scatter_kernel<64, 2><<<NF, 128>>>(out3, nbr_ff, gFff, gIff, (float*)A);
    final_kernel<<<NF, 128>>>((const float*)A, W_c4, b_c4, dense, (float*)d_out);
}

// round 8
// speedup vs baseline: 2.6846x; 1.3347x over previous
#include <cuda_runtime.h>
#include <cuda_bf16.h>
#include <cstdint>
#include <cstddef>

#define NF   16000
#define KNBR 64
#define RADIUS_F ((float)(0.5*6.0*1.5*0.025))

// ---------------- scratch (device globals; no allocation APIs) ----------------
__device__ float  g_A[(size_t)NF * 64 * 96];   // bf16 A for layers 2/3; fp32 P for layer 4
__device__ float4 g_gF_ff[NF * KNBR];
__device__ int    g_gI_ff[NF * KNBR];
__device__ float4 g_gF_wf[NF * KNBR];
__device__ int    g_gI_wf[NF * KNBR];
__device__ float  g_out1[NF * 96];
__device__ float  g_out2[NF * 64];
__device__ float  g_out3[NF * 64];
__device__ float  g_dense[NF * 64];
__device__ uint32_t g_Wb2[3072 * 64];          // W_c2 packed bf16x2, [kp][n]
__device__ uint32_t g_Wb3[2048 * 64];          // W_c3 packed bf16x2
__device__ float  g_Wp4[64 * 256];             // W_c4 re-laid [c][cell*4+o], pad o=3 -> 0
__device__ int    g_mask_u8;

// ---------------- helpers ----------------
__device__ __forceinline__ uint32_t smem_u32(const void* p) {
    uint32_t a;
    asm("{ .reg .u64 t; cvta.to.shared.u64 t, %1; cvt.u32.u64 %0, t; }" : "=r"(a) : "l"(p));
    return a;
}
__device__ __forceinline__ void cp16(uint32_t dst, const void* src) {
    asm volatile("cp.async.cg.shared.global [%0], [%1], 16;" :: "r"(dst), "l"(src));
}
#define CP_COMMIT() asm volatile("cp.async.commit_group;" ::: "memory")
__device__ __forceinline__ uint32_t bf16x2(float hi, float lo) {
    uint32_t r;
    asm("cvt.rn.bf16x2.f32 %0, %1, %2;" : "=r"(r) : "f"(hi), "f"(lo));
    return r;
}

// ---------------- mask dtype detector ----------------
__global__ void detect_mask_kernel(const unsigned int* __restrict__ m)
{
    __shared__ int s;
    if (threadIdx.x == 0) s = 0;
    __syncthreads();
    int bad = 0;
    for (int i = threadIdx.x; i < 65536; i += blockDim.x)
        if (m[i] > 1u) { bad = 1; break; }
    if (bad) atomicOr(&s, 1);
    __syncthreads();
    if (threadIdx.x == 0) g_mask_u8 = s;
}

// ---------------- geometry ----------------
static __device__ __forceinline__ float sgnf(float v) {
    return (v > 0.f) ? 1.f : ((v < 0.f) ? -1.f : 0.f);
}
__device__ __forceinline__ void gridmap(float u, int& i0, float& f) {
    float cc = (u * 0.5f + 0.5f) * 3.f;
    cc = fminf(fmaxf(cc, 0.f), 3.f);
    float fi = floorf(cc);
    fi = fminf(fi, 2.f);
    f = cc - fi;
    i0 = (int)fi;
}

__global__ void geom_kernel(const float* __restrict__ pin, const float* __restrict__ pout,
                            const int* __restrict__ nbr, const void* __restrict__ mask,
                            float4* __restrict__ gF, int* __restrict__ gI)
{
    int idx = blockIdx.x * blockDim.x + threadIdx.x;
    if (idx >= NF * KNBR) return;
    int mv = g_mask_u8 ? (int)((const unsigned char*)mask)[idx]
                       : ((const int*)mask)[idx];
    if (mv == 0) { gF[idx] = make_float4(0.f, 0.f, 0.f, 0.f); gI[idx] = 0; return; }
    int n = idx >> 6;
    int j = nbr[idx];
    float x = (pin[j*3+0] - pout[n*3+0]) / RADIUS_F;
    float y = (pin[j*3+1] - pout[n*3+1]) / RADIUS_F;
    float z = (pin[j*3+2] - pout[n*3+2]) / RADIUS_F;
    float sq = x*x + y*y + z*z;
    float t1 = 1.f - sq;
    float win = fminf(fmaxf(t1*t1*t1, 0.f), 1.f);

    const float eps = 1e-12f;
    float norm = sqrtf(fmaxf(sq, eps));
    float rho  = sqrtf(fmaxf(x*x + y*y, eps));
    bool  top  = (1.25f*z*z > x*x + y*y);
    float s_top = sqrtf(3.f*norm / (norm + fabsf(z)));
    float xs = top ? x*s_top : (x*norm)/rho;
    float ys = top ? y*s_top : (y*norm)/rho;
    float zs = top ? sgnf(z)*norm : 1.5f*z;
    if (sq < eps) { xs = 0.f; ys = 0.f; zs = 0.f; }
    float rxy = sqrtf(fmaxf(xs*xs + ys*ys, eps));
    bool use_x = fabsf(ys) <= fabsf(xs);
    float ddx = (use_x  && fabsf(xs) > eps) ? xs : 1.f;
    float ddy = (!use_x && fabsf(ys) > eps) ? ys : 1.f;
    const float c4 = 1.27323954473516276487f;  // 4/pi
    float xc = use_x ? sgnf(xs)*rxy : sgnf(ys)*rxy*c4*atanf(xs/ddy);
    float yc = use_x ? sgnf(xs)*rxy*c4*atanf(ys/ddx) : sgnf(ys)*rxy;
    if (xs*xs + ys*ys < eps) { xc = 0.f; yc = 0.f; }

    int ix, iy, iz; float fx, fy, fz;
    gridmap(xc, ix, fx); gridmap(yc, iy, fy); gridmap(zs, iz, fz);
    gF[idx] = make_float4(fx, fy, fz, win);
    gI[idx] = (ix*4 + iy)*4 + iz;
}

// ---------------- layer-1 cconv (cin=3, cout=32) ----------------
__global__ __launch_bounds__(256) void conv1_kernel(
    const float* __restrict__ feat, const int* __restrict__ nbr,
    const float4* __restrict__ gF, const int* __restrict__ gI,
    const float* __restrict__ W, const float* __restrict__ b,
    float* __restrict__ out1, int col0)
{
    __shared__ float A[4][192];
    __shared__ float red[256];
    int t = threadIdx.x;
    int p = t >> 6, tl = t & 63;
    int n = blockIdx.x * 4 + p;
    float* Ap = A[p];
    Ap[tl] = 0.f; Ap[tl + 64] = 0.f; Ap[tl + 128] = 0.f;
    __syncthreads();

    int idx = n * KNBR + tl;
    float4 g = gF[idx];
    if (g.w != 0.f) {
        int j = nbr[idx];
        float f0 = feat[j*3+0]*g.w, f1 = feat[j*3+1]*g.w, f2 = feat[j*3+2]*g.w;
        int base = gI[idx];
        float wx[2] = {1.f - g.x, g.x};
        float wy[2] = {1.f - g.y, g.y};
        float wz[2] = {1.f - g.z, g.z};
        #pragma unroll
        for (int cx = 0; cx < 2; cx++)
        #pragma unroll
        for (int cy = 0; cy < 2; cy++)
        #pragma unroll
        for (int cz = 0; cz < 2; cz++) {
            float wc = wx[cx]*wy[cy]*wz[cz];
            int cell = base + cx*16 + cy*4 + cz;
            atomicAdd(&Ap[cell*3+0], wc*f0);
            atomicAdd(&Ap[cell*3+1], wc*f1);
            atomicAdd(&Ap[cell*3+2], wc*f2);
        }
    }
    __syncthreads();

    int o = tl & 31, h = tl >> 5;
    float acc = 0.f;
    for (int i = h*96; i < h*96 + 96; i++)
        acc += Ap[i] * W[i*32 + o];
    red[t] = acc;
    __syncthreads();
    if (tl < 32) {
        float v = red[p*64 + tl] + red[p*64 + tl + 32] + b[o];
        out1[n*96 + col0 + tl] = fmaxf(v, 0.f);
    }
}

// ---------------- cellgemm: A[n] = S[n] @ F[n] on tensor cores (layers 2/3) ----------------
#define S_WLDS 36
template<int CIN>
__global__ __launch_bounds__(128) void cellgemm_kernel(
    const float* __restrict__ feat, const int* __restrict__ nbr,
    const float4* __restrict__ gF, const int* __restrict__ gI,
    uint32_t* __restrict__ Aout)
{
    constexpr int F_WLDS = CIN + 8;
    constexpr int NT = CIN / 8;
    __shared__ uint32_t sS[64 * S_WLDS];
    __shared__ uint32_t sF[32 * F_WLDS];
    __shared__ float4 sG[KNBR];
    __shared__ int    sJ[KNBR];
    __shared__ int    sB[KNBR];
    int n = blockIdx.x, t = threadIdx.x;
    int w = t >> 5, lane = t & 31;
    int g = lane >> 2, tg = lane & 3;

    if (t < KNBR) { sG[t] = gF[n*KNBR + t]; sB[t] = gI[n*KNBR + t]; sJ[t] = nbr[n*KNBR + t]; }
    for (int i = t; i < 64 * S_WLDS; i += 128) sS[i] = 0;
    __syncthreads();

    if (t < KNBR) {
        float4 gv = sG[t];
        if (gv.w != 0.f) {
            __nv_bfloat16* Sh = (__nv_bfloat16*)sS;
            int base = sB[t];
            float wx0 = (1.f - gv.x) * gv.w, wx1 = gv.x * gv.w;
            float wy0 = 1.f - gv.y, wy1 = gv.y;
            float wz0 = 1.f - gv.z, wz1 = gv.z;
            Sh[(base     ) * (2*S_WLDS) + t] = __float2bfloat16(wx0*wy0*wz0);
            Sh[(base +  1) * (2*S_WLDS) + t] = __float2bfloat16(wx0*wy0*wz1);
            Sh[(base +  4) * (2*S_WLDS) + t] = __float2bfloat16(wx0*wy1*wz0);
            Sh[(base +  5) * (2*S_WLDS) + t] = __float2bfloat16(wx0*wy1*wz1);
            Sh[(base + 16) * (2*S_WLDS) + t] = __float2bfloat16(wx1*wy0*wz0);
            Sh[(base + 17) * (2*S_WLDS) + t] = __float2bfloat16(wx1*wy0*wz1);
            Sh[(base + 20) * (2*S_WLDS) + t] = __float2bfloat16(wx1*wy1*wz0);
            Sh[(base + 21) * (2*S_WLDS) + t] = __float2bfloat16(wx1*wy1*wz1);
        }
    }

    for (int i = t; i < 32 * CIN; i += 128) {
        int kp = i / CIN, c = i - kp * CIN;
        float f0 = feat[(size_t)sJ[2*kp    ] * CIN + c];
        float f1 = feat[(size_t)sJ[2*kp + 1] * CIN + c];
        sF[kp * F_WLDS + c] = bf16x2(f1, f0);
    }
    __syncthreads();

    float acc[NT][4];
    #pragma unroll
    for (int nt = 0; nt < NT; nt++)
        #pragma unroll
        for (int q = 0; q < 4; q++) acc[nt][q] = 0.f;

    #pragma unroll
    for (int q = 0; q < 4; q++) {
        int r = w * 16 + g;
        uint32_t a0 = sS[(r    ) * S_WLDS + 8*q + tg    ];
        uint32_t a1 = sS[(r + 8) * S_WLDS + 8*q + tg    ];
        uint32_t a2 = sS[(r    ) * S_WLDS + 8*q + tg + 4];
        uint32_t a3 = sS[(r + 8) * S_WLDS + 8*q + tg + 4];
        #pragma unroll
        for (int nt = 0; nt < NT; nt++) {
            uint32_t b0 = sF[(8*q + tg    ) * F_WLDS + nt * 8 + g];
            uint32_t b1 = sF[(8*q + tg + 4) * F_WLDS + nt * 8 + g];
            asm volatile(
                "mma.sync.aligned.m16n8k16.row.col.f32.bf16.bf16.f32 "
                "{%0,%1,%2,%3},{%4,%5,%6,%7},{%8,%9},{%0,%1,%2,%3};"
                : "+f"(acc[nt][0]), "+f"(acc[nt][1]), "+f"(acc[nt][2]), "+f"(acc[nt][3])
                : "r"(a0), "r"(a1), "r"(a2), "r"(a3), "r"(b0), "r"(b1));
        }
    }

    uint32_t* out = Aout + (size_t)n * (32 * CIN);
    #pragma unroll
    for (int nt = 0; nt < NT; nt++) {
        #pragma unroll
        for (int h = 0; h < 2; h++) {
            int cell = w * 16 + g + h * 8;
            out[cell * (CIN/2) + nt * 4 + tg] = bf16x2(acc[nt][h*2+1], acc[nt][h*2+0]);
        }
    }
}

// ---------------- W pack: Wb[kp*64+n] = bf16x2(W[(2kp+1)*64+n], W[2kp*64+n]) ----------------
__global__ void pack_w_kernel(const float* __restrict__ W, uint32_t* __restrict__ Wb, int KP)
{
    int idx = blockIdx.x * blockDim.x + threadIdx.x;
    if (idx >= KP * 64) return;
    int kp = idx >> 6, n = idx & 63;
    Wb[idx] = bf16x2(W[(size_t)(2*kp+1)*64 + n], W[(size_t)(2*kp)*64 + n]);
}

// ---------------- W_c4 re-layout: Wp[c*256 + cell*4 + o] ----------------
__global__ void pack_w4_kernel(const float* __restrict__ W, float* __restrict__ Wp)
{
    int idx = blockIdx.x * blockDim.x + threadIdx.x;
    if (idx >= 64 * 256) return;
    int c = idx >> 8, col = idx & 255;
    int cell = col >> 2, o = col & 3;
    Wp[idx] = (o < 3) ? W[((size_t)cell * 64 + c) * 3 + o] : 0.f;
}

// ---------------- pconv4: P[n, cell*4+o] = out3[n,:] @ Wp[:, cell*4+o] (fp32) ----------------
__global__ __launch_bounds__(256) void pconv4_kernel(
    const float* __restrict__ X, const float* __restrict__ Wp, float* __restrict__ P)
{
    __shared__ float4 Xs[32][16];                 // 32 particles x 64 floats
    int t = threadIdx.x;
    int n0 = blockIdx.x * 32;
    for (int i = t; i < 512; i += 256) {
        int r = i >> 4, c4 = i & 15;
        Xs[r][c4] = *(const float4*)(X + (size_t)(n0 + r) * 64 + c4 * 4);
    }
    __syncthreads();

    float acc[32];
    #pragma unroll
    for (int r = 0; r < 32; r++) acc[r] = 0.f;
    #pragma unroll
    for (int c4 = 0; c4 < 16; c4++) {
        float w0 = Wp[(c4*4 + 0) * 256 + t];
        float w1 = Wp[(c4*4 + 1) * 256 + t];
        float w2 = Wp[(c4*4 + 2) * 256 + t];
        float w3 = Wp[(c4*4 + 3) * 256 + t];
        #pragma unroll
        for (int r = 0; r < 32; r++) {
            float4 xv = Xs[r][c4];
            acc[r] += xv.x*w0 + xv.y*w1 + xv.z*w2 + xv.w*w3;
        }
    }
    #pragma unroll
    for (int r = 0; r < 32; r++)
        P[(size_t)(n0 + r) * 256 + t] = acc[r];
}

// ---------------- conv4 gather: out[n,:] = sum_k win * sum_corner w * P[j_k, cell, :] ----------
__global__ __launch_bounds__(64) void conv4_kernel(
    const float* __restrict__ P, const int* __restrict__ nbr,
    const float4* __restrict__ gF, const int* __restrict__ gI,
    const float* __restrict__ b, const float* __restrict__ dense,
    float* __restrict__ out)
{
    __shared__ float red[2][3];
    int n = blockIdx.x, t = threadIdx.x;          // 64 threads = 64 neighbors
    float a0 = 0.f, a1 = 0.f, a2 = 0.f;
    float4 g = gF[n*KNBR + t];
    if (g.w != 0.f) {
        int j = nbr[n*KNBR + t];
        const float4* Pj = (const float4*)(P + (size_t)j * 256);
        int base = gI[n*KNBR + t];
        float wx0 = (1.f - g.x) * g.w, wx1 = g.x * g.w;
        float wy0 = 1.f - g.y, wy1 = g.y;
        float wz0 = 1.f - g.z, wz1 = g.z;
        float wq[8] = {wx0*wy0*wz0, wx0*wy0*wz1, wx0*wy1*wz0, wx0*wy1*wz1,
                       wx1*wy0*wz0, wx1*wy0*wz1, wx1*wy1*wz0, wx1*wy1*wz1};
        const int off[8] = {0, 1, 4, 5, 16, 17, 20, 21};
        #pragma unroll
        for (int q = 0; q < 8; q++) {
            float4 p = Pj[base + off[q]];
            a0 += wq[q] * p.x; a1 += wq[q] * p.y; a2 += wq[q] * p.z;
        }
    }
    #pragma unroll
    for (int s = 16; s > 0; s >>= 1) {
        a0 += __shfl_down_sync(0xffffffff, a0, s);
        a1 += __shfl_down_sync(0xffffffff, a1, s);
        a2 += __shfl_down_sync(0xffffffff, a2, s);
    }
    if ((t & 31) == 0) { red[t>>5][0] = a0; red[t>>5][1] = a1; red[t>>5][2] = a2; }
    __syncthreads();
    if (t < 3) out[n*3 + t] = red[0][t] + red[1][t] + b[t] + dense[n*3 + t];
}

// ---------------- bf16 tensor GEMM: out[M,64] = A[M,K] @ W[K,64], mma m16n8k16 ----------------
#define STAGES 4
#define A_WLDS 20
#define B_WLDS 72
#define A_WSTAGE (128*A_WLDS)
#define B_WSTAGE (16*B_WLDS)
#define GEMM_SMEM (STAGES*(A_WSTAGE + B_WSTAGE)*4)

template<int HAS_ADD, int HAS_RES, int RELU>
__global__ __launch_bounds__(128) void gemm_mma(
    const __nv_bfloat16* __restrict__ Ag, const uint32_t* __restrict__ Wb,
    const float* __restrict__ bias, const float* __restrict__ addv,
    const float* __restrict__ resv, float* __restrict__ out, int K)
{
    extern __shared__ uint32_t sm[];
    uint32_t* sA = sm;
    uint32_t* sB = sm + STAGES * A_WSTAGE;
    int tid = threadIdx.x, w = tid >> 5, lane = tid & 31;
    int g = lane >> 2, tg = lane & 3;
    int m0 = blockIdx.x * 128;
    int NIT = K >> 5;
    uint32_t sAu = smem_u32(sA), sBu = smem_u32(sB);

    auto load_stage = [&](int s, int c) {
        uint32_t ab = sAu + (uint32_t)s * A_WSTAGE * 4;
        const __nv_bfloat16* as = Ag + (size_t)m0 * K + c * 32;
        #pragma unroll
        for (int r = 0; r < 4; r++) {
            int idx = r * 128 + tid;
            int row = idx >> 2, seg = idx & 3;
            cp16(ab + (row * A_WLDS + seg * 4) * 4, as + (size_t)row * K + seg * 8);
        }
        uint32_t bb = sBu + (uint32_t)s * B_WSTAGE * 4;
        const uint32_t* bs = Wb + (size_t)c * 16 * 64;
        #pragma unroll
        for (int r = 0; r < 2; r++) {
            int idx = r * 128 + tid;
            int kp = idx >> 4, seg = idx & 15;
            cp16(bb + (kp * B_WLDS + seg * 4) * 4, bs + kp * 64 + seg * 4);
        }
    };

    float acc[2][8][4];
    #pragma unroll
    for (int mt = 0; mt < 2; mt++)
        #pragma unroll
        for (int nt = 0; nt < 8; nt++)
            #pragma unroll
            for (int q = 0; q < 4; q++) acc[mt][nt][q] = 0.f;

    #pragma unroll
    for (int s = 0; s < STAGES; s++) { load_stage(s, s); CP_COMMIT(); }

    for (int i = 0; i < NIT; i++) {
        asm volatile("cp.async.wait_group %0;" :: "n"(STAGES - 1));
        __syncthreads();
        const uint32_t* cA = sA + (i % STAGES) * A_WSTAGE;
        const uint32_t* cB = sB + (i % STAGES) * B_WSTAGE;
        #pragma unroll
        for (int q = 0; q < 2; q++) {
            uint32_t a[2][4], b[8][2];
            #pragma unroll
            for (int mt = 0; mt < 2; mt++) {
                int r = w * 32 + mt * 16 + g;
                a[mt][0] = cA[(r    ) * A_WLDS + 8*q + tg    ];
                a[mt][1] = cA[(r + 8) * A_WLDS + 8*q + tg    ];
                a[mt][2] = cA[(r    ) * A_WLDS + 8*q + tg + 4];
                a[mt][3] = cA[(r + 8) * A_WLDS + 8*q + tg + 4];
            }
            #pragma unroll
            for (int nt = 0; nt < 8; nt++) {
                b[nt][0] = cB[(8*q + tg    ) * B_WLDS + nt * 8 + g];
                b[nt][1] = cB[(8*q + tg + 4) * B_WLDS + nt * 8 + g];
            }
            #pragma unroll
            for (int mt = 0; mt < 2; mt++)
                #pragma unroll
                for (int nt = 0; nt < 8; nt++)
                    asm volatile(
                        "mma.sync.aligned.m16n8k16.row.col.f32.bf16.bf16.f32 "
                        "{%0,%1,%2,%3},{%4,%5,%6,%7},{%8,%9},{%0,%1,%2,%3};"
                        : "+f"(acc[mt][nt][0]), "+f"(acc[mt][nt][1]),
                          "+f"(acc[mt][nt][2]), "+f"(acc[mt][nt][3])
                        : "r"(a[mt][0]), "r"(a[mt][1]), "r"(a[mt][2]), "r"(a[mt][3]),
                          "r"(b[nt][0]), "r"(b[nt][1]));
        }
        __syncthreads();
        if (i + STAGES < NIT) load_stage(i % STAGES, i + STAGES);
        CP_COMMIT();
    }

    #pragma unroll
    for (int mt = 0; mt < 2; mt++) {
        #pragma unroll
        for (int nt = 0; nt < 8; nt++) {
            #pragma unroll
            for (int h = 0; h < 2; h++) {
                int m = m0 + w * 32 + mt * 16 + g + h * 8;
                int n0 = nt * 8 + 2 * tg;
                float lo = acc[mt][nt][h*2+0], hi = acc[mt][nt][h*2+1];
                float2 bb = *(const float2*)&bias[n0];
                lo += bb.x; hi += bb.y;
                if (HAS_ADD) {
                    float2 v = *(const float2*)&addv[(size_t)m*64 + n0];
                    lo += v.x; hi += v.y;
                }
                if (HAS_RES) {
                    float2 v = *(const float2*)&resv[(size_t)m*64 + n0];
                    lo += v.x; hi += v.y;
                }
                if (RELU) { lo = fmaxf(lo, 0.f); hi = fmaxf(hi, 0.f); }
                *(float2*)&out[(size_t)m*64 + n0] = make_float2(lo, hi);
            }
        }
    }
}

// ---------------- dense shortcut ----------------
__global__ void dense_kernel(const float* __restrict__ X, const float* __restrict__ W,
                             const float* __restrict__ b, float* __restrict__ Y,
                             int CIN, int COUT, int ldY, int col0)
{
    int idx = blockIdx.x * blockDim.x + threadIdx.x;
    if (idx >= NF * COUT) return;
    int n = idx / COUT, o = idx - n*COUT;
    float acc = b[o];
    const float* x = X + (size_t)n * CIN;
    for (int c = 0; c < CIN; c++) acc += x[c] * W[c*COUT + o];
    Y[(size_t)n*ldY + col0 + o] = acc;
}

// ---------------- launch ----------------
extern "C" void kernel_launch(void* const* d_in, const int* in_sizes, int n_in,
                              void* d_out, int out_size)
{
    const float* fluid_pos = (const float*)d_in[0];
    const float* wall_pos  = (const float*)d_in[1];
    const float* fluid_vel = (const float*)d_in[2];
    const float* wall_nv   = (const float*)d_in[3];
    const int*   nbr_wf    = (const int*)d_in[4];
    const void*  mask_wf   = d_in[5];
    const int*   nbr_ff    = (const int*)d_in[6];
    const void*  mask_ff   = d_in[7];
    const float* W_wall1 = (const float*)d_in[8];
    const float* b_wall1 = (const float*)d_in[9];
    const float* W_fluid1 = (const float*)d_in[10];
    const float* b_fluid1 = (const float*)d_in[11];
    const float* W_d1 = (const float*)d_in[12];
    const float* b_d1 = (const float*)d_in[13];
    const float* W_c2 = (const float*)d_in[14];
    const float* b_c2 = (const float*)d_in[15];
    const float* W_d2 = (const float*)d_in[16];
    const float* b_d2 = (const float*)d_in[17];
    const float* W_c3 = (const float*)d_in[18];
    const float* b_c3 = (const float*)d_in[19];
    const float* W_d3 = (const float*)d_in[20];
    const float* b_d3 = (const float*)d_in[21];
    const float* W_c4 = (const float*)d_in[22];
    const float* b_c4 = (const float*)d_in[23];
    const float* W_d4 = (const float*)d_in[24];
    const float* b_d4 = (const float*)d_in[25];

    void *pA, *pgFff, *pgIff, *pgFwf, *pgIwf, *pout1, *pout2, *pout3, *pdense, *pWb2, *pWb3, *pWp4;
    cudaGetSymbolAddress(&pA, g_A);
    cudaGetSymbolAddress(&pgFff, g_gF_ff);
    cudaGetSymbolAddress(&pgIff, g_gI_ff);
    cudaGetSymbolAddress(&pgFwf, g_gF_wf);
    cudaGetSymbolAddress(&pgIwf, g_gI_wf);
    cudaGetSymbolAddress(&pout1, g_out1);
    cudaGetSymbolAddress(&pout2, g_out2);
    cudaGetSymbolAddress(&pout3, g_out3);
    cudaGetSymbolAddress(&pdense, g_dense);
    cudaGetSymbolAddress(&pWb2, g_Wb2);
    cudaGetSymbolAddress(&pWb3, g_Wb3);
    cudaGetSymbolAddress(&pWp4, g_Wp4);
    void*   A     = pA;
    float4* gFff  = (float4*)pgFff;
    int*    gIff  = (int*)pgIff;
    float4* gFwf  = (float4*)pgFwf;
    int*    gIwf  = (int*)pgIwf;
    float*  out1  = (float*)pout1;
    float*  out2  = (float*)pout2;
    float*  out3  = (float*)pout3;
    float*  dense = (float*)pdense;
    uint32_t* Wb2 = (uint32_t*)pWb2;
    uint32_t* Wb3 = (uint32_t*)pWb3;
    float*  Wp4   = (float*)pWp4;

    cudaFuncSetAttribute(gemm_mma<1,0,1>, cudaFuncAttributeMaxDynamicSharedMemorySize, GEMM_SMEM);
    cudaFuncSetAttribute(gemm_mma<1,1,1>, cudaFuncAttributeMaxDynamicSharedMemorySize, GEMM_SMEM);

    const int tot = NF * KNBR;
    detect_mask_kernel<<<1, 1024>>>((const unsigned int*)mask_wf);
    geom_kernel<<<(tot + 255)/256, 256>>>(wall_pos,  fluid_pos, nbr_wf, mask_wf, gFwf, gIwf);
    geom_kernel<<<(tot + 255)/256, 256>>>(fluid_pos, fluid_pos, nbr_ff, mask_ff, gFff, gIff);
    pack_w_kernel<<<(3072*64 + 255)/256, 256>>>(W_c2, Wb2, 3072);
    pack_w_kernel<<<(2048*64 + 255)/256, 256>>>(W_c3, Wb3, 2048);
    pack_w4_kernel<<<(64*256 + 255)/256, 256>>>(W_c4, Wp4);

    // layer 1
    conv1_kernel<<<NF/4, 256>>>(wall_nv,   nbr_wf, gFwf, gIwf, W_wall1,  b_wall1,  out1, 0);
    conv1_kernel<<<NF/4, 256>>>(fluid_vel, nbr_ff, gFff, gIff, W_fluid1, b_fluid1, out1, 32);
    dense_kernel<<<(NF*32 + 255)/256, 256>>>(fluid_vel, W_d1, b_d1, out1, 3, 32, 96, 64);

    // layer 2
    dense_kernel<<<(NF*64 + 255)/256, 256>>>(out1, W_d2, b_d2, dense, 96, 64, 64, 0);
    cellgemm_kernel<96><<<NF, 128>>>(out1, nbr_ff, gFff, gIff, (uint32_t*)A);
    gemm_mma<1, 0, 1><<<NF/128, 128, GEMM_SMEM>>>((const __nv_bfloat16*)A, Wb2, b_c2, dense, nullptr, out2, 6144);

    // layer 3
    dense_kernel<<<(NF*64 + 255)/256, 256>>>(out2, W_d3, b_d3, dense, 64, 64, 64, 0);
    cellgemm_kernel<64><<<NF, 128>>>(out2, nbr_ff, gFff, gIff, (uint32_t*)A);
    gemm_mma<1, 1, 1><<<NF/128, 128, GEMM_SMEM>>>((const __nv_bfloat16*)A, Wb3, b_c3, dense, out2, out3, 4096);

    // layer 4: P = out3 @ W_c4 (per input particle), then trilinear gather
    dense_kernel<<<(NF*3 + 255)/256, 256>>>(out3, W_d4, b_d4, dense, 64, 3, 3, 0);
    pconv4_kernel<<<NF/32, 256>>>(out3, Wp4, (float*)A);
    conv4_kernel<<<NF, 64>>>((const float*)A, nbr_ff, gFff, gIff, b_c4, dense, (float*)d_out);
}

// round 10
// speedup vs baseline: 2.7425x; 1.0216x over previous
#include <cuda_runtime.h>
#include <cuda_bf16.h>
#include <cstdint>
#include <cstddef>

#define NF   16000
#define KNBR 64
#define RADIUS_F ((float)(0.5*6.0*1.5*0.025))

// ---------------- scratch (device globals; no allocation APIs) ----------------
__device__ float  g_A[(size_t)NF * 64 * 96];   // bf16 A for layers 2/3; fp32 P for layer 4
__device__ float4 g_gF_ff[NF * KNBR];
__device__ int    g_gI_ff[NF * KNBR];
__device__ float4 g_gF_wf[NF * KNBR];
__device__ int    g_gI_wf[NF * KNBR];
__device__ float  g_out1[NF * 96];
__device__ float  g_out2[NF * 64];
__device__ float  g_out3[NF * 64];
__device__ float  g_dense[NF * 64];
__device__ uint32_t g_Wb2[3072 * 64];          // W_c2 packed bf16x2, [kp][n]
__device__ uint32_t g_Wb3[2048 * 64];          // W_c3 packed bf16x2
__device__ float  g_Wp4[64 * 256];             // W_c4 re-laid [c][cell*4+o], pad o=3 -> 0
__device__ int    g_mask_u8;

// ---------------- helpers ----------------
__device__ __forceinline__ uint32_t smem_u32(const void* p) {
    uint32_t a;
    asm("{ .reg .u64 t; cvta.to.shared.u64 t, %1; cvt.u32.u64 %0, t; }" : "=r"(a) : "l"(p));
    return a;
}
__device__ __forceinline__ void cp16(uint32_t dst, const void* src) {
    asm volatile("cp.async.cg.shared.global [%0], [%1], 16;" :: "r"(dst), "l"(src));
}
#define CP_COMMIT() asm volatile("cp.async.commit_group;" ::: "memory")
__device__ __forceinline__ uint32_t bf16x2(float hi, float lo) {
    uint32_t r;
    asm("cvt.rn.bf16x2.f32 %0, %1, %2;" : "=r"(r) : "f"(hi), "f"(lo));
    return r;
}

// ---------------- mask dtype detector ----------------
__global__ void detect_mask_kernel(const unsigned int* __restrict__ m)
{
    __shared__ int s;
    if (threadIdx.x == 0) s = 0;
    __syncthreads();
    int bad = 0;
    for (int i = threadIdx.x; i < 65536; i += blockDim.x)
        if (m[i] > 1u) { bad = 1; break; }
    if (bad) atomicOr(&s, 1);
    __syncthreads();
    if (threadIdx.x == 0) g_mask_u8 = s;
}

// ---------------- geometry ----------------
static __device__ __forceinline__ float sgnf(float v) {
    return (v > 0.f) ? 1.f : ((v < 0.f) ? -1.f : 0.f);
}
__device__ __forceinline__ void gridmap(float u, int& i0, float& f) {
    float cc = (u * 0.5f + 0.5f) * 3.f;
    cc = fminf(fmaxf(cc, 0.f), 3.f);
    float fi = floorf(cc);
    fi = fminf(fi, 2.f);
    f = cc - fi;
    i0 = (int)fi;
}

__global__ void geom_kernel(const float* __restrict__ pin, const float* __restrict__ pout,
                            const int* __restrict__ nbr, const void* __restrict__ mask,
                            float4* __restrict__ gF, int* __restrict__ gI)
{
    int idx = blockIdx.x * blockDim.x + threadIdx.x;
    if (idx >= NF * KNBR) return;
    int mv = g_mask_u8 ? (int)((const unsigned char*)mask)[idx]
                       : ((const int*)mask)[idx];
    if (mv == 0) { gF[idx] = make_float4(0.f, 0.f, 0.f, 0.f); gI[idx] = 0; return; }
    int n = idx >> 6;
    int j = nbr[idx];
    float x = (pin[j*3+0] - pout[n*3+0]) / RADIUS_F;
    float y = (pin[j*3+1] - pout[n*3+1]) / RADIUS_F;
    float z = (pin[j*3+2] - pout[n*3+2]) / RADIUS_F;
    float sq = x*x + y*y + z*z;
    float t1 = 1.f - sq;
    float win = fminf(fmaxf(t1*t1*t1, 0.f), 1.f);

    const float eps = 1e-12f;
    float norm = sqrtf(fmaxf(sq, eps));
    float rho  = sqrtf(fmaxf(x*x + y*y, eps));
    bool  top  = (1.25f*z*z > x*x + y*y);
    float s_top = sqrtf(3.f*norm / (norm + fabsf(z)));
    float xs = top ? x*s_top : (x*norm)/rho;
    float ys = top ? y*s_top : (y*norm)/rho;
    float zs = top ? sgnf(z)*norm : 1.5f*z;
    if (sq < eps) { xs = 0.f; ys = 0.f; zs = 0.f; }
    float rxy = sqrtf(fmaxf(xs*xs + ys*ys, eps));
    bool use_x = fabsf(ys) <= fabsf(xs);
    float ddx = (use_x  && fabsf(xs) > eps) ? xs : 1.f;
    float ddy = (!use_x && fabsf(ys) > eps) ? ys : 1.f;
    const float c4 = 1.27323954473516276487f;  // 4/pi
    float xc = use_x ? sgnf(xs)*rxy : sgnf(ys)*rxy*c4*atanf(xs/ddy);
    float yc = use_x ? sgnf(xs)*rxy*c4*atanf(ys/ddx) : sgnf(ys)*rxy;
    if (xs*xs + ys*ys < eps) { xc = 0.f; yc = 0.f; }

    int ix, iy, iz; float fx, fy, fz;
    gridmap(xc, ix, fx); gridmap(yc, iy, fy); gridmap(zs, iz, fz);
    gF[idx] = make_float4(fx, fy, fz, win);
    gI[idx] = (ix*4 + iy)*4 + iz;
}

// ---------------- layer-1 cconv (cin=3, cout=32), W staged in smem (FULL 6144) ----------------
__global__ __launch_bounds__(256) void conv1_kernel(
    const float* __restrict__ feat, const int* __restrict__ nbr,
    const float4* __restrict__ gF, const int* __restrict__ gI,
    const float* __restrict__ W, const float* __restrict__ b,
    float* __restrict__ out1, int col0)
{
    __shared__ float A[4][192];
    __shared__ float sW[192 * 32];     // full W: 64 cells x 3 cin x 32 cout
    __shared__ float red[256];
    int t = threadIdx.x;
    int p = t >> 6, tl = t & 63;
    int n = blockIdx.x * 4 + p;
    float* Ap = A[p];
    Ap[tl] = 0.f; Ap[tl + 64] = 0.f; Ap[tl + 128] = 0.f;
    #pragma unroll
    for (int i = 0; i < 24; i++) sW[i * 256 + t] = W[i * 256 + t];
    __syncthreads();

    int idx = n * KNBR + tl;
    float4 g = gF[idx];
    if (g.w != 0.f) {
        int j = nbr[idx];
        float f0 = feat[j*3+0]*g.w, f1 = feat[j*3+1]*g.w, f2 = feat[j*3+2]*g.w;
        int base = gI[idx];
        float wx[2] = {1.f - g.x, g.x};
        float wy[2] = {1.f - g.y, g.y};
        float wz[2] = {1.f - g.z, g.z};
        #pragma unroll
        for (int cx = 0; cx < 2; cx++)
        #pragma unroll
        for (int cy = 0; cy < 2; cy++)
        #pragma unroll
        for (int cz = 0; cz < 2; cz++) {
            float wc = wx[cx]*wy[cy]*wz[cz];
            int cell = base + cx*16 + cy*4 + cz;
            atomicAdd(&Ap[cell*3+0], wc*f0);
            atomicAdd(&Ap[cell*3+1], wc*f1);
            atomicAdd(&Ap[cell*3+2], wc*f2);
        }
    }
    __syncthreads();

    int o = tl & 31, h = tl >> 5;
    float acc = 0.f;
    #pragma unroll 8
    for (int i = h*96; i < h*96 + 96; i++)
        acc += Ap[i] * sW[i*32 + o];
    red[t] = acc;
    __syncthreads();
    if (tl < 32) {
        float v = red[p*64 + tl] + red[p*64 + tl + 32] + b[o];
        out1[n*96 + col0 + tl] = fmaxf(v, 0.f);
    }
}

// ---------------- cellgemm: A[n] = S[n] @ F[n] on tensor cores (layers 2/3) ----------------
#define S_WLDS 36
template<int CIN>
__global__ __launch_bounds__(128) void cellgemm_kernel(
    const float* __restrict__ feat, const int* __restrict__ nbr,
    const float4* __restrict__ gF, const int* __restrict__ gI,
    uint32_t* __restrict__ Aout)
{
    constexpr int F_WLDS = CIN + 8;
    constexpr int NT = CIN / 8;
    __shared__ uint32_t sS[64 * S_WLDS];
    __shared__ uint32_t sF[32 * F_WLDS];
    __shared__ float4 sG[KNBR];
    __shared__ int    sJ[KNBR];
    __shared__ int    sB[KNBR];
    int n = blockIdx.x, t = threadIdx.x;
    int w = t >> 5, lane = t & 31;
    int g = lane >> 2, tg = lane & 3;

    if (t < KNBR) { sG[t] = gF[n*KNBR + t]; sB[t] = gI[n*KNBR + t]; sJ[t] = nbr[n*KNBR + t]; }
    for (int i = t; i < 64 * S_WLDS; i += 128) sS[i] = 0;
    __syncthreads();

    if (t < KNBR) {
        float4 gv = sG[t];
        if (gv.w != 0.f) {
            __nv_bfloat16* Sh = (__nv_bfloat16*)sS;
            int base = sB[t];
            float wx0 = (1.f - gv.x) * gv.w, wx1 = gv.x * gv.w;
            float wy0 = 1.f - gv.y, wy1 = gv.y;
            float wz0 = 1.f - gv.z, wz1 = gv.z;
            Sh[(base     ) * (2*S_WLDS) + t] = __float2bfloat16(wx0*wy0*wz0);
            Sh[(base +  1) * (2*S_WLDS) + t] = __float2bfloat16(wx0*wy0*wz1);
            Sh[(base +  4) * (2*S_WLDS) + t] = __float2bfloat16(wx0*wy1*wz0);
            Sh[(base +  5) * (2*S_WLDS) + t] = __float2bfloat16(wx0*wy1*wz1);
            Sh[(base + 16) * (2*S_WLDS) + t] = __float2bfloat16(wx1*wy0*wz0);
            Sh[(base + 17) * (2*S_WLDS) + t] = __float2bfloat16(wx1*wy0*wz1);
            Sh[(base + 20) * (2*S_WLDS) + t] = __float2bfloat16(wx1*wy1*wz0);
            Sh[(base + 21) * (2*S_WLDS) + t] = __float2bfloat16(wx1*wy1*wz1);
        }
    }

    for (int i = t; i < 32 * CIN; i += 128) {
        int kp = i / CIN, c = i - kp * CIN;
        float f0 = feat[(size_t)sJ[2*kp    ] * CIN + c];
        float f1 = feat[(size_t)sJ[2*kp + 1] * CIN + c];
        sF[kp * F_WLDS + c] = bf16x2(f1, f0);
    }
    __syncthreads();

    float acc[NT][4];
    #pragma unroll
    for (int nt = 0; nt < NT; nt++)
        #pragma unroll
        for (int q = 0; q < 4; q++) acc[nt][q] = 0.f;

    #pragma unroll
    for (int q = 0; q < 4; q++) {
        int r = w * 16 + g;
        uint32_t a0 = sS[(r    ) * S_WLDS + 8*q + tg    ];
        uint32_t a1 = sS[(r + 8) * S_WLDS + 8*q + tg    ];
        uint32_t a2 = sS[(r    ) * S_WLDS + 8*q + tg + 4];
        uint32_t a3 = sS[(r + 8) * S_WLDS + 8*q + tg + 4];
        #pragma unroll
        for (int nt = 0; nt < NT; nt++) {
            uint32_t b0 = sF[(8*q + tg    ) * F_WLDS + nt * 8 + g];
            uint32_t b1 = sF[(8*q + tg + 4) * F_WLDS + nt * 8 + g];
            asm volatile(
                "mma.sync.aligned.m16n8k16.row.col.f32.bf16.bf16.f32 "
                "{%0,%1,%2,%3},{%4,%5,%6,%7},{%8,%9},{%0,%1,%2,%3};"
                : "+f"(acc[nt][0]), "+f"(acc[nt][1]), "+f"(acc[nt][2]), "+f"(acc[nt][3])
                : "r"(a0), "r"(a1), "r"(a2), "r"(a3), "r"(b0), "r"(b1));
        }
    }

    uint32_t* out = Aout + (size_t)n * (32 * CIN);
    #pragma unroll
    for (int nt = 0; nt < NT; nt++) {
        #pragma unroll
        for (int h = 0; h < 2; h++) {
            int cell = w * 16 + g + h * 8;
            out[cell * (CIN/2) + nt * 4 + tg] = bf16x2(acc[nt][h*2+1], acc[nt][h*2+0]);
        }
    }
}

// ---------------- W pack: Wb[kp*64+n] = bf16x2(W[(2kp+1)*64+n], W[2kp*64+n]) ----------------
__global__ void pack_w_kernel(const float* __restrict__ W, uint32_t* __restrict__ Wb, int KP)
{
    int idx = blockIdx.x * blockDim.x + threadIdx.x;
    if (idx >= KP * 64) return;
    int kp = idx >> 6, n = idx & 63;
    Wb[idx] = bf16x2(W[(size_t)(2*kp+1)*64 + n], W[(size_t)(2*kp)*64 + n]);
}

// ---------------- W_c4 re-layout: Wp[c*256 + cell*4 + o] ----------------
__global__ void pack_w4_kernel(const float* __restrict__ W, float* __restrict__ Wp)
{
    int idx = blockIdx.x * blockDim.x + threadIdx.x;
    if (idx >= 64 * 256) return;
    int c = idx >> 8, col = idx & 255;
    int cell = col >> 2, o = col & 3;
    Wp[idx] = (o < 3) ? W[((size_t)cell * 64 + c) * 3 + o] : 0.f;
}

// ---------------- pconv4: P[n, cell*4+o] = out3[n,:] @ Wp[:, cell*4+o] (fp32) ----------------
__global__ __launch_bounds__(256) void pconv4_kernel(
    const float* __restrict__ X, const float* __restrict__ Wp, float* __restrict__ P)
{
    __shared__ float4 Xs[32][16];                 // 32 particles x 64 floats
    int t = threadIdx.x;
    int n0 = blockIdx.x * 32;
    for (int i = t; i < 512; i += 256) {
        int r = i >> 4, c4 = i & 15;
        Xs[r][c4] = *(const float4*)(X + (size_t)(n0 + r) * 64 + c4 * 4);
    }
    __syncthreads();

    float acc[32];
    #pragma unroll
    for (int r = 0; r < 32; r++) acc[r] = 0.f;
    #pragma unroll
    for (int c4 = 0; c4 < 16; c4++) {
        float w0 = Wp[(c4*4 + 0) * 256 + t];
        float w1 = Wp[(c4*4 + 1) * 256 + t];
        float w2 = Wp[(c4*4 + 2) * 256 + t];
        float w3 = Wp[(c4*4 + 3) * 256 + t];
        #pragma unroll
        for (int r = 0; r < 32; r++) {
            float4 xv = Xs[r][c4];
            acc[r] += xv.x*w0 + xv.y*w1 + xv.z*w2 + xv.w*w3;
        }
    }
    #pragma unroll
    for (int r = 0; r < 32; r++)
        P[(size_t)(n0 + r) * 256 + t] = acc[r];
}

// ---------------- conv4 gather ----------------
__global__ __launch_bounds__(64) void conv4_kernel(
    const float* __restrict__ P, const int* __restrict__ nbr,
    const float4* __restrict__ gF, const int* __restrict__ gI,
    const float* __restrict__ b, const float* __restrict__ dense,
    float* __restrict__ out)
{
    __shared__ float red[2][3];
    int n = blockIdx.x, t = threadIdx.x;          // 64 threads = 64 neighbors
    float a0 = 0.f, a1 = 0.f, a2 = 0.f;
    float4 g = gF[n*KNBR + t];
    if (g.w != 0.f) {
        int j = nbr[n*KNBR + t];
        const float4* Pj = (const float4*)(P + (size_t)j * 256);
        int base = gI[n*KNBR + t];
        float wx0 = (1.f - g.x) * g.w, wx1 = g.x * g.w;
        float wy0 = 1.f - g.y, wy1 = g.y;
        float wz0 = 1.f - g.z, wz1 = g.z;
        float wq[8] = {wx0*wy0*wz0, wx0*wy0*wz1, wx0*wy1*wz0, wx0*wy1*wz1,
                       wx1*wy0*wz0, wx1*wy0*wz1, wx1*wy1*wz0, wx1*wy1*wz1};
        const int off[8] = {0, 1, 4, 5, 16, 17, 20, 21};
        #pragma unroll
        for (int q = 0; q < 8; q++) {
            float4 p = Pj[base + off[q]];
            a0 += wq[q] * p.x; a1 += wq[q] * p.y; a2 += wq[q] * p.z;
        }
    }
    #pragma unroll
    for (int s = 16; s > 0; s >>= 1) {
        a0 += __shfl_down_sync(0xffffffff, a0, s);
        a1 += __shfl_down_sync(0xffffffff, a1, s);
        a2 += __shfl_down_sync(0xffffffff, a2, s);
    }
    if ((t & 31) == 0) { red[t>>5][0] = a0; red[t>>5][1] = a1; red[t>>5][2] = a2; }
    __syncthreads();
    if (t < 3) out[n*3 + t] = red[0][t] + red[1][t] + b[t] + dense[n*3 + t];
}

// ---------------- bf16 tensor GEMM: out[M,64] = A[M,K] @ W[K,64], mma m16n8k16 ----------------
#define STAGES 4
#define A_WLDS 20
#define B_WLDS 72
#define A_WSTAGE (128*A_WLDS)
#define B_WSTAGE (16*B_WLDS)
#define GEMM_SMEM (STAGES*(A_WSTAGE + B_WSTAGE)*4)

template<int HAS_ADD, int HAS_RES, int RELU>
__global__ __launch_bounds__(128) void gemm_mma(
    const __nv_bfloat16* __restrict__ Ag, const uint32_t* __restrict__ Wb,
    const float* __restrict__ bias, const float* __restrict__ addv,
    const float* __restrict__ resv, float* __restrict__ out, int K)
{
    extern __shared__ uint32_t sm[];
    uint32_t* sA = sm;
    uint32_t* sB = sm + STAGES * A_WSTAGE;
    int tid = threadIdx.x, w = tid >> 5, lane = tid & 31;
    int g = lane >> 2, tg = lane & 3;
    int m0 = blockIdx.x * 128;
    int NIT = K >> 5;
    uint32_t sAu = smem_u32(sA), sBu = smem_u32(sB);

    auto load_stage = [&](int s, int c) {
        uint32_t ab = sAu + (uint32_t)s * A_WSTAGE * 4;
        const __nv_bfloat16* as = Ag + (size_t)m0 * K + c * 32;
        #pragma unroll
        for (int r = 0; r < 4; r++) {
            int idx = r * 128 + tid;
            int row = idx >> 2, seg = idx & 3;
            cp16(ab + (row * A_WLDS + seg * 4) * 4, as + (size_t)row * K + seg * 8);
        }
        uint32_t bb = sBu + (uint32_t)s * B_WSTAGE * 4;
        const uint32_t* bs = Wb + (size_t)c * 16 * 64;
        #pragma unroll
        for (int r = 0; r < 2; r++) {
            int idx = r * 128 + tid;
            int kp = idx >> 4, seg = idx & 15;
            cp16(bb + (kp * B_WLDS + seg * 4) * 4, bs + kp * 64 + seg * 4);
        }
    };

    float acc[2][8][4];
    #pragma unroll
    for (int mt = 0; mt < 2; mt++)
        #pragma unroll
        for (int nt = 0; nt < 8; nt++)
            #pragma unroll
            for (int q = 0; q < 4; q++) acc[mt][nt][q] = 0.f;

    #pragma unroll
    for (int s = 0; s < STAGES; s++) { load_stage(s, s); CP_COMMIT(); }

    for (int i = 0; i < NIT; i++) {
        asm volatile("cp.async.wait_group %0;" :: "n"(STAGES - 1));
        __syncthreads();
        const uint32_t* cA = sA + (i % STAGES) * A_WSTAGE;
        const uint32_t* cB = sB + (i % STAGES) * B_WSTAGE;
        #pragma unroll
        for (int q = 0; q < 2; q++) {
            uint32_t a[2][4], b[8][2];
            #pragma unroll
            for (int mt = 0; mt < 2; mt++) {
                int r = w * 32 + mt * 16 + g;
                a[mt][0] = cA[(r    ) * A_WLDS + 8*q + tg    ];
                a[mt][1] = cA[(r + 8) * A_WLDS + 8*q + tg    ];
                a[mt][2] = cA[(r    ) * A_WLDS + 8*q + tg + 4];
                a[mt][3] = cA[(r + 8) * A_WLDS + 8*q + tg + 4];
            }
            #pragma unroll
            for (int nt = 0; nt < 8; nt++) {
                b[nt][0] = cB[(8*q + tg    ) * B_WLDS + nt * 8 + g];
                b[nt][1] = cB[(8*q + tg + 4) * B_WLDS + nt * 8 + g];
            }
            #pragma unroll
            for (int mt = 0; mt < 2; mt++)
                #pragma unroll
                for (int nt = 0; nt < 8; nt++)
                    asm volatile(
                        "mma.sync.aligned.m16n8k16.row.col.f32.bf16.bf16.f32 "
                        "{%0,%1,%2,%3},{%4,%5,%6,%7},{%8,%9},{%0,%1,%2,%3};"
                        : "+f"(acc[mt][nt][0]), "+f"(acc[mt][nt][1]),
                          "+f"(acc[mt][nt][2]), "+f"(acc[mt][nt][3])
                        : "r"(a[mt][0]), "r"(a[mt][1]), "r"(a[mt][2]), "r"(a[mt][3]),
                          "r"(b[nt][0]), "r"(b[nt][1]));
        }
        __syncthreads();
        if (i + STAGES < NIT) load_stage(i % STAGES, i + STAGES);
        CP_COMMIT();
    }

    #pragma unroll
    for (int mt = 0; mt < 2; mt++) {
        #pragma unroll
        for (int nt = 0; nt < 8; nt++) {
            #pragma unroll
            for (int h = 0; h < 2; h++) {
                int m = m0 + w * 32 + mt * 16 + g + h * 8;
                int n0 = nt * 8 + 2 * tg;
                float lo = acc[mt][nt][h*2+0], hi = acc[mt][nt][h*2+1];
                float2 bb = *(const float2*)&bias[n0];
                lo += bb.x; hi += bb.y;
                if (HAS_ADD) {
                    float2 v = *(const float2*)&addv[(size_t)m*64 + n0];
                    lo += v.x; hi += v.y;
                }
                if (HAS_RES) {
                    float2 v = *(const float2*)&resv[(size_t)m*64 + n0];
                    lo += v.x; hi += v.y;
                }
                if (RELU) { lo = fmaxf(lo, 0.f); hi = fmaxf(hi, 0.f); }
                *(float2*)&out[(size_t)m*64 + n0] = make_float2(lo, hi);
            }
        }
    }
}

// ---------------- dense GEMM (pconv4 pattern): Y[n0..n0+32, col0+o] = X@W + b ----------------
template<int CIN, int COUT, int RPT>
__global__ __launch_bounds__(COUT * (32 / RPT)) void dense_gemm(
    const float* __restrict__ X, const float* __restrict__ W,
    const float* __restrict__ b, float* __restrict__ Y, int ldY, int col0)
{
    constexpr int BD = COUT * (32 / RPT);
    __shared__ float Xs[32 * CIN];
    int t = threadIdx.x;
    int n0 = blockIdx.x * 32;
    for (int i = t; i < 32 * CIN; i += BD)
        Xs[i] = X[(size_t)n0 * CIN + i];
    __syncthreads();

    int o = t % COUT, rg = t / COUT;
    float acc[RPT];
    float bo = b[o];
    #pragma unroll
    for (int r = 0; r < RPT; r++) acc[r] = bo;
    #pragma unroll 4
    for (int c = 0; c < CIN; c++) {
        float wv = W[c * COUT + o];
        #pragma unroll
        for (int r = 0; r < RPT; r++)
            acc[r] += Xs[(rg * RPT + r) * CIN + c] * wv;
    }
    #pragma unroll
    for (int r = 0; r < RPT; r++)
        Y[(size_t)(n0 + rg * RPT + r) * ldY + col0 + o] = acc[r];
}

// ---------------- small dense (layer-4 shortcut, COUT=3) ----------------
__global__ void dense_kernel(const float* __restrict__ X, const float* __restrict__ W,
                             const float* __restrict__ b, float* __restrict__ Y,
                             int CIN, int COUT, int ldY, int col0)
{
    int idx = blockIdx.x * blockDim.x + threadIdx.x;
    if (idx >= NF * COUT) return;
    int n = idx / COUT, o = idx - n*COUT;
    float acc = b[o];
    const float* x = X + (size_t)n * CIN;
    for (int c = 0; c < CIN; c++) acc += x[c] * W[c*COUT + o];
    Y[(size_t)n*ldY + col0 + o] = acc;
}

// ---------------- launch ----------------
extern "C" void kernel_launch(void* const* d_in, const int* in_sizes, int n_in,
                              void* d_out, int out_size)
{
    const float* fluid_pos = (const float*)d_in[0];
    const float* wall_pos  = (const float*)d_in[1];
    const float* fluid_vel = (const float*)d_in[2];
    const float* wall_nv   = (const float*)d_in[3];
    const int*   nbr_wf    = (const int*)d_in[4];
    const void*  mask_wf   = d_in[5];
    const int*   nbr_ff    = (const int*)d_in[6];
    const void*  mask_ff   = d_in[7];
    const float* W_wall1 = (const float*)d_in[8];
    const float* b_wall1 = (const float*)d_in[9];
    const float* W_fluid1 = (const float*)d_in[10];
    const float* b_fluid1 = (const float*)d_in[11];
    const float* W_d1 = (const float*)d_in[12];
    const float* b_d1 = (const float*)d_in[13];
    const float* W_c2 = (const float*)d_in[14];
    const float* b_c2 = (const float*)d_in[15];
    const float* W_d2 = (const float*)d_in[16];
    const float* b_d2 = (const float*)d_in[17];
    const float* W_c3 = (const float*)d_in[18];
    const float* b_c3 = (const float*)d_in[19];
    const float* W_d3 = (const float*)d_in[20];
    const float* b_d3 = (const float*)d_in[21];
    const float* W_c4 = (const float*)d_in[22];
    const float* b_c4 = (const float*)d_in[23];
    const float* W_d4 = (const float*)d_in[24];
    const float* b_d4 = (const float*)d_in[25];

    void *pA, *pgFff, *pgIff, *pgFwf, *pgIwf, *pout1, *pout2, *pout3, *pdense, *pWb2, *pWb3, *pWp4;
    cudaGetSymbolAddress(&pA, g_A);
    cudaGetSymbolAddress(&pgFff, g_gF_ff);
    cudaGetSymbolAddress(&pgIff, g_gI_ff);
    cudaGetSymbolAddress(&pgFwf, g_gF_wf);
    cudaGetSymbolAddress(&pgIwf, g_gI_wf);
    cudaGetSymbolAddress(&pout1, g_out1);
    cudaGetSymbolAddress(&pout2, g_out2);
    cudaGetSymbolAddress(&pout3, g_out3);
    cudaGetSymbolAddress(&pdense, g_dense);
    cudaGetSymbolAddress(&pWb2, g_Wb2);
    cudaGetSymbolAddress(&pWb3, g_Wb3);
    cudaGetSymbolAddress(&pWp4, g_Wp4);
    void*   A     = pA;
    float4* gFff  = (float4*)pgFff;
    int*    gIff  = (int*)pgIff;
    float4* gFwf  = (float4*)pgFwf;
    int*    gIwf  = (int*)pgIwf;
    float*  out1  = (float*)pout1;
    float*  out2  = (float*)pout2;
    float*  out3  = (float*)pout3;
    float*  dense = (float*)pdense;
    uint32_t* Wb2 = (uint32_t*)pWb2;
    uint32_t* Wb3 = (uint32_t*)pWb3;
    float*  Wp4   = (float*)pWp4;

    cudaFuncSetAttribute(gemm_mma<1,0,1>, cudaFuncAttributeMaxDynamicSharedMemorySize, GEMM_SMEM);
    cudaFuncSetAttribute(gemm_mma<1,1,1>, cudaFuncAttributeMaxDynamicSharedMemorySize, GEMM_SMEM);

    const int tot = NF * KNBR;
    detect_mask_kernel<<<1, 1024>>>((const unsigned int*)mask_wf);
    geom_kernel<<<(tot + 255)/256, 256>>>(wall_pos,  fluid_pos, nbr_wf, mask_wf, gFwf, gIwf);
    geom_kernel<<<(tot + 255)/256, 256>>>(fluid_pos, fluid_pos, nbr_ff, mask_ff, gFff, gIff);
    pack_w_kernel<<<(3072*64 + 255)/256, 256>>>(W_c2, Wb2, 3072);
    pack_w_kernel<<<(2048*64 + 255)/256, 256>>>(W_c3, Wb3, 2048);
    pack_w4_kernel<<<(64*256 + 255)/256, 256>>>(W_c4, Wp4);

    // layer 1
    conv1_kernel<<<NF/4, 256>>>(wall_nv,   nbr_wf, gFwf, gIwf, W_wall1,  b_wall1,  out1, 0);
    conv1_kernel<<<NF/4, 256>>>(fluid_vel, nbr_ff, gFff, gIff, W_fluid1, b_fluid1, out1, 32);
    dense_gemm<3, 32, 4><<<NF/32, 256>>>(fluid_vel, W_d1, b_d1, out1, 96, 64);

    // layer 2
    dense_gemm<96, 64, 8><<<NF/32, 256>>>(out1, W_d2, b_d2, dense, 64, 0);
    cellgemm_kernel<96><<<NF, 128>>>(out1, nbr_ff, gFff, gIff, (uint32_t*)A);
    gemm_mma<1, 0, 1><<<NF/128, 128, GEMM_SMEM>>>((const __nv_bfloat16*)A, Wb2, b_c2, dense, nullptr, out2, 6144);

    // layer 3
    dense_gemm<64, 64, 8><<<NF/32, 256>>>(out2, W_d3, b_d3, dense, 64, 0);
    cellgemm_kernel<64><<<NF, 128>>>(out2, nbr_ff, gFff, gIff, (uint32_t*)A);
    gemm_mma<1, 1, 1><<<NF/128, 128, GEMM_SMEM>>>((const __nv_bfloat16*)A, Wb3, b_c3, dense, out2, out3, 4096);

    // layer 4: P = out3 @ W_c4 (per input particle), then trilinear gather
    dense_kernel<<<(NF*3 + 255)/256, 256>>>(out3, W_d4, b_d4, dense, 64, 3, 3, 0);
    pconv4_kernel<<<NF/32, 256>>>(out3, Wp4, (float*)A);
    conv4_kernel<<<NF, 64>>>((const float*)A, nbr_ff, gFff, gIff, b_c4, dense, (float*)d_out);
}

// round 11
// speedup vs baseline: 3.1107x; 1.1342x over previous
#include <cuda_runtime.h>
#include <cuda_bf16.h>
#include <cstdint>
#include <cstddef>

#define NF   16000
#define KNBR 64
#define RADIUS_F ((float)(0.5*6.0*1.5*0.025))

// ---------------- scratch (device globals; no allocation APIs) ----------------
__device__ float  g_A[(size_t)NF * 64 * 96];   // bf16 A for layers 2/3; fp32 P for layer 4
__device__ float4 g_gF_ff[NF * KNBR];
__device__ int    g_gI_ff[NF * KNBR];
__device__ float4 g_gF_wf[NF * KNBR];
__device__ int    g_gI_wf[NF * KNBR];
__device__ float  g_out1[NF * 96];
__device__ __nv_bfloat16 g_out1b[NF * 96];     // bf16 mirror of out1 (cellgemm gather)
__device__ float  g_out2[NF * 64];
__device__ __nv_bfloat16 g_out2b[NF * 64];     // bf16 mirror of out2
__device__ float  g_out3[NF * 64];
__device__ float  g_dense[NF * 64];
__device__ uint32_t g_Wb2[3072 * 64];          // W_c2 packed bf16x2, [kp][n]
__device__ uint32_t g_Wb3[2048 * 64];          // W_c3 packed bf16x2
__device__ float  g_Wp4[64 * 256];             // W_c4 re-laid [c][cell*4+o], pad o=3 -> 0
__device__ int    g_mask_u8;

// ---------------- helpers ----------------
__device__ __forceinline__ uint32_t smem_u32(const void* p) {
    uint32_t a;
    asm("{ .reg .u64 t; cvta.to.shared.u64 t, %1; cvt.u32.u64 %0, t; }" : "=r"(a) : "l"(p));
    return a;
}
__device__ __forceinline__ void cp16(uint32_t dst, const void* src) {
    asm volatile("cp.async.cg.shared.global [%0], [%1], 16;" :: "r"(dst), "l"(src));
}
#define CP_COMMIT() asm volatile("cp.async.commit_group;" ::: "memory")
__device__ __forceinline__ uint32_t bf16x2(float hi, float lo) {
    uint32_t r;
    asm("cvt.rn.bf16x2.f32 %0, %1, %2;" : "=r"(r) : "f"(hi), "f"(lo));
    return r;
}

// ---------------- mask dtype detector (16K words is plenty) ----------------
__global__ void detect_mask_kernel(const unsigned int* __restrict__ m)
{
    __shared__ int s;
    if (threadIdx.x == 0) s = 0;
    __syncthreads();
    int bad = 0;
    for (int i = threadIdx.x; i < 16384; i += blockDim.x)
        if (m[i] > 1u) { bad = 1; break; }
    if (bad) atomicOr(&s, 1);
    __syncthreads();
    if (threadIdx.x == 0) g_mask_u8 = s;
}

// ---------------- geometry (both neighbor sets in one launch) ----------------
static __device__ __forceinline__ float sgnf(float v) {
    return (v > 0.f) ? 1.f : ((v < 0.f) ? -1.f : 0.f);
}
__device__ __forceinline__ void gridmap(float u, int& i0, float& f) {
    float cc = (u * 0.5f + 0.5f) * 3.f;
    cc = fminf(fmaxf(cc, 0.f), 3.f);
    float fi = floorf(cc);
    fi = fminf(fi, 2.f);
    f = cc - fi;
    i0 = (int)fi;
}

__global__ void geom2_kernel(
    const float* __restrict__ fluid_pos, const float* __restrict__ wall_pos,
    const int* __restrict__ nbr_ff, const void* __restrict__ mask_ff,
    float4* __restrict__ gFff, int* __restrict__ gIff,
    const int* __restrict__ nbr_wf, const void* __restrict__ mask_wf,
    float4* __restrict__ gFwf, int* __restrict__ gIwf)
{
    int gidx = blockIdx.x * blockDim.x + threadIdx.x;
    if (gidx >= 2 * NF * KNBR) return;
    int which = gidx >= NF * KNBR;                 // uniform per block (tot % 256 == 0)
    int idx = which ? gidx - NF * KNBR : gidx;
    const float* pin = which ? wall_pos : fluid_pos;
    const int*   nbr = which ? nbr_wf   : nbr_ff;
    const void*  mask = which ? mask_wf : mask_ff;
    float4* gF = which ? gFwf : gFff;
    int*    gI = which ? gIwf : gIff;

    int mv = g_mask_u8 ? (int)((const unsigned char*)mask)[idx]
                       : ((const int*)mask)[idx];
    if (mv == 0) { gF[idx] = make_float4(0.f, 0.f, 0.f, 0.f); gI[idx] = 0; return; }
    int n = idx >> 6;
    int j = nbr[idx];
    float x = (pin[j*3+0] - fluid_pos[n*3+0]) / RADIUS_F;
    float y = (pin[j*3+1] - fluid_pos[n*3+1]) / RADIUS_F;
    float z = (pin[j*3+2] - fluid_pos[n*3+2]) / RADIUS_F;
    float sq = x*x + y*y + z*z;
    float t1 = 1.f - sq;
    float win = fminf(fmaxf(t1*t1*t1, 0.f), 1.f);

    const float eps = 1e-12f;
    float norm = sqrtf(fmaxf(sq, eps));
    float rho  = sqrtf(fmaxf(x*x + y*y, eps));
    bool  top  = (1.25f*z*z > x*x + y*y);
    float s_top = sqrtf(3.f*norm / (norm + fabsf(z)));
    float xs = top ? x*s_top : (x*norm)/rho;
    float ys = top ? y*s_top : (y*norm)/rho;
    float zs = top ? sgnf(z)*norm : 1.5f*z;
    if (sq < eps) { xs = 0.f; ys = 0.f; zs = 0.f; }
    float rxy = sqrtf(fmaxf(xs*xs + ys*ys, eps));
    bool use_x = fabsf(ys) <= fabsf(xs);
    float ddx = (use_x  && fabsf(xs) > eps) ? xs : 1.f;
    float ddy = (!use_x && fabsf(ys) > eps) ? ys : 1.f;
    const float c4 = 1.27323954473516276487f;  // 4/pi
    float xc = use_x ? sgnf(xs)*rxy : sgnf(ys)*rxy*c4*atanf(xs/ddy);
    float yc = use_x ? sgnf(xs)*rxy*c4*atanf(ys/ddx) : sgnf(ys)*rxy;
    if (xs*xs + ys*ys < eps) { xc = 0.f; yc = 0.f; }

    int ix, iy, iz; float fx, fy, fz;
    gridmap(xc, ix, fx); gridmap(yc, iy, fy); gridmap(zs, iz, fz);
    gF[idx] = make_float4(fx, fy, fz, win);
    gI[idx] = (ix*4 + iy)*4 + iz;
}

// ---------------- layer-1 cconv (cin=3, cout=32), W staged in smem ----------------
__global__ __launch_bounds__(256) void conv1_kernel(
    const float* __restrict__ feat, const int* __restrict__ nbr,
    const float4* __restrict__ gF, const int* __restrict__ gI,
    const float* __restrict__ W, const float* __restrict__ b,
    float* __restrict__ out1, __nv_bfloat16* __restrict__ out1b, int col0)
{
    __shared__ float A[4][192];
    __shared__ float sW[192 * 32];     // full W: 64 cells x 3 cin x 32 cout
    __shared__ float red[256];
    int t = threadIdx.x;
    int p = t >> 6, tl = t & 63;
    int n = blockIdx.x * 4 + p;
    float* Ap = A[p];
    Ap[tl] = 0.f; Ap[tl + 64] = 0.f; Ap[tl + 128] = 0.f;
    #pragma unroll
    for (int i = 0; i < 24; i++) sW[i * 256 + t] = W[i * 256 + t];
    __syncthreads();

    int idx = n * KNBR + tl;
    float4 g = gF[idx];
    if (g.w != 0.f) {
        int j = nbr[idx];
        float f0 = feat[j*3+0]*g.w, f1 = feat[j*3+1]*g.w, f2 = feat[j*3+2]*g.w;
        int base = gI[idx];
        float wx[2] = {1.f - g.x, g.x};
        float wy[2] = {1.f - g.y, g.y};
        float wz[2] = {1.f - g.z, g.z};
        #pragma unroll
        for (int cx = 0; cx < 2; cx++)
        #pragma unroll
        for (int cy = 0; cy < 2; cy++)
        #pragma unroll
        for (int cz = 0; cz < 2; cz++) {
            float wc = wx[cx]*wy[cy]*wz[cz];
            int cell = base + cx*16 + cy*4 + cz;
            atomicAdd(&Ap[cell*3+0], wc*f0);
            atomicAdd(&Ap[cell*3+1], wc*f1);
            atomicAdd(&Ap[cell*3+2], wc*f2);
        }
    }
    __syncthreads();

    int o = tl & 31, h = tl >> 5;
    float acc = 0.f;
    #pragma unroll 8
    for (int i = h*96; i < h*96 + 96; i++)
        acc += Ap[i] * sW[i*32 + o];
    red[t] = acc;
    __syncthreads();
    if (tl < 32) {
        float v = red[p*64 + tl] + red[p*64 + tl + 32] + b[o];
        v = fmaxf(v, 0.f);
        out1 [n*96 + col0 + tl] = v;
        out1b[n*96 + col0 + tl] = __float2bfloat16(v);
    }
}

// ---------------- cellgemm: A[n] = S[n] @ F[n] on tensor cores (layers 2/3) ----------------
// F gathered from bf16 mirror: half the traffic, identical bits.
#define S_WLDS 36
template<int CIN>
__global__ __launch_bounds__(128) void cellgemm_kernel(
    const __nv_bfloat16* __restrict__ featb, const int* __restrict__ nbr,
    const float4* __restrict__ gF, const int* __restrict__ gI,
    uint32_t* __restrict__ Aout)
{
    constexpr int F_WLDS = CIN + 8;
    constexpr int NT = CIN / 8;
    __shared__ uint32_t sS[64 * S_WLDS];
    __shared__ uint32_t sF[32 * F_WLDS];
    __shared__ float4 sG[KNBR];
    __shared__ int    sJ[KNBR];
    __shared__ int    sB[KNBR];
    int n = blockIdx.x, t = threadIdx.x;
    int w = t >> 5, lane = t & 31;
    int g = lane >> 2, tg = lane & 3;

    if (t < KNBR) { sG[t] = gF[n*KNBR + t]; sB[t] = gI[n*KNBR + t]; sJ[t] = nbr[n*KNBR + t]; }
    for (int i = t; i < 64 * S_WLDS; i += 128) sS[i] = 0;
    __syncthreads();

    if (t < KNBR) {
        float4 gv = sG[t];
        if (gv.w != 0.f) {
            __nv_bfloat16* Sh = (__nv_bfloat16*)sS;
            int base = sB[t];
            float wx0 = (1.f - gv.x) * gv.w, wx1 = gv.x * gv.w;
            float wy0 = 1.f - gv.y, wy1 = gv.y;
            float wz0 = 1.f - gv.z, wz1 = gv.z;
            Sh[(base     ) * (2*S_WLDS) + t] = __float2bfloat16(wx0*wy0*wz0);
            Sh[(base +  1) * (2*S_WLDS) + t] = __float2bfloat16(wx0*wy0*wz1);
            Sh[(base +  4) * (2*S_WLDS) + t] = __float2bfloat16(wx0*wy1*wz0);
            Sh[(base +  5) * (2*S_WLDS) + t] = __float2bfloat16(wx0*wy1*wz1);
            Sh[(base + 16) * (2*S_WLDS) + t] = __float2bfloat16(wx1*wy0*wz0);
            Sh[(base + 17) * (2*S_WLDS) + t] = __float2bfloat16(wx1*wy0*wz1);
            Sh[(base + 20) * (2*S_WLDS) + t] = __float2bfloat16(wx1*wy1*wz0);
            Sh[(base + 21) * (2*S_WLDS) + t] = __float2bfloat16(wx1*wy1*wz1);
        }
    }

    for (int i = t; i < 32 * CIN; i += 128) {
        int kp = i / CIN, c = i - kp * CIN;
        uint32_t u0 = *(const unsigned short*)(featb + (size_t)sJ[2*kp    ] * CIN + c);
        uint32_t u1 = *(const unsigned short*)(featb + (size_t)sJ[2*kp + 1] * CIN + c);
        sF[kp * F_WLDS + c] = (u1 << 16) | u0;
    }
    __syncthreads();

    float acc[NT][4];
    #pragma unroll
    for (int nt = 0; nt < NT; nt++)
        #pragma unroll
        for (int q = 0; q < 4; q++) acc[nt][q] = 0.f;

    #pragma unroll
    for (int q = 0; q < 4; q++) {
        int r = w * 16 + g;
        uint32_t a0 = sS[(r    ) * S_WLDS + 8*q + tg    ];
        uint32_t a1 = sS[(r + 8) * S_WLDS + 8*q + tg    ];
        uint32_t a2 = sS[(r    ) * S_WLDS + 8*q + tg + 4];
        uint32_t a3 = sS[(r + 8) * S_WLDS + 8*q + tg + 4];
        #pragma unroll
        for (int nt = 0; nt < NT; nt++) {
            uint32_t b0 = sF[(8*q + tg    ) * F_WLDS + nt * 8 + g];
            uint32_t b1 = sF[(8*q + tg + 4) * F_WLDS + nt * 8 + g];
            asm volatile(
                "mma.sync.aligned.m16n8k16.row.col.f32.bf16.bf16.f32 "
                "{%0,%1,%2,%3},{%4,%5,%6,%7},{%8,%9},{%0,%1,%2,%3};"
                : "+f"(acc[nt][0]), "+f"(acc[nt][1]), "+f"(acc[nt][2]), "+f"(acc[nt][3])
                : "r"(a0), "r"(a1), "r"(a2), "r"(a3), "r"(b0), "r"(b1));
        }
    }

    uint32_t* out = Aout + (size_t)n * (32 * CIN);
    #pragma unroll
    for (int nt = 0; nt < NT; nt++) {
        #pragma unroll
        for (int h = 0; h < 2; h++) {
            int cell = w * 16 + g + h * 8;
            out[cell * (CIN/2) + nt * 4 + tg] = bf16x2(acc[nt][h*2+1], acc[nt][h*2+0]);
        }
    }
}

// ---------------- merged weight prep: Wb2 + Wb3 + Wp4 in one launch ----------------
#define N_WB2 (3072 * 64)
#define N_WB3 (2048 * 64)
#define N_WP4 (64 * 256)
__global__ void pack_all_kernel(
    const float* __restrict__ W2, const float* __restrict__ W3, const float* __restrict__ W4,
    uint32_t* __restrict__ Wb2, uint32_t* __restrict__ Wb3, float* __restrict__ Wp4)
{
    int idx = blockIdx.x * blockDim.x + threadIdx.x;
    if (idx < N_WB2) {
        int kp = idx >> 6, n = idx & 63;
        Wb2[idx] = bf16x2(W2[(size_t)(2*kp+1)*64 + n], W2[(size_t)(2*kp)*64 + n]);
    } else if (idx < N_WB2 + N_WB3) {
        int j = idx - N_WB2;
        int kp = j >> 6, n = j & 63;
        Wb3[j] = bf16x2(W3[(size_t)(2*kp+1)*64 + n], W3[(size_t)(2*kp)*64 + n]);
    } else if (idx < N_WB2 + N_WB3 + N_WP4) {
        int j = idx - N_WB2 - N_WB3;
        int c = j >> 8, col = j & 255;
        int cell = col >> 2, o = col & 3;
        Wp4[j] = (o < 3) ? W4[((size_t)cell * 64 + c) * 3 + o] : 0.f;
    }
}

// ---------------- pconv4: P[n, cell*4+o] = out3[n,:] @ Wp[:, cell*4+o] (fp32) ----------------
__global__ __launch_bounds__(256) void pconv4_kernel(
    const float* __restrict__ X, const float* __restrict__ Wp, float* __restrict__ P)
{
    __shared__ float4 Xs[32][16];                 // 32 particles x 64 floats
    int t = threadIdx.x;
    int n0 = blockIdx.x * 32;
    for (int i = t; i < 512; i += 256) {
        int r = i >> 4, c4 = i & 15;
        Xs[r][c4] = *(const float4*)(X + (size_t)(n0 + r) * 64 + c4 * 4);
    }
    __syncthreads();

    float acc[32];
    #pragma unroll
    for (int r = 0; r < 32; r++) acc[r] = 0.f;
    #pragma unroll
    for (int c4 = 0; c4 < 16; c4++) {
        float w0 = Wp[(c4*4 + 0) * 256 + t];
        float w1 = Wp[(c4*4 + 1) * 256 + t];
        float w2 = Wp[(c4*4 + 2) * 256 + t];
        float w3 = Wp[(c4*4 + 3) * 256 + t];
        #pragma unroll
        for (int r = 0; r < 32; r++) {
            float4 xv = Xs[r][c4];
            acc[r] += xv.x*w0 + xv.y*w1 + xv.z*w2 + xv.w*w3;
        }
    }
    #pragma unroll
    for (int r = 0; r < 32; r++)
        P[(size_t)(n0 + r) * 256 + t] = acc[r];
}

// ---------------- conv4 gather + fused dense shortcut ----------------
__global__ __launch_bounds__(64) void conv4_kernel(
    const float* __restrict__ P, const int* __restrict__ nbr,
    const float4* __restrict__ gF, const int* __restrict__ gI,
    const float* __restrict__ bc4, const float* __restrict__ out3,
    const float* __restrict__ Wd4, const float* __restrict__ bd4,
    float* __restrict__ out)
{
    __shared__ float red[2][3];
    int n = blockIdx.x, t = threadIdx.x;          // 64 threads = 64 neighbors / 64 channels
    float a0 = 0.f, a1 = 0.f, a2 = 0.f;
    // dense shortcut: channel t's contribution, reduced together with the conv part
    {
        float x = out3[(size_t)n * 64 + t];
        a0 += x * Wd4[t*3 + 0];
        a1 += x * Wd4[t*3 + 1];
        a2 += x * Wd4[t*3 + 2];
    }
    float4 g = gF[n*KNBR + t];
    if (g.w != 0.f) {
        int j = nbr[n*KNBR + t];
        const float4* Pj = (const float4*)(P + (size_t)j * 256);
        int base = gI[n*KNBR + t];
        float wx0 = (1.f - g.x) * g.w, wx1 = g.x * g.w;
        float wy0 = 1.f - g.y, wy1 = g.y;
        float wz0 = 1.f - g.z, wz1 = g.z;
        float wq[8] = {wx0*wy0*wz0, wx0*wy0*wz1, wx0*wy1*wz0, wx0*wy1*wz1,
                       wx1*wy0*wz0, wx1*wy0*wz1, wx1*wy1*wz0, wx1*wy1*wz1};
        const int off[8] = {0, 1, 4, 5, 16, 17, 20, 21};
        #pragma unroll
        for (int q = 0; q < 8; q++) {
            float4 p = Pj[base + off[q]];
            a0 += wq[q] * p.x; a1 += wq[q] * p.y; a2 += wq[q] * p.z;
        }
    }
    #pragma unroll
    for (int s = 16; s > 0; s >>= 1) {
        a0 += __shfl_down_sync(0xffffffff, a0, s);
        a1 += __shfl_down_sync(0xffffffff, a1, s);
        a2 += __shfl_down_sync(0xffffffff, a2, s);
    }
    if ((t & 31) == 0) { red[t>>5][0] = a0; red[t>>5][1] = a1; red[t>>5][2] = a2; }
    __syncthreads();
    if (t < 3) out[n*3 + t] = red[0][t] + red[1][t] + bc4[t] + bd4[t];
}

// ---------------- bf16 tensor GEMM: out[M,64] = A[M,K] @ W[K,64], mma m16n8k16 ----------------
#define STAGES 4
#define A_WLDS 20
#define B_WLDS 72
#define A_WSTAGE (128*A_WLDS)
#define B_WSTAGE (16*B_WLDS)
#define GEMM_SMEM (STAGES*(A_WSTAGE + B_WSTAGE)*4)

template<int HAS_ADD, int HAS_RES, int RELU>
__global__ __launch_bounds__(128) void gemm_mma(
    const __nv_bfloat16* __restrict__ Ag, const uint32_t* __restrict__ Wb,
    const float* __restrict__ bias, const float* __restrict__ addv,
    const float* __restrict__ resv, float* __restrict__ out,
    __nv_bfloat16* __restrict__ outb, int K)
{
    extern __shared__ uint32_t sm[];
    uint32_t* sA = sm;
    uint32_t* sB = sm + STAGES * A_WSTAGE;
    int tid = threadIdx.x, w = tid >> 5, lane = tid & 31;
    int g = lane >> 2, tg = lane & 3;
    int m0 = blockIdx.x * 128;
    int NIT = K >> 5;
    uint32_t sAu = smem_u32(sA), sBu = smem_u32(sB);

    auto load_stage = [&](int s, int c) {
        uint32_t ab = sAu + (uint32_t)s * A_WSTAGE * 4;
        const __nv_bfloat16* as = Ag + (size_t)m0 * K + c * 32;
        #pragma unroll
        for (int r = 0; r < 4; r++) {
            int idx = r * 128 + tid;
            int row = idx >> 2, seg = idx & 3;
            cp16(ab + (row * A_WLDS + seg * 4) * 4, as + (size_t)row * K + seg * 8);
        }
        uint32_t bb = sBu + (uint32_t)s * B_WSTAGE * 4;
        const uint32_t* bs = Wb + (size_t)c * 16 * 64;
        #pragma unroll
        for (int r = 0; r < 2; r++) {
            int idx = r * 128 + tid;
            int kp = idx >> 4, seg = idx & 15;
            cp16(bb + (kp * B_WLDS + seg * 4) * 4, bs + kp * 64 + seg * 4);
        }
    };

    float acc[2][8][4];
    #pragma unroll
    for (int mt = 0; mt < 2; mt++)
        #pragma unroll
        for (int nt = 0; nt < 8; nt++)
            #pragma unroll
            for (int q = 0; q < 4; q++) acc[mt][nt][q] = 0.f;

    #pragma unroll
    for (int s = 0; s < STAGES; s++) { load_stage(s, s); CP_COMMIT(); }

    for (int i = 0; i < NIT; i++) {
        asm volatile("cp.async.wait_group %0;" :: "n"(STAGES - 1));
        __syncthreads();
        const uint32_t* cA = sA + (i % STAGES) * A_WSTAGE;
        const uint32_t* cB = sB + (i % STAGES) * B_WSTAGE;
        #pragma unroll
        for (int q = 0; q < 2; q++) {
            uint32_t a[2][4], b[8][2];
            #pragma unroll
            for (int mt = 0; mt < 2; mt++) {
                int r = w * 32 + mt * 16 + g;
                a[mt][0] = cA[(r    ) * A_WLDS + 8*q + tg    ];
                a[mt][1] = cA[(r + 8) * A_WLDS + 8*q + tg    ];
                a[mt][2] = cA[(r    ) * A_WLDS + 8*q + tg + 4];
                a[mt][3] = cA[(r + 8) * A_WLDS + 8*q + tg + 4];
            }
            #pragma unroll
            for (int nt = 0; nt < 8; nt++) {
                b[nt][0] = cB[(8*q + tg    ) * B_WLDS + nt * 8 + g];
                b[nt][1] = cB[(8*q + tg + 4) * B_WLDS + nt * 8 + g];
            }
            #pragma unroll
            for (int mt = 0; mt < 2; mt++)
                #pragma unroll
                for (int nt = 0; nt < 8; nt++)
                    asm volatile(
                        "mma.sync.aligned.m16n8k16.row.col.f32.bf16.bf16.f32 "
                        "{%0,%1,%2,%3},{%4,%5,%6,%7},{%8,%9},{%0,%1,%2,%3};"
                        : "+f"(acc[mt][nt][0]), "+f"(acc[mt][nt][1]),
                          "+f"(acc[mt][nt][2]), "+f"(acc[mt][nt][3])
                        : "r"(a[mt][0]), "r"(a[mt][1]), "r"(a[mt][2]), "r"(a[mt][3]),
                          "r"(b[nt][0]), "r"(b[nt][1]));
        }
        __syncthreads();
        if (i + STAGES < NIT) load_stage(i % STAGES, i + STAGES);
        CP_COMMIT();
    }

    #pragma unroll
    for (int mt = 0; mt < 2; mt++) {
        #pragma unroll
        for (int nt = 0; nt < 8; nt++) {
            #pragma unroll
            for (int h = 0; h < 2; h++) {
                int m = m0 + w * 32 + mt * 16 + g + h * 8;
                int n0 = nt * 8 + 2 * tg;
                float lo = acc[mt][nt][h*2+0], hi = acc[mt][nt][h*2+1];
                float2 bb = *(const float2*)&bias[n0];
                lo += bb.x; hi += bb.y;
                if (HAS_ADD) {
                    float2 v = *(const float2*)&addv[(size_t)m*64 + n0];
                    lo += v.x; hi += v.y;
                }
                if (HAS_RES) {
                    float2 v = *(const float2*)&resv[(size_t)m*64 + n0];
                    lo += v.x; hi += v.y;
                }
                if (RELU) { lo = fmaxf(lo, 0.f); hi = fmaxf(hi, 0.f); }
                *(float2*)&out[(size_t)m*64 + n0] = make_float2(lo, hi);
                if (outb)
                    *(uint32_t*)&outb[(size_t)m*64 + n0] = bf16x2(hi, lo);
            }
        }
    }
}

// ---------------- dense GEMM: Y[n0..n0+32, col0+o] = X@W + b (+ optional bf16 mirror) ------
template<int CIN, int COUT, int RPT>
__global__ __launch_bounds__(COUT * (32 / RPT)) void dense_gemm(
    const float* __restrict__ X, const float* __restrict__ W,
    const float* __restrict__ b, float* __restrict__ Y,
    __nv_bfloat16* __restrict__ Yb, int ldY, int col0)
{
    constexpr int BD = COUT * (32 / RPT);
    __shared__ float Xs[32 * CIN];
    int t = threadIdx.x;
    int n0 = blockIdx.x * 32;
    for (int i = t; i < 32 * CIN; i += BD)
        Xs[i] = X[(size_t)n0 * CIN + i];
    __syncthreads();

    int o = t % COUT, rg = t / COUT;
    float acc[RPT];
    float bo = b[o];
    #pragma unroll
    for (int r = 0; r < RPT; r++) acc[r] = bo;
    #pragma unroll 4
    for (int c = 0; c < CIN; c++) {
        float wv = W[c * COUT + o];
        #pragma unroll
        for (int r = 0; r < RPT; r++)
            acc[r] += Xs[(rg * RPT + r) * CIN + c] * wv;
    }
    #pragma unroll
    for (int r = 0; r < RPT; r++) {
        size_t off = (size_t)(n0 + rg * RPT + r) * ldY + col0 + o;
        Y[off] = acc[r];
        if (Yb) Yb[off] = __float2bfloat16(acc[r]);
    }
}

// ---------------- launch ----------------
extern "C" void kernel_launch(void* const* d_in, const int* in_sizes, int n_in,
                              void* d_out, int out_size)
{
    const float* fluid_pos = (const float*)d_in[0];
    const float* wall_pos  = (const float*)d_in[1];
    const float* fluid_vel = (const float*)d_in[2];
    const float* wall_nv   = (const float*)d_in[3];
    const int*   nbr_wf    = (const int*)d_in[4];
    const void*  mask_wf   = d_in[5];
    const int*   nbr_ff    = (const int*)d_in[6];
    const void*  mask_ff   = d_in[7];
    const float* W_wall1 = (const float*)d_in[8];
    const float* b_wall1 = (const float*)d_in[9];
    const float* W_fluid1 = (const float*)d_in[10];
    const float* b_fluid1 = (const float*)d_in[11];
    const float* W_d1 = (const float*)d_in[12];
    const float* b_d1 = (const float*)d_in[13];
    const float* W_c2 = (const float*)d_in[14];
    const float* b_c2 = (const float*)d_in[15];
    const float* W_d2 = (const float*)d_in[16];
    const float* b_d2 = (const float*)d_in[17];
    const float* W_c3 = (const float*)d_in[18];
    const float* b_c3 = (const float*)d_in[19];
    const float* W_d3 = (const float*)d_in[20];
    const float* b_d3 = (const float*)d_in[21];
    const float* W_c4 = (const float*)d_in[22];
    const float* b_c4 = (const float*)d_in[23];
    const float* W_d4 = (const float*)d_in[24];
    const float* b_d4 = (const float*)d_in[25];

    void *pA, *pgFff, *pgIff, *pgFwf, *pgIwf, *pout1, *pout1b, *pout2, *pout2b,
         *pout3, *pdense, *pWb2, *pWb3, *pWp4;
    cudaGetSymbolAddress(&pA, g_A);
    cudaGetSymbolAddress(&pgFff, g_gF_ff);
    cudaGetSymbolAddress(&pgIff, g_gI_ff);
    cudaGetSymbolAddress(&pgFwf, g_gF_wf);
    cudaGetSymbolAddress(&pgIwf, g_gI_wf);
    cudaGetSymbolAddress(&pout1, g_out1);
    cudaGetSymbolAddress(&pout1b, g_out1b);
    cudaGetSymbolAddress(&pout2, g_out2);
    cudaGetSymbolAddress(&pout2b, g_out2b);
    cudaGetSymbolAddress(&pout3, g_out3);
    cudaGetSymbolAddress(&pdense, g_dense);
    cudaGetSymbolAddress(&pWb2, g_Wb2);
    cudaGetSymbolAddress(&pWb3, g_Wb3);
    cudaGetSymbolAddress(&pWp4, g_Wp4);
    void*   A     = pA;
    float4* gFff  = (float4*)pgFff;
    int*    gIff  = (int*)pgIff;
    float4* gFwf  = (float4*)pgFwf;
    int*    gIwf  = (int*)pgIwf;
    float*  out1  = (float*)pout1;
    __nv_bfloat16* out1b = (__nv_bfloat16*)pout1b;
    float*  out2  = (float*)pout2;
    __nv_bfloat16* out2b = (__nv_bfloat16*)pout2b;
    float*  out3  = (float*)pout3;
    float*  dense = (float*)pdense;
    uint32_t* Wb2 = (uint32_t*)pWb2;
    uint32_t* Wb3 = (uint32_t*)pWb3;
    float*  Wp4   = (float*)pWp4;

    cudaFuncSetAttribute(gemm_mma<1,0,1>, cudaFuncAttributeMaxDynamicSharedMemorySize, GEMM_SMEM);
    cudaFuncSetAttribute(gemm_mma<1,1,1>, cudaFuncAttributeMaxDynamicSharedMemorySize, GEMM_SMEM);

    const int tot = NF * KNBR;
    detect_mask_kernel<<<1, 1024>>>((const unsigned int*)mask_wf);
    geom2_kernel<<<(2*tot + 255)/256, 256>>>(fluid_pos, wall_pos,
                                             nbr_ff, mask_ff, gFff, gIff,
                                             nbr_wf, mask_wf, gFwf, gIwf);
    pack_all_kernel<<<(N_WB2 + N_WB3 + N_WP4 + 255)/256, 256>>>(W_c2, W_c3, W_c4, Wb2, Wb3, Wp4);

    // layer 1
    conv1_kernel<<<NF/4, 256>>>(wall_nv,   nbr_wf, gFwf, gIwf, W_wall1,  b_wall1,  out1, out1b, 0);
    conv1_kernel<<<NF/4, 256>>>(fluid_vel, nbr_ff, gFff, gIff, W_fluid1, b_fluid1, out1, out1b, 32);
    dense_gemm<3, 32, 4><<<NF/32, 256>>>(fluid_vel, W_d1, b_d1, out1, out1b, 96, 64);

    // layer 2
    dense_gemm<96, 64, 8><<<NF/32, 256>>>(out1, W_d2, b_d2, dense, nullptr, 64, 0);
    cellgemm_kernel<96><<<NF, 128>>>(out1b, nbr_ff, gFff, gIff, (uint32_t*)A);
    gemm_mma<1, 0, 1><<<NF/128, 128, GEMM_SMEM>>>((const __nv_bfloat16*)A, Wb2, b_c2, dense,
                                                  nullptr, out2, out2b, 6144);

    // layer 3
    dense_gemm<64, 64, 8><<<NF/32, 256>>>(out2, W_d3, b_d3, dense, nullptr, 64, 0);
    cellgemm_kernel<64><<<NF, 128>>>(out2b, nbr_ff, gFff, gIff, (uint32_t*)A);
    gemm_mma<1, 1, 1><<<NF/128, 128, GEMM_SMEM>>>((const __nv_bfloat16*)A, Wb3, b_c3, dense,
                                                  out2, out3, nullptr, 4096);

    // layer 4: P = out3 @ W_c4 (per input particle), then trilinear gather + fused dense
    pconv4_kernel<<<NF/32, 256>>>(out3, Wp4, (float*)A);
    conv4_kernel<<<NF, 64>>>((const float*)A, nbr_ff, gFff, gIff, b_c4,
                             out3, W_d4, b_d4, (float*)d_out);
}

// round 12
// speedup vs baseline: 3.1832x; 1.0233x over previous
#include <cuda_runtime.h>
#include <cuda_bf16.h>
#include <cstdint>
#include <cstddef>

#define NF   16000
#define KNBR 64
#define RADIUS_F ((float)(0.5*6.0*1.5*0.025))

// ---------------- scratch (device globals; no allocation APIs) ----------------
__device__ float  g_A[(size_t)NF * 64 * 96];   // bf16 A for layers 2/3; fp32 P for layer 4
__device__ float4 g_gF_ff[NF * KNBR];
__device__ int    g_gI_ff[NF * KNBR];
__device__ float4 g_gF_wf[NF * KNBR];
__device__ int    g_gI_wf[NF * KNBR];
__device__ float  g_out1[NF * 96];
__device__ __nv_bfloat16 g_out1b[NF * 96];     // bf16 mirror of out1 (cellgemm gather)
__device__ float  g_out2[NF * 64];
__device__ __nv_bfloat16 g_out2b[NF * 64];     // bf16 mirror of out2
__device__ float  g_out3[NF * 64];
__device__ float  g_dense[NF * 64];
__device__ uint32_t g_Wb2[3072 * 64];          // W_c2 packed bf16x2, [kp][n]
__device__ uint32_t g_Wb3[2048 * 64];          // W_c3 packed bf16x2
__device__ float  g_Wp4[64 * 256];             // W_c4 re-laid [c][cell*4+o], pad o=3 -> 0
__device__ int    g_mask_u8;

// ---------------- helpers ----------------
__device__ __forceinline__ uint32_t smem_u32(const void* p) {
    uint32_t a;
    asm("{ .reg .u64 t; cvta.to.shared.u64 t, %1; cvt.u32.u64 %0, t; }" : "=r"(a) : "l"(p));
    return a;
}
__device__ __forceinline__ void cp16(uint32_t dst, const void* src) {
    asm volatile("cp.async.cg.shared.global [%0], [%1], 16;" :: "r"(dst), "l"(src));
}
#define CP_COMMIT() asm volatile("cp.async.commit_group;" ::: "memory")
__device__ __forceinline__ uint32_t bf16x2(float hi, float lo) {
    uint32_t r;
    asm("cvt.rn.bf16x2.f32 %0, %1, %2;" : "=r"(r) : "f"(hi), "f"(lo));
    return r;
}
__device__ __forceinline__ float fast_sqrt_pos(float m) {   // m > 0
    return m * rsqrtf(m);
}

// ---------------- mask dtype detector ----------------
__global__ void detect_mask_kernel(const unsigned int* __restrict__ m)
{
    __shared__ int s;
    if (threadIdx.x == 0) s = 0;
    __syncthreads();
    int bad = 0;
    for (int i = threadIdx.x; i < 16384; i += blockDim.x)
        if (m[i] > 1u) { bad = 1; break; }
    if (bad) atomicOr(&s, 1);
    __syncthreads();
    if (threadIdx.x == 0) g_mask_u8 = s;
}

// ---------------- geometry (both neighbor sets, fast math) ----------------
static __device__ __forceinline__ float sgnf(float v) {
    return (v > 0.f) ? 1.f : ((v < 0.f) ? -1.f : 0.f);
}
__device__ __forceinline__ void gridmap(float u, int& i0, float& f) {
    float cc = (u * 0.5f + 0.5f) * 3.f;
    cc = fminf(fmaxf(cc, 0.f), 3.f);
    float fi = floorf(cc);
    fi = fminf(fi, 2.f);
    f = cc - fi;
    i0 = (int)fi;
}

__global__ void geom2_kernel(
    const float* __restrict__ fluid_pos, const float* __restrict__ wall_pos,
    const int* __restrict__ nbr_ff, const void* __restrict__ mask_ff,
    float4* __restrict__ gFff, int* __restrict__ gIff,
    const int* __restrict__ nbr_wf, const void* __restrict__ mask_wf,
    float4* __restrict__ gFwf, int* __restrict__ gIwf)
{
    int gidx = blockIdx.x * blockDim.x + threadIdx.x;
    if (gidx >= 2 * NF * KNBR) return;
    int which = gidx >= NF * KNBR;                 // uniform per block
    int idx = which ? gidx - NF * KNBR : gidx;
    const float* pin = which ? wall_pos : fluid_pos;
    const int*   nbr = which ? nbr_wf   : nbr_ff;
    const void*  mask = which ? mask_wf : mask_ff;
    float4* gF = which ? gFwf : gFff;
    int*    gI = which ? gIwf : gIff;

    int mv = g_mask_u8 ? (int)((const unsigned char*)mask)[idx]
                       : ((const int*)mask)[idx];
    if (mv == 0) { gF[idx] = make_float4(0.f, 0.f, 0.f, 0.f); gI[idx] = 0; return; }
    int n = idx >> 6;
    int j = nbr[idx];
    float x = (pin[j*3+0] - fluid_pos[n*3+0]) * (1.f / RADIUS_F);
    float y = (pin[j*3+1] - fluid_pos[n*3+1]) * (1.f / RADIUS_F);
    float z = (pin[j*3+2] - fluid_pos[n*3+2]) * (1.f / RADIUS_F);
    float sq = x*x + y*y + z*z;
    float t1 = 1.f - sq;
    float win = fminf(fmaxf(t1*t1*t1, 0.f), 1.f);

    const float eps = 1e-12f;
    float norm = fast_sqrt_pos(fmaxf(sq, eps));
    float rho  = fast_sqrt_pos(fmaxf(x*x + y*y, eps));
    bool  top  = (1.25f*z*z > x*x + y*y);
    float st_arg = __fdividef(3.f*norm, norm + fabsf(z));
    float s_top = fast_sqrt_pos(st_arg);
    float inv_rho_n = __fdividef(norm, rho);
    float xs = top ? x*s_top : x*inv_rho_n;
    float ys = top ? y*s_top : y*inv_rho_n;
    float zs = top ? sgnf(z)*norm : 1.5f*z;
    if (sq < eps) { xs = 0.f; ys = 0.f; zs = 0.f; }
    float rxy = fast_sqrt_pos(fmaxf(xs*xs + ys*ys, eps));
    bool use_x = fabsf(ys) <= fabsf(xs);
    float ddx = (use_x  && fabsf(xs) > eps) ? xs : 1.f;
    float ddy = (!use_x && fabsf(ys) > eps) ? ys : 1.f;
    const float c4 = 1.27323954473516276487f;  // 4/pi
    float xc = use_x ? sgnf(xs)*rxy : sgnf(ys)*rxy*c4*atanf(__fdividef(xs, ddy));
    float yc = use_x ? sgnf(xs)*rxy*c4*atanf(__fdividef(ys, ddx)) : sgnf(ys)*rxy;
    if (xs*xs + ys*ys < eps) { xc = 0.f; yc = 0.f; }

    int ix, iy, iz; float fx, fy, fz;
    gridmap(xc, ix, fx); gridmap(yc, iy, fy); gridmap(zs, iz, fz);
    gF[idx] = make_float4(fx, fy, fz, win);
    gI[idx] = (ix*4 + iy)*4 + iz;
}

// ---------------- layer-1 cconv, both convs in one launch, float4 reduction ----------------
__global__ __launch_bounds__(256) void conv1_both(
    const float* __restrict__ wall_nv, const int* __restrict__ nbr_wf,
    const float4* __restrict__ gFwf, const int* __restrict__ gIwf,
    const float* __restrict__ W_wall, const float* __restrict__ b_wall,
    const float* __restrict__ fluid_vel, const int* __restrict__ nbr_ff,
    const float4* __restrict__ gFff, const int* __restrict__ gIff,
    const float* __restrict__ W_fluid, const float* __restrict__ b_fluid,
    float* __restrict__ out1, __nv_bfloat16* __restrict__ out1b)
{
    __shared__ alignas(16) float A[4][192];
    __shared__ float sW[192 * 32];
    __shared__ float red[256];
    int bid = blockIdx.x;
    int which = bid >= (NF/4);                  // 0 = wall conv (cols 0..31), 1 = fluid (32..63)
    int nb = which ? bid - NF/4 : bid;
    const float* feat = which ? fluid_vel : wall_nv;
    const int*   nbr  = which ? nbr_ff : nbr_wf;
    const float4* gF  = which ? gFff : gFwf;
    const int*   gI   = which ? gIff : gIwf;
    const float* W    = which ? W_fluid : W_wall;
    const float* b    = which ? b_fluid : b_wall;
    int col0 = which ? 32 : 0;

    int t = threadIdx.x;
    int p = t >> 6, tl = t & 63;
    int n = nb * 4 + p;
    float* Ap = A[p];
    Ap[tl] = 0.f; Ap[tl + 64] = 0.f; Ap[tl + 128] = 0.f;
    #pragma unroll
    for (int i = 0; i < 24; i++) sW[i * 256 + t] = W[i * 256 + t];
    __syncthreads();

    int idx = n * KNBR + tl;
    float4 g = gF[idx];
    if (g.w != 0.f) {
        int j = nbr[idx];
        float f0 = feat[j*3+0]*g.w, f1 = feat[j*3+1]*g.w, f2 = feat[j*3+2]*g.w;
        int base = gI[idx];
        float wx[2] = {1.f - g.x, g.x};
        float wy[2] = {1.f - g.y, g.y};
        float wz[2] = {1.f - g.z, g.z};
        #pragma unroll
        for (int cx = 0; cx < 2; cx++)
        #pragma unroll
        for (int cy = 0; cy < 2; cy++)
        #pragma unroll
        for (int cz = 0; cz < 2; cz++) {
            float wc = wx[cx]*wy[cy]*wz[cz];
            int cell = base + cx*16 + cy*4 + cz;
            atomicAdd(&Ap[cell*3+0], wc*f0);
            atomicAdd(&Ap[cell*3+1], wc*f1);
            atomicAdd(&Ap[cell*3+2], wc*f2);
        }
    }
    __syncthreads();

    int o = tl & 31, h = tl >> 5;
    const float4* Ap4 = (const float4*)(Ap + h * 96);
    const float* sWh = sW + h * 96 * 32 + o;
    float acc = 0.f;
    #pragma unroll
    for (int i4 = 0; i4 < 24; i4++) {
        float4 av = Ap4[i4];
        acc += av.x * sWh[i4*128      ]
             + av.y * sWh[i4*128 +  32]
             + av.z * sWh[i4*128 +  64]
             + av.w * sWh[i4*128 +  96];
    }
    red[t] = acc;
    __syncthreads();
    if (tl < 32) {
        float v = red[p*64 + tl] + red[p*64 + tl + 32] + b[o];
        v = fmaxf(v, 0.f);
        out1 [n*96 + col0 + tl] = v;
        out1b[n*96 + col0 + tl] = __float2bfloat16(v);
    }
}

// ---------------- cellgemm: A[n] = S[n] @ F[n] on tensor cores (layers 2/3) ----------------
#define S_WLDS 36
template<int CIN>
__global__ __launch_bounds__(128) void cellgemm_kernel(
    const __nv_bfloat16* __restrict__ featb, const int* __restrict__ nbr,
    const float4* __restrict__ gF, const int* __restrict__ gI,
    uint32_t* __restrict__ Aout)
{
    constexpr int F_WLDS = CIN + 8;
    constexpr int NT = CIN / 8;
    __shared__ uint32_t sS[64 * S_WLDS];
    __shared__ uint32_t sF[32 * F_WLDS];
    __shared__ float4 sG[KNBR];
    __shared__ int    sJ[KNBR];
    __shared__ int    sB[KNBR];
    int n = blockIdx.x, t = threadIdx.x;
    int w = t >> 5, lane = t & 31;
    int g = lane >> 2, tg = lane & 3;

    if (t < KNBR) { sG[t] = gF[n*KNBR + t]; sB[t] = gI[n*KNBR + t]; sJ[t] = nbr[n*KNBR + t]; }
    for (int i = t; i < 64 * S_WLDS; i += 128) sS[i] = 0;
    __syncthreads();

    if (t < KNBR) {
        float4 gv = sG[t];
        if (gv.w != 0.f) {
            __nv_bfloat16* Sh = (__nv_bfloat16*)sS;
            int base = sB[t];
            float wx0 = (1.f - gv.x) * gv.w, wx1 = gv.x * gv.w;
            float wy0 = 1.f - gv.y, wy1 = gv.y;
            float wz0 = 1.f - gv.z, wz1 = gv.z;
            Sh[(base     ) * (2*S_WLDS) + t] = __float2bfloat16(wx0*wy0*wz0);
            Sh[(base +  1) * (2*S_WLDS) + t] = __float2bfloat16(wx0*wy0*wz1);
            Sh[(base +  4) * (2*S_WLDS) + t] = __float2bfloat16(wx0*wy1*wz0);
            Sh[(base +  5) * (2*S_WLDS) + t] = __float2bfloat16(wx0*wy1*wz1);
            Sh[(base + 16) * (2*S_WLDS) + t] = __float2bfloat16(wx1*wy0*wz0);
            Sh[(base + 17) * (2*S_WLDS) + t] = __float2bfloat16(wx1*wy0*wz1);
            Sh[(base + 20) * (2*S_WLDS) + t] = __float2bfloat16(wx1*wy1*wz0);
            Sh[(base + 21) * (2*S_WLDS) + t] = __float2bfloat16(wx1*wy1*wz1);
        }
    }

    for (int i = t; i < 32 * CIN; i += 128) {
        int kp = i / CIN, c = i - kp * CIN;
        uint32_t u0 = *(const unsigned short*)(featb + (size_t)sJ[2*kp    ] * CIN + c);
        uint32_t u1 = *(const unsigned short*)(featb + (size_t)sJ[2*kp + 1] * CIN + c);
        sF[kp * F_WLDS + c] = (u1 << 16) | u0;
    }
    __syncthreads();

    float acc[NT][4];
    #pragma unroll
    for (int nt = 0; nt < NT; nt++)
        #pragma unroll
        for (int q = 0; q < 4; q++) acc[nt][q] = 0.f;

    #pragma unroll
    for (int q = 0; q < 4; q++) {
        int r = w * 16 + g;
        uint32_t a0 = sS[(r    ) * S_WLDS + 8*q + tg    ];
        uint32_t a1 = sS[(r + 8) * S_WLDS + 8*q + tg    ];
        uint32_t a2 = sS[(r    ) * S_WLDS + 8*q + tg + 4];
        uint32_t a3 = sS[(r + 8) * S_WLDS + 8*q + tg + 4];
        #pragma unroll
        for (int nt = 0; nt < NT; nt++) {
            uint32_t b0 = sF[(8*q + tg    ) * F_WLDS + nt * 8 + g];
            uint32_t b1 = sF[(8*q + tg + 4) * F_WLDS + nt * 8 + g];
            asm volatile(
                "mma.sync.aligned.m16n8k16.row.col.f32.bf16.bf16.f32 "
                "{%0,%1,%2,%3},{%4,%5,%6,%7},{%8,%9},{%0,%1,%2,%3};"
                : "+f"(acc[nt][0]), "+f"(acc[nt][1]), "+f"(acc[nt][2]), "+f"(acc[nt][3])
                : "r"(a0), "r"(a1), "r"(a2), "r"(a3), "r"(b0), "r"(b1));
        }
    }

    uint32_t* out = Aout + (size_t)n * (32 * CIN);
    #pragma unroll
    for (int nt = 0; nt < NT; nt++) {
        #pragma unroll
        for (int h = 0; h < 2; h++) {
            int cell = w * 16 + g + h * 8;
            out[cell * (CIN/2) + nt * 4 + tg] = bf16x2(acc[nt][h*2+1], acc[nt][h*2+0]);
        }
    }
}

// ---------------- merged weight prep ----------------
#define N_WB2 (3072 * 64)
#define N_WB3 (2048 * 64)
#define N_WP4 (64 * 256)
__global__ void pack_all_kernel(
    const float* __restrict__ W2, const float* __restrict__ W3, const float* __restrict__ W4,
    uint32_t* __restrict__ Wb2, uint32_t* __restrict__ Wb3, float* __restrict__ Wp4)
{
    int idx = blockIdx.x * blockDim.x + threadIdx.x;
    if (idx < N_WB2) {
        int kp = idx >> 6, n = idx & 63;
        Wb2[idx] = bf16x2(W2[(size_t)(2*kp+1)*64 + n], W2[(size_t)(2*kp)*64 + n]);
    } else if (idx < N_WB2 + N_WB3) {
        int j = idx - N_WB2;
        int kp = j >> 6, n = j & 63;
        Wb3[j] = bf16x2(W3[(size_t)(2*kp+1)*64 + n], W3[(size_t)(2*kp)*64 + n]);
    } else if (idx < N_WB2 + N_WB3 + N_WP4) {
        int j = idx - N_WB2 - N_WB3;
        int c = j >> 8, col = j & 255;
        int cell = col >> 2, o = col & 3;
        Wp4[j] = (o < 3) ? W4[((size_t)cell * 64 + c) * 3 + o] : 0.f;
    }
}

// ---------------- pconv4: P[n, cell*4+o] = out3[n,:] @ Wp[:, cell*4+o] (fp32) ----------------
__global__ __launch_bounds__(256) void pconv4_kernel(
    const float* __restrict__ X, const float* __restrict__ Wp, float* __restrict__ P)
{
    __shared__ float4 Xs[32][16];
    int t = threadIdx.x;
    int n0 = blockIdx.x * 32;
    for (int i = t; i < 512; i += 256) {
        int r = i >> 4, c4 = i & 15;
        Xs[r][c4] = *(const float4*)(X + (size_t)(n0 + r) * 64 + c4 * 4);
    }
    __syncthreads();

    float acc[32];
    #pragma unroll
    for (int r = 0; r < 32; r++) acc[r] = 0.f;
    #pragma unroll
    for (int c4 = 0; c4 < 16; c4++) {
        float w0 = Wp[(c4*4 + 0) * 256 + t];
        float w1 = Wp[(c4*4 + 1) * 256 + t];
        float w2 = Wp[(c4*4 + 2) * 256 + t];
        float w3 = Wp[(c4*4 + 3) * 256 + t];
        #pragma unroll
        for (int r = 0; r < 32; r++) {
            float4 xv = Xs[r][c4];
            acc[r] += xv.x*w0 + xv.y*w1 + xv.z*w2 + xv.w*w3;
        }
    }
    #pragma unroll
    for (int r = 0; r < 32; r++)
        P[(size_t)(n0 + r) * 256 + t] = acc[r];
}

// ---------------- conv4 gather + fused dense shortcut ----------------
__global__ __launch_bounds__(64) void conv4_kernel(
    const float* __restrict__ P, const int* __restrict__ nbr,
    const float4* __restrict__ gF, const int* __restrict__ gI,
    const float* __restrict__ bc4, const float* __restrict__ out3,
    const float* __restrict__ Wd4, const float* __restrict__ bd4,
    float* __restrict__ out)
{
    __shared__ float red[2][3];
    int n = blockIdx.x, t = threadIdx.x;
    float a0 = 0.f, a1 = 0.f, a2 = 0.f;
    {
        float x = out3[(size_t)n * 64 + t];
        a0 += x * Wd4[t*3 + 0];
        a1 += x * Wd4[t*3 + 1];
        a2 += x * Wd4[t*3 + 2];
    }
    float4 g = gF[n*KNBR + t];
    if (g.w != 0.f) {
        int j = nbr[n*KNBR + t];
        const float4* Pj = (const float4*)(P + (size_t)j * 256);
        int base = gI[n*KNBR + t];
        float wx0 = (1.f - g.x) * g.w, wx1 = g.x * g.w;
        float wy0 = 1.f - g.y, wy1 = g.y;
        float wz0 = 1.f - g.z, wz1 = g.z;
        float wq[8] = {wx0*wy0*wz0, wx0*wy0*wz1, wx0*wy1*wz0, wx0*wy1*wz1,
                       wx1*wy0*wz0, wx1*wy0*wz1, wx1*wy1*wz0, wx1*wy1*wz1};
        const int off[8] = {0, 1, 4, 5, 16, 17, 20, 21};
        #pragma unroll
        for (int q = 0; q < 8; q++) {
            float4 p = Pj[base + off[q]];
            a0 += wq[q] * p.x; a1 += wq[q] * p.y; a2 += wq[q] * p.z;
        }
    }
    #pragma unroll
    for (int s = 16; s > 0; s >>= 1) {
        a0 += __shfl_down_sync(0xffffffff, a0, s);
        a1 += __shfl_down_sync(0xffffffff, a1, s);
        a2 += __shfl_down_sync(0xffffffff, a2, s);
    }
    if ((t & 31) == 0) { red[t>>5][0] = a0; red[t>>5][1] = a1; red[t>>5][2] = a2; }
    __syncthreads();
    if (t < 3) out[n*3 + t] = red[0][t] + red[1][t] + bc4[t] + bd4[t];
}

// ---------------- bf16 tensor GEMM ----------------
#define STAGES 4
#define A_WLDS 20
#define B_WLDS 72
#define A_WSTAGE (128*A_WLDS)
#define B_WSTAGE (16*B_WLDS)
#define GEMM_SMEM (STAGES*(A_WSTAGE + B_WSTAGE)*4)

template<int HAS_ADD, int HAS_RES, int RELU>
__global__ __launch_bounds__(128) void gemm_mma(
    const __nv_bfloat16* __restrict__ Ag, const uint32_t* __restrict__ Wb,
    const float* __restrict__ bias, const float* __restrict__ addv,
    const float* __restrict__ resv, float* __restrict__ out,
    __nv_bfloat16* __restrict__ outb, int K)
{
    extern __shared__ uint32_t sm[];
    uint32_t* sA = sm;
    uint32_t* sB = sm + STAGES * A_WSTAGE;
    int tid = threadIdx.x, w = tid >> 5, lane = tid & 31;
    int g = lane >> 2, tg = lane & 3;
    int m0 = blockIdx.x * 128;
    int NIT = K >> 5;
    uint32_t sAu = smem_u32(sA), sBu = smem_u32(sB);

    auto load_stage = [&](int s, int c) {
        uint32_t ab = sAu + (uint32_t)s * A_WSTAGE * 4;
        const __nv_bfloat16* as = Ag + (size_t)m0 * K + c * 32;
        #pragma unroll
        for (int r = 0; r < 4; r++) {
            int idx = r * 128 + tid;
            int row = idx >> 2, seg = idx & 3;
            cp16(ab + (row * A_WLDS + seg * 4) * 4, as + (size_t)row * K + seg * 8);
        }
        uint32_t bb = sBu + (uint32_t)s * B_WSTAGE * 4;
        const uint32_t* bs = Wb + (size_t)c * 16 * 64;
        #pragma unroll
        for (int r = 0; r < 2; r++) {
            int idx = r * 128 + tid;
            int kp = idx >> 4, seg = idx & 15;
            cp16(bb + (kp * B_WLDS + seg * 4) * 4, bs + kp * 64 + seg * 4);
        }
    };

    float acc[2][8][4];
    #pragma unroll
    for (int mt = 0; mt < 2; mt++)
        #pragma unroll
        for (int nt = 0; nt < 8; nt++)
            #pragma unroll
            for (int q = 0; q < 4; q++) acc[mt][nt][q] = 0.f;

    #pragma unroll
    for (int s = 0; s < STAGES; s++) { load_stage(s, s); CP_COMMIT(); }

    for (int i = 0; i < NIT; i++) {
        asm volatile("cp.async.wait_group %0;" :: "n"(STAGES - 1));
        __syncthreads();
        const uint32_t* cA = sA + (i % STAGES) * A_WSTAGE;
        const uint32_t* cB = sB + (i % STAGES) * B_WSTAGE;
        #pragma unroll
        for (int q = 0; q < 2; q++) {
            uint32_t a[2][4], b[8][2];
            #pragma unroll
            for (int mt = 0; mt < 2; mt++) {
                int r = w * 32 + mt * 16 + g;
                a[mt][0] = cA[(r    ) * A_WLDS + 8*q + tg    ];
                a[mt][1] = cA[(r + 8) * A_WLDS + 8*q + tg    ];
                a[mt][2] = cA[(r    ) * A_WLDS + 8*q + tg + 4];
                a[mt][3] = cA[(r + 8) * A_WLDS + 8*q + tg + 4];
            }
            #pragma unroll
            for (int nt = 0; nt < 8; nt++) {
                b[nt][0] = cB[(8*q + tg    ) * B_WLDS + nt * 8 + g];
                b[nt][1] = cB[(8*q + tg + 4) * B_WLDS + nt * 8 + g];
            }
            #pragma unroll
            for (int mt = 0; mt < 2; mt++)
                #pragma unroll
                for (int nt = 0; nt < 8; nt++)
                    asm volatile(
                        "mma.sync.aligned.m16n8k16.row.col.f32.bf16.bf16.f32 "
                        "{%0,%1,%2,%3},{%4,%5,%6,%7},{%8,%9},{%0,%1,%2,%3};"
                        : "+f"(acc[mt][nt][0]), "+f"(acc[mt][nt][1]),
                          "+f"(acc[mt][nt][2]), "+f"(acc[mt][nt][3])
                        : "r"(a[mt][0]), "r"(a[mt][1]), "r"(a[mt][2]), "r"(a[mt][3]),
                          "r"(b[nt][0]), "r"(b[nt][1]));
        }
        __syncthreads();
        if (i + STAGES < NIT) load_stage(i % STAGES, i + STAGES);
        CP_COMMIT();
    }

    #pragma unroll
    for (int mt = 0; mt < 2; mt++) {
        #pragma unroll
        for (int nt = 0; nt < 8; nt++) {
            #pragma unroll
            for (int h = 0; h < 2; h++) {
                int m = m0 + w * 32 + mt * 16 + g + h * 8;
                int n0 = nt * 8 + 2 * tg;
                float lo = acc[mt][nt][h*2+0], hi = acc[mt][nt][h*2+1];
                float2 bb = *(const float2*)&bias[n0];
                lo += bb.x; hi += bb.y;
                if (HAS_ADD) {
                    float2 v = *(const float2*)&addv[(size_t)m*64 + n0];
                    lo += v.x; hi += v.y;
                }
                if (HAS_RES) {
                    float2 v = *(const float2*)&resv[(size_t)m*64 + n0];
                    lo += v.x; hi += v.y;
                }
                if (RELU) { lo = fmaxf(lo, 0.f); hi = fmaxf(hi, 0.f); }
                *(float2*)&out[(size_t)m*64 + n0] = make_float2(lo, hi);
                if (outb)
                    *(uint32_t*)&outb[(size_t)m*64 + n0] = bf16x2(hi, lo);
            }
        }
    }
}

// ---------------- dense GEMM ----------------
template<int CIN, int COUT, int RPT>
__global__ __launch_bounds__(COUT * (32 / RPT)) void dense_gemm(
    const float* __restrict__ X, const float* __restrict__ W,
    const float* __restrict__ b, float* __restrict__ Y,
    __nv_bfloat16* __restrict__ Yb, int ldY, int col0)
{
    constexpr int BD = COUT * (32 / RPT);
    __shared__ float Xs[32 * CIN];
    int t = threadIdx.x;
    int n0 = blockIdx.x * 32;
    for (int i = t; i < 32 * CIN; i += BD)
        Xs[i] = X[(size_t)n0 * CIN + i];
    __syncthreads();

    int o = t % COUT, rg = t / COUT;
    float acc[RPT];
    float bo = b[o];
    #pragma unroll
    for (int r = 0; r < RPT; r++) acc[r] = bo;
    #pragma unroll 4
    for (int c = 0; c < CIN; c++) {
        float wv = W[c * COUT + o];
        #pragma unroll
        for (int r = 0; r < RPT; r++)
            acc[r] += Xs[(rg * RPT + r) * CIN + c] * wv;
    }
    #pragma unroll
    for (int r = 0; r < RPT; r++) {
        size_t off = (size_t)(n0 + rg * RPT + r) * ldY + col0 + o;
        Y[off] = acc[r];
        if (Yb) Yb[off] = __float2bfloat16(acc[r]);
    }
}

// ---------------- launch ----------------
extern "C" void kernel_launch(void* const* d_in, const int* in_sizes, int n_in,
                              void* d_out, int out_size)
{
    const float* fluid_pos = (const float*)d_in[0];
    const float* wall_pos  = (const float*)d_in[1];
    const float* fluid_vel = (const float*)d_in[2];
    const float* wall_nv   = (const float*)d_in[3];
    const int*   nbr_wf    = (const int*)d_in[4];
    const void*  mask_wf   = d_in[5];
    const int*   nbr_ff    = (const int*)d_in[6];
    const void*  mask_ff   = d_in[7];
    const float* W_wall1 = (const float*)d_in[8];
    const float* b_wall1 = (const float*)d_in[9];
    const float* W_fluid1 = (const float*)d_in[10];
    const float* b_fluid1 = (const float*)d_in[11];
    const float* W_d1 = (const float*)d_in[12];
    const float* b_d1 = (const float*)d_in[13];
    const float* W_c2 = (const float*)d_in[14];
    const float* b_c2 = (const float*)d_in[15];
    const float* W_d2 = (const float*)d_in[16];
    const float* b_d2 = (const float*)d_in[17];
    const float* W_c3 = (const float*)d_in[18];
    const float* b_c3 = (const float*)d_in[19];
    const float* W_d3 = (const float*)d_in[20];
    const float* b_d3 = (const float*)d_in[21];
    const float* W_c4 = (const float*)d_in[22];
    const float* b_c4 = (const float*)d_in[23];
    const float* W_d4 = (const float*)d_in[24];
    const float* b_d4 = (const float*)d_in[25];

    void *pA, *pgFff, *pgIff, *pgFwf, *pgIwf, *pout1, *pout1b, *pout2, *pout2b,
         *pout3, *pdense, *pWb2, *pWb3, *pWp4;
    cudaGetSymbolAddress(&pA, g_A);
    cudaGetSymbolAddress(&pgFff, g_gF_ff);
    cudaGetSymbolAddress(&pgIff, g_gI_ff);
    cudaGetSymbolAddress(&pgFwf, g_gF_wf);
    cudaGetSymbolAddress(&pgIwf, g_gI_wf);
    cudaGetSymbolAddress(&pout1, g_out1);
    cudaGetSymbolAddress(&pout1b, g_out1b);
    cudaGetSymbolAddress(&pout2, g_out2);
    cudaGetSymbolAddress(&pout2b, g_out2b);
    cudaGetSymbolAddress(&pout3, g_out3);
    cudaGetSymbolAddress(&pdense, g_dense);
    cudaGetSymbolAddress(&pWb2, g_Wb2);
    cudaGetSymbolAddress(&pWb3, g_Wb3);
    cudaGetSymbolAddress(&pWp4, g_Wp4);
    void*   A     = pA;
    float4* gFff  = (float4*)pgFff;
    int*    gIff  = (int*)pgIff;
    float4* gFwf  = (float4*)pgFwf;
    int*    gIwf  = (int*)pgIwf;
    float*  out1  = (float*)pout1;
    __nv_bfloat16* out1b = (__nv_bfloat16*)pout1b;
    float*  out2  = (float*)pout2;
    __nv_bfloat16* out2b = (__nv_bfloat16*)pout2b;
    float*  out3  = (float*)pout3;
    float*  dense = (float*)pdense;
    uint32_t* Wb2 = (uint32_t*)pWb2;
    uint32_t* Wb3 = (uint32_t*)pWb3;
    float*  Wp4   = (float*)pWp4;

    cudaFuncSetAttribute(gemm_mma<1,0,1>, cudaFuncAttributeMaxDynamicSharedMemorySize, GEMM_SMEM);
    cudaFuncSetAttribute(gemm_mma<1,1,1>, cudaFuncAttributeMaxDynamicSharedMemorySize, GEMM_SMEM);

    const int tot = NF * KNBR;
    detect_mask_kernel<<<1, 1024>>>((const unsigned int*)mask_wf);
    geom2_kernel<<<(2*tot + 255)/256, 256>>>(fluid_pos, wall_pos,
                                             nbr_ff, mask_ff, gFff, gIff,
                                             nbr_wf, mask_wf, gFwf, gIwf);
    pack_all_kernel<<<(N_WB2 + N_WB3 + N_WP4 + 255)/256, 256>>>(W_c2, W_c3, W_c4, Wb2, Wb3, Wp4);

    // layer 1 (both convs in one launch)
    conv1_both<<<NF/2, 256>>>(wall_nv, nbr_wf, gFwf, gIwf, W_wall1, b_wall1,
                              fluid_vel, nbr_ff, gFff, gIff, W_fluid1, b_fluid1,
                              out1, out1b);
    dense_gemm<3, 32, 4><<<NF/32, 256>>>(fluid_vel, W_d1, b_d1, out1, out1b, 96, 64);

    // layer 2
    dense_gemm<96, 64, 8><<<NF/32, 256>>>(out1, W_d2, b_d2, dense, nullptr, 64, 0);
    cellgemm_kernel<96><<<NF, 128>>>(out1b, nbr_ff, gFff, gIff, (uint32_t*)A);
    gemm_mma<1, 0, 1><<<NF/128, 128, GEMM_SMEM>>>((const __nv_bfloat16*)A, Wb2, b_c2, dense,
                                                  nullptr, out2, out2b, 6144);

    // layer 3
    dense_gemm<64, 64, 8><<<NF/32, 256>>>(out2, W_d3, b_d3, dense, nullptr, 64, 0);
    cellgemm_kernel<64><<<NF, 128>>>(out2b, nbr_ff, gFff, gIff, (uint32_t*)A);
    gemm_mma<1, 1, 1><<<NF/128, 128, GEMM_SMEM>>>((const __nv_bfloat16*)A, Wb3, b_c3, dense,
                                                  out2, out3, nullptr, 4096);

    // layer 4
    pconv4_kernel<<<NF/32, 256>>>(out3, Wp4, (float*)A);
    conv4_kernel<<<NF, 64>>>((const float*)A, nbr_ff, gFff, gIff, b_c4,
                             out3, W_d4, b_d4, (float*)d_out);
}